// round 6
// baseline (speedup 1.0000x reference)
/*
 * LearnedSimModel fused GNN - fp32 SIMT baseline, edge_index as int32 (R5 fix).
 * encoder_kernel   : per-32-row tile MLP (node/edge encoders)
 * gnn_layer_kernel : fused edge-MLP + edge-LN + node-MLP + red.v4 scatter
 * node_update      : residual + LN + re-zero accumulator (graph-replay idempotent)
 * decoder_kernel   : final MLP minus noise
 */
#include <cuda_runtime.h>
#include <cstdint>

#define N_NODES 20000
#define N_EDGES 640000
#define HDIM    128
#define NLAYERS 10
#define LN_EPS  1e-5f
#define TR      32

__device__ float g_h   [(size_t)N_NODES * HDIM];
__device__ float g_hagg[(size_t)N_NODES * HDIM];
__device__ float g_e   [(size_t)N_EDGES * HDIM];

// ---------------- encoder: out = relu((in+noise) @ w1 + b1) @ w2 + b2 ----------------
template<int D>
__global__ void __launch_bounds__(128) encoder_kernel(
    const float* __restrict__ in, const float* __restrict__ noise,
    const float* __restrict__ w1, const float* __restrict__ b1,
    const float* __restrict__ w2, const float* __restrict__ b2,
    float* __restrict__ out)
{
    __shared__ float s_in [TR * D];
    __shared__ float s_hid[TR * HDIM];
    const int tid = threadIdx.x;
    const size_t row0 = (size_t)blockIdx.x * TR;

    for (int i = tid; i < TR * D; i += 128)
        s_in[i] = in[row0 * D + i] + noise[row0 * D + i];
    __syncthreads();

    float acc[TR];
    {
        const float bb = b1[tid];
        #pragma unroll
        for (int r = 0; r < TR; r++) acc[r] = bb;
    }
    #pragma unroll
    for (int k = 0; k < D; k++) {
        const float w = w1[k * HDIM + tid];
        #pragma unroll
        for (int r = 0; r < TR; r++) acc[r] += s_in[r * D + k] * w;
    }
    #pragma unroll
    for (int r = 0; r < TR; r++) s_hid[r * HDIM + tid] = fmaxf(acc[r], 0.f);
    __syncthreads();

    {
        const float bb = b2[tid];
        #pragma unroll
        for (int r = 0; r < TR; r++) acc[r] = bb;
    }
    for (int k = 0; k < HDIM; k++) {
        const float w = w2[k * HDIM + tid];
        #pragma unroll
        for (int r = 0; r < TR; r++) acc[r] += s_hid[r * HDIM + k] * w;
    }
    #pragma unroll
    for (int r = 0; r < TR; r++) out[(row0 + r) * HDIM + tid] = acc[r];
}

// ---------------- fused GNN layer over a tile of 32 edges ----------------
// e_new = e + edge_mlp([xi,xj,e]);  g_e <- LN(e + e_new)
// msg   = xi + node_mlp([xi,e_new]); g_hagg[dst] += msg (vector red)
__global__ void __launch_bounds__(128) gnn_layer_kernel(
    const int* __restrict__ ei,          // int32: [0,E) = src, [E,2E) = dst
    const float* __restrict__ We1, const float* __restrict__ be1,
    const float* __restrict__ We2, const float* __restrict__ be2,
    const float* __restrict__ Wn1, const float* __restrict__ bn1,
    const float* __restrict__ Wn2, const float* __restrict__ bn2,
    const float* __restrict__ eg,  const float* __restrict__ eb)
{
    extern __shared__ float sm[];
    float* s_xi  = sm;                 // [TR][H] gathered h[dst]
    float* s_xj  = sm + TR * HDIM;     // [TR][H] gathered h[src]; later e_new
    float* s_e   = sm + 2 * TR * HDIM; // [TR][H] edge feats; later msg
    float* s_hid = sm + 3 * TR * HDIM; // [TR][H] MLP hidden
    __shared__ int s_src[TR];
    __shared__ int s_dst[TR];

    const int tid = threadIdx.x;
    const size_t e0 = (size_t)blockIdx.x * TR;

    if (tid < TR)            s_src[tid]      = ei[e0 + tid];
    else if (tid < 2 * TR)   s_dst[tid - TR] = ei[(size_t)N_EDGES + e0 + (tid - TR)];
    __syncthreads();

    #pragma unroll 4
    for (int r = 0; r < TR; r++) {
        s_xi[r * HDIM + tid] = g_h[(size_t)s_dst[r] * HDIM + tid];
        s_xj[r * HDIM + tid] = g_h[(size_t)s_src[r] * HDIM + tid];
        s_e [r * HDIM + tid] = g_e[(e0 + r) * HDIM + tid];
    }
    __syncthreads();

    float acc[TR];

    // GEMM1: hid = relu([xi,xj,e] @ We1 + be1)
    {
        const float bb = be1[tid];
        #pragma unroll
        for (int r = 0; r < TR; r++) acc[r] = bb;
    }
    for (int k = 0; k < HDIM; k++) {
        const float w = We1[k * HDIM + tid];
        #pragma unroll
        for (int r = 0; r < TR; r++) acc[r] += s_xi[r * HDIM + k] * w;
    }
    for (int k = 0; k < HDIM; k++) {
        const float w = We1[(HDIM + k) * HDIM + tid];
        #pragma unroll
        for (int r = 0; r < TR; r++) acc[r] += s_xj[r * HDIM + k] * w;
    }
    for (int k = 0; k < HDIM; k++) {
        const float w = We1[(2 * HDIM + k) * HDIM + tid];
        #pragma unroll
        for (int r = 0; r < TR; r++) acc[r] += s_e[r * HDIM + k] * w;
    }
    #pragma unroll
    for (int r = 0; r < TR; r++) s_hid[r * HDIM + tid] = fmaxf(acc[r], 0.f);
    __syncthreads();

    // GEMM2: e_new = e + hid @ We2 + be2  (written into s_xj)
    {
        const float bb = be2[tid];
        #pragma unroll
        for (int r = 0; r < TR; r++) acc[r] = bb;
    }
    for (int k = 0; k < HDIM; k++) {
        const float w = We2[k * HDIM + tid];
        #pragma unroll
        for (int r = 0; r < TR; r++) acc[r] += s_hid[r * HDIM + k] * w;
    }
    __syncthreads();
    #pragma unroll
    for (int r = 0; r < TR; r++) s_xj[r * HDIM + tid] = s_e[r * HDIM + tid] + acc[r];
    __syncthreads();

    // edge LayerNorm: g_e <- LN(e + e_new) * eg + eb (one warp per row)
    {
        const int warp = tid >> 5, lane = tid & 31;
        for (int r = warp; r < TR; r += 4) {
            const float* pe = &s_e [r * HDIM + lane * 4];
            const float* pn = &s_xj[r * HDIM + lane * 4];
            float v[4]; float s = 0.f, q = 0.f;
            #pragma unroll
            for (int j = 0; j < 4; j++) { v[j] = pe[j] + pn[j]; s += v[j]; q += v[j] * v[j]; }
            #pragma unroll
            for (int o = 16; o > 0; o >>= 1) {
                s += __shfl_xor_sync(0xffffffffu, s, o);
                q += __shfl_xor_sync(0xffffffffu, q, o);
            }
            const float mean = s * (1.f / HDIM);
            const float var  = q * (1.f / HDIM) - mean * mean;
            const float rstd = rsqrtf(var + LN_EPS);
            #pragma unroll
            for (int j = 0; j < 4; j++) {
                const int c = lane * 4 + j;
                g_e[(e0 + r) * HDIM + c] = (v[j] - mean) * rstd * eg[c] + eb[c];
            }
        }
    }

    // GEMM3: hid2 = relu([xi, e_new] @ Wn1 + bn1)  (into s_hid)
    {
        const float bb = bn1[tid];
        #pragma unroll
        for (int r = 0; r < TR; r++) acc[r] = bb;
    }
    for (int k = 0; k < HDIM; k++) {
        const float w = Wn1[k * HDIM + tid];
        #pragma unroll
        for (int r = 0; r < TR; r++) acc[r] += s_xi[r * HDIM + k] * w;
    }
    for (int k = 0; k < HDIM; k++) {
        const float w = Wn1[(HDIM + k) * HDIM + tid];
        #pragma unroll
        for (int r = 0; r < TR; r++) acc[r] += s_xj[r * HDIM + k] * w;
    }
    __syncthreads();
    #pragma unroll
    for (int r = 0; r < TR; r++) s_hid[r * HDIM + tid] = fmaxf(acc[r], 0.f);
    __syncthreads();

    // GEMM4: msg = xi + hid2 @ Wn2 + bn2  (into s_e)
    {
        const float bb = bn2[tid];
        #pragma unroll
        for (int r = 0; r < TR; r++) acc[r] = bb;
    }
    for (int k = 0; k < HDIM; k++) {
        const float w = Wn2[k * HDIM + tid];
        #pragma unroll
        for (int r = 0; r < TR; r++) acc[r] += s_hid[r * HDIM + k] * w;
    }
    #pragma unroll
    for (int r = 0; r < TR; r++) s_e[r * HDIM + tid] = s_xi[r * HDIM + tid] + acc[r];
    __syncthreads();

    // scatter: g_hagg[dst] += msg via vector reductions
    for (int i = tid; i < TR * (HDIM / 4); i += 128) {
        const int r = i >> 5;
        const int g = i & 31;
        const float4 v = *(const float4*)&s_e[r * HDIM + g * 4];
        float* p = &g_hagg[(size_t)s_dst[r] * HDIM + g * 4];
        asm volatile("red.global.add.v4.f32 [%0], {%1,%2,%3,%4};"
                     :: "l"(p), "f"(v.x), "f"(v.y), "f"(v.z), "f"(v.w) : "memory");
    }
}

// ---------------- node update: g_h <- LN(h + h_agg); g_hagg <- 0 ----------------
__global__ void __launch_bounds__(256) node_update_kernel(
    const float* __restrict__ xg, const float* __restrict__ xb)
{
    const int warp = threadIdx.x >> 5, lane = threadIdx.x & 31;
    const int n = blockIdx.x * 8 + warp;
    if (n >= N_NODES) return;
    const size_t base = (size_t)n * HDIM + lane * 4;

    const float4 hv = *(const float4*)&g_h[base];
    const float4 av = *(const float4*)&g_hagg[base];
    float v[4] = { hv.x + av.x, hv.y + av.y, hv.z + av.z, hv.w + av.w };
    float s = 0.f, q = 0.f;
    #pragma unroll
    for (int j = 0; j < 4; j++) { s += v[j]; q += v[j] * v[j]; }
    #pragma unroll
    for (int o = 16; o > 0; o >>= 1) {
        s += __shfl_xor_sync(0xffffffffu, s, o);
        q += __shfl_xor_sync(0xffffffffu, q, o);
    }
    const float mean = s * (1.f / HDIM);
    const float var  = q * (1.f / HDIM) - mean * mean;
    const float rstd = rsqrtf(var + LN_EPS);

    float4 o4;
    o4.x = (v[0] - mean) * rstd * xg[lane * 4 + 0] + xb[lane * 4 + 0];
    o4.y = (v[1] - mean) * rstd * xg[lane * 4 + 1] + xb[lane * 4 + 1];
    o4.z = (v[2] - mean) * rstd * xg[lane * 4 + 2] + xb[lane * 4 + 2];
    o4.w = (v[3] - mean) * rstd * xg[lane * 4 + 3] + xb[lane * 4 + 3];
    *(float4*)&g_h[base]    = o4;
    *(float4*)&g_hagg[base] = make_float4(0.f, 0.f, 0.f, 0.f);
}

// ---------------- decoder: out = relu(h @ w1 + b1) @ w2 + b2 - noise[:, :2] ----------------
__global__ void __launch_bounds__(256) decoder_kernel(
    const float* __restrict__ w1, const float* __restrict__ b1,
    const float* __restrict__ w2, const float* __restrict__ b2,
    const float* __restrict__ noise, float* __restrict__ out)
{
    const int warp = threadIdx.x >> 5, lane = threadIdx.x & 31;
    const int n = blockIdx.x * 8 + warp;
    if (n >= N_NODES) return;
    const float* hrow = &g_h[(size_t)n * HDIM];

    float acc[4];
    #pragma unroll
    for (int j = 0; j < 4; j++) acc[j] = b1[lane * 4 + j];
    for (int k = 0; k < HDIM; k++) {
        const float hk = __ldg(&hrow[k]);
        const float4 w = *(const float4*)&w1[k * HDIM + lane * 4];
        acc[0] += hk * w.x; acc[1] += hk * w.y; acc[2] += hk * w.z; acc[3] += hk * w.w;
    }
    float o0 = 0.f, o1 = 0.f;
    #pragma unroll
    for (int j = 0; j < 4; j++) {
        const float hid = fmaxf(acc[j], 0.f);
        const int c = lane * 4 + j;
        o0 += hid * w2[c * 2 + 0];
        o1 += hid * w2[c * 2 + 1];
    }
    #pragma unroll
    for (int o = 16; o > 0; o >>= 1) {
        o0 += __shfl_xor_sync(0xffffffffu, o0, o);
        o1 += __shfl_xor_sync(0xffffffffu, o1, o);
    }
    if (lane == 0) {
        out[n * 2 + 0] = o0 + b2[0] - noise[n * 16 + 0];
        out[n * 2 + 1] = o1 + b2[1] - noise[n * 16 + 1];
    }
}

// ---------------- launch ----------------
extern "C" void kernel_launch(void* const* d_in, const int* in_sizes, int n_in,
                              void* d_out, int out_size)
{
    const float* x          = (const float*)d_in[0];
    const float* edge_attr  = (const float*)d_in[1];
    const int*   ei         = (const int*)d_in[2];       // int32 (JAX x64 disabled)
    const float* node_noise = (const float*)d_in[3];
    const float* edge_noise = (const float*)d_in[4];
    const float* nw1 = (const float*)d_in[5];  const float* nb1 = (const float*)d_in[6];
    const float* nw2 = (const float*)d_in[7];  const float* nb2 = (const float*)d_in[8];
    const float* ew1 = (const float*)d_in[9];  const float* eb1 = (const float*)d_in[10];
    const float* ew2 = (const float*)d_in[11]; const float* eb2 = (const float*)d_in[12];
    const float* gew1 = (const float*)d_in[13]; const float* geb1 = (const float*)d_in[14];
    const float* gew2 = (const float*)d_in[15]; const float* geb2 = (const float*)d_in[16];
    const float* gnw1 = (const float*)d_in[17]; const float* gnb1 = (const float*)d_in[18];
    const float* gnw2 = (const float*)d_in[19]; const float* gnb2 = (const float*)d_in[20];
    const float* xlg = (const float*)d_in[21]; const float* xlb = (const float*)d_in[22];
    const float* elg = (const float*)d_in[23]; const float* elb = (const float*)d_in[24];
    const float* dw1 = (const float*)d_in[25]; const float* db1 = (const float*)d_in[26];
    const float* dw2 = (const float*)d_in[27]; const float* db2 = (const float*)d_in[28];
    float* out = (float*)d_out;

    float *ph = nullptr, *pe = nullptr;
    cudaGetSymbolAddress((void**)&ph, g_h);
    cudaGetSymbolAddress((void**)&pe, g_e);

    const int gnn_smem = 4 * TR * HDIM * (int)sizeof(float);   // 64 KB dynamic smem
    cudaFuncSetAttribute(gnn_layer_kernel,
                         cudaFuncAttributeMaxDynamicSharedMemorySize, gnn_smem);

    encoder_kernel<16><<<N_NODES / TR, 128>>>(x, node_noise, nw1, nb1, nw2, nb2, ph);
    encoder_kernel<8><<<N_EDGES / TR, 128>>>(edge_attr, edge_noise, ew1, eb1, ew2, eb2, pe);

    for (int l = 0; l < NLAYERS; l++) {
        gnn_layer_kernel<<<N_EDGES / TR, 128, gnn_smem>>>(
            ei, gew1, geb1, gew2, geb2, gnw1, gnb1, gnw2, gnb2,
            elg + (size_t)l * HDIM, elb + (size_t)l * HDIM);
        node_update_kernel<<<(N_NODES + 7) / 8, 256>>>(
            xlg + (size_t)l * HDIM, xlb + (size_t)l * HDIM);
    }

    decoder_kernel<<<(N_NODES + 7) / 8, 256>>>(dw1, db1, dw2, db2, node_noise, out);
}

// round 7
// speedup vs baseline: 2.4290x; 2.4290x over previous
/*
 * LearnedSimModel fused GNN - round 7: packed f32x2 + LDS.128 transposed tiles.
 * gnn_layer_kernel: per-32-edge tile, operands stored [feature][row] (pad 36),
 * inner loop = 8x LDS.128 (4 rows) + 16x fma.rn.f32x2 per k. Exact fp32 math.
 */
#include <cuda_runtime.h>
#include <cstdint>

#define N_NODES 20000
#define N_EDGES 640000
#define HDIM    128
#define NLAYERS 10
#define LN_EPS  1e-5f
#define TR      32
#define HP      36      // transposed row pitch (floats): 144B, 16B-aligned
#define RM      132     // row-major LN scratch pitch

__device__ float g_h   [(size_t)N_NODES * HDIM];
__device__ float g_hagg[(size_t)N_NODES * HDIM];
__device__ float g_e   [(size_t)N_EDGES * HDIM];

typedef unsigned long long u64;

__device__ __forceinline__ u64 pk2(float lo, float hi) {
    u64 r; asm("mov.b64 %0,{%1,%2};" : "=l"(r) : "f"(lo), "f"(hi)); return r;
}
__device__ __forceinline__ void upk2(u64 v, float& lo, float& hi) {
    asm("mov.b64 {%0,%1},%2;" : "=f"(lo), "=f"(hi) : "l"(v));
}
__device__ __forceinline__ void ffma2(u64& d, u64 a, u64 b) {
    asm("fma.rn.f32x2 %0,%1,%2,%0;" : "+l"(d) : "l"(a), "l"(b));
}
__device__ __forceinline__ u64 fadd2(u64 a, u64 b) {
    u64 r; asm("add.rn.f32x2 %0,%1,%2;" : "=l"(r) : "l"(a), "l"(b)); return r;
}

// accumulate acc[p] (+)= sT[k][2p,2p+1] * W[k][tid] over k = 0..127
__device__ __forceinline__ void gemm_block(const float* __restrict__ W, int tid,
                                           const float* __restrict__ sT, u64* acc)
{
    #pragma unroll 4
    for (int k = 0; k < HDIM; k++) {
        const float w = __ldg(&W[k * HDIM + tid]);
        const u64 wp = pk2(w, w);
        const ulonglong2* p = (const ulonglong2*)(sT + k * HP);
        #pragma unroll
        for (int q = 0; q < 8; q++) {
            ulonglong2 v = p[q];          // rows 4q..4q+3 at feature k
            ffma2(acc[2 * q],     v.x, wp);
            ffma2(acc[2 * q + 1], v.y, wp);
        }
    }
}

// ---------------- encoder (unchanged from passing R6 kernel) ----------------
template<int D>
__global__ void __launch_bounds__(128) encoder_kernel(
    const float* __restrict__ in, const float* __restrict__ noise,
    const float* __restrict__ w1, const float* __restrict__ b1,
    const float* __restrict__ w2, const float* __restrict__ b2,
    float* __restrict__ out)
{
    __shared__ float s_in [TR * D];
    __shared__ float s_hid[TR * HDIM];
    const int tid = threadIdx.x;
    const size_t row0 = (size_t)blockIdx.x * TR;

    for (int i = tid; i < TR * D; i += 128)
        s_in[i] = in[row0 * D + i] + noise[row0 * D + i];
    __syncthreads();

    float acc[TR];
    {
        const float bb = b1[tid];
        #pragma unroll
        for (int r = 0; r < TR; r++) acc[r] = bb;
    }
    #pragma unroll
    for (int k = 0; k < D; k++) {
        const float w = w1[k * HDIM + tid];
        #pragma unroll
        for (int r = 0; r < TR; r++) acc[r] += s_in[r * D + k] * w;
    }
    #pragma unroll
    for (int r = 0; r < TR; r++) s_hid[r * HDIM + tid] = fmaxf(acc[r], 0.f);
    __syncthreads();

    {
        const float bb = b2[tid];
        #pragma unroll
        for (int r = 0; r < TR; r++) acc[r] = bb;
    }
    for (int k = 0; k < HDIM; k++) {
        const float w = w2[k * HDIM + tid];
        #pragma unroll
        for (int r = 0; r < TR; r++) acc[r] += s_hid[r * HDIM + k] * w;
    }
    #pragma unroll
    for (int r = 0; r < TR; r++) out[(row0 + r) * HDIM + tid] = acc[r];
}

// ---------------- fused GNN layer, packed-f32x2 version ----------------
__global__ void __launch_bounds__(128) gnn_layer_kernel(
    const int* __restrict__ ei,
    const float* __restrict__ We1, const float* __restrict__ be1,
    const float* __restrict__ We2, const float* __restrict__ be2,
    const float* __restrict__ Wn1, const float* __restrict__ bn1,
    const float* __restrict__ Wn2, const float* __restrict__ bn2,
    const float* __restrict__ eg,  const float* __restrict__ eb)
{
    extern __shared__ float sm[];
    float* s_xiT = sm;                 // [HDIM][HP] h[dst] transposed
    float* s_xjT = sm + HDIM * HP;     // [HDIM][HP] h[src]; later e_new
    float* s_eT  = sm + 2 * HDIM * HP; // [HDIM][HP] edge feats
    float* s_hT  = sm + 3 * HDIM * HP; // [HDIM][HP] hidden; also LN scratch [TR][RM]
    __shared__ int s_src[TR];
    __shared__ int s_dst[TR];

    const int tid = threadIdx.x;
    const size_t e0 = (size_t)blockIdx.x * TR;

    if (tid < TR)          s_src[tid]      = ei[e0 + tid];
    else if (tid < 2 * TR) s_dst[tid - TR] = ei[(size_t)N_EDGES + e0 + (tid - TR)];
    __syncthreads();

    // gather: coalesced global reads, transposed smem writes (feature = tid)
    #pragma unroll 4
    for (int r = 0; r < TR; r++) {
        s_xiT[tid * HP + r] = g_h[(size_t)s_dst[r] * HDIM + tid];
        s_xjT[tid * HP + r] = g_h[(size_t)s_src[r] * HDIM + tid];
        s_eT [tid * HP + r] = g_e[(e0 + r) * HDIM + tid];
    }
    __syncthreads();

    u64 acc[16];   // pair p covers rows (2p, 2p+1), column tid

    // GEMM1: hid = relu([xi,xj,e] @ We1 + be1)
    {
        const float bb = be1[tid];
        #pragma unroll
        for (int p = 0; p < 16; p++) acc[p] = pk2(bb, bb);
    }
    gemm_block(We1,                   tid, s_xiT, acc);
    gemm_block(We1 + HDIM * HDIM,     tid, s_xjT, acc);
    gemm_block(We1 + 2 * HDIM * HDIM, tid, s_eT,  acc);
    {
        u64* q = (u64*)(s_hT + tid * HP);
        #pragma unroll
        for (int p = 0; p < 16; p++) {
            float lo, hi; upk2(acc[p], lo, hi);
            q[p] = pk2(fmaxf(lo, 0.f), fmaxf(hi, 0.f));
        }
    }
    __syncthreads();

    // GEMM2: e_new = e + hid @ We2 + be2 ; t = e + e_new (kept in regs)
    u64 enew[16];
    {
        const float bb = be2[tid];
        #pragma unroll
        for (int p = 0; p < 16; p++) acc[p] = pk2(bb, bb);
        gemm_block(We2, tid, s_hT, acc);
        const u64* ecol = (const u64*)(s_eT + tid * HP);
        #pragma unroll
        for (int p = 0; p < 16; p++) {
            const u64 e2 = ecol[p];
            enew[p] = fadd2(acc[p], e2);     // e_new
            acc[p]  = fadd2(enew[p], e2);    // t = e + e_new (reuse acc)
        }
    }
    __syncthreads();   // everyone done reading s_hT (GEMM2 input)

    // store e_new (transposed, own column) and t (row-major scratch in s_hT)
    {
        u64* q = (u64*)(s_xjT + tid * HP);
        #pragma unroll
        for (int p = 0; p < 16; p++) {
            q[p] = enew[p];
            float lo, hi; upk2(acc[p], lo, hi);
            s_hT[(2 * p)     * RM + tid] = lo;
            s_hT[(2 * p + 1) * RM + tid] = hi;
        }
    }
    __syncthreads();

    // edge LayerNorm: g_e <- LN(t) * eg + eb (one warp per row)
    {
        const int warp = tid >> 5, lane = tid & 31;
        float g4[4], b4[4];
        #pragma unroll
        for (int j = 0; j < 4; j++) { g4[j] = eg[lane * 4 + j]; b4[j] = eb[lane * 4 + j]; }
        for (int r = warp; r < TR; r += 4) {
            const float4 v4 = *(const float4*)&s_hT[r * RM + lane * 4];
            float v[4] = { v4.x, v4.y, v4.z, v4.w };
            float s = 0.f, q = 0.f;
            #pragma unroll
            for (int j = 0; j < 4; j++) { s += v[j]; q += v[j] * v[j]; }
            #pragma unroll
            for (int o = 16; o > 0; o >>= 1) {
                s += __shfl_xor_sync(0xffffffffu, s, o);
                q += __shfl_xor_sync(0xffffffffu, q, o);
            }
            const float mean = s * (1.f / HDIM);
            const float var  = q * (1.f / HDIM) - mean * mean;
            const float rstd = rsqrtf(var + LN_EPS);
            float4 o4;
            o4.x = (v[0] - mean) * rstd * g4[0] + b4[0];
            o4.y = (v[1] - mean) * rstd * g4[1] + b4[1];
            o4.z = (v[2] - mean) * rstd * g4[2] + b4[2];
            o4.w = (v[3] - mean) * rstd * g4[3] + b4[3];
            *(float4*)&g_e[(e0 + r) * HDIM + lane * 4] = o4;
        }
    }
    __syncthreads();   // LN done reading s_hT scratch

    // GEMM3: hid2 = relu([xi, e_new] @ Wn1 + bn1) -> s_hT (transposed)
    {
        const float bb = bn1[tid];
        #pragma unroll
        for (int p = 0; p < 16; p++) acc[p] = pk2(bb, bb);
    }
    gemm_block(Wn1,               tid, s_xiT, acc);
    gemm_block(Wn1 + HDIM * HDIM, tid, s_xjT, acc);
    {
        u64* q = (u64*)(s_hT + tid * HP);
        #pragma unroll
        for (int p = 0; p < 16; p++) {
            float lo, hi; upk2(acc[p], lo, hi);
            q[p] = pk2(fmaxf(lo, 0.f), fmaxf(hi, 0.f));
        }
    }
    __syncthreads();

    // GEMM4: msg = xi + hid2 @ Wn2 + bn2 ; scatter red-add into g_hagg
    {
        const float bb = bn2[tid];
        #pragma unroll
        for (int p = 0; p < 16; p++) acc[p] = pk2(bb, bb);
        gemm_block(Wn2, tid, s_hT, acc);
        const u64* xicol = (const u64*)(s_xiT + tid * HP);
        #pragma unroll
        for (int p = 0; p < 16; p++) {
            const u64 m = fadd2(acc[p], xicol[p]);
            float lo, hi; upk2(m, lo, hi);
            float* p0 = &g_hagg[(size_t)s_dst[2 * p]     * HDIM + tid];
            float* p1 = &g_hagg[(size_t)s_dst[2 * p + 1] * HDIM + tid];
            asm volatile("red.global.add.f32 [%0], %1;" :: "l"(p0), "f"(lo) : "memory");
            asm volatile("red.global.add.f32 [%0], %1;" :: "l"(p1), "f"(hi) : "memory");
        }
    }
}

// ---------------- node update: g_h <- LN(h + h_agg); g_hagg <- 0 ----------------
__global__ void __launch_bounds__(256) node_update_kernel(
    const float* __restrict__ xg, const float* __restrict__ xb)
{
    const int warp = threadIdx.x >> 5, lane = threadIdx.x & 31;
    const int n = blockIdx.x * 8 + warp;
    if (n >= N_NODES) return;
    const size_t base = (size_t)n * HDIM + lane * 4;

    const float4 hv = *(const float4*)&g_h[base];
    const float4 av = *(const float4*)&g_hagg[base];
    float v[4] = { hv.x + av.x, hv.y + av.y, hv.z + av.z, hv.w + av.w };
    float s = 0.f, q = 0.f;
    #pragma unroll
    for (int j = 0; j < 4; j++) { s += v[j]; q += v[j] * v[j]; }
    #pragma unroll
    for (int o = 16; o > 0; o >>= 1) {
        s += __shfl_xor_sync(0xffffffffu, s, o);
        q += __shfl_xor_sync(0xffffffffu, q, o);
    }
    const float mean = s * (1.f / HDIM);
    const float var  = q * (1.f / HDIM) - mean * mean;
    const float rstd = rsqrtf(var + LN_EPS);

    float4 o4;
    o4.x = (v[0] - mean) * rstd * xg[lane * 4 + 0] + xb[lane * 4 + 0];
    o4.y = (v[1] - mean) * rstd * xg[lane * 4 + 1] + xb[lane * 4 + 1];
    o4.z = (v[2] - mean) * rstd * xg[lane * 4 + 2] + xb[lane * 4 + 2];
    o4.w = (v[3] - mean) * rstd * xg[lane * 4 + 3] + xb[lane * 4 + 3];
    *(float4*)&g_h[base]    = o4;
    *(float4*)&g_hagg[base] = make_float4(0.f, 0.f, 0.f, 0.f);
}

// ---------------- decoder ----------------
__global__ void __launch_bounds__(256) decoder_kernel(
    const float* __restrict__ w1, const float* __restrict__ b1,
    const float* __restrict__ w2, const float* __restrict__ b2,
    const float* __restrict__ noise, float* __restrict__ out)
{
    const int warp = threadIdx.x >> 5, lane = threadIdx.x & 31;
    const int n = blockIdx.x * 8 + warp;
    if (n >= N_NODES) return;
    const float* hrow = &g_h[(size_t)n * HDIM];

    float acc[4];
    #pragma unroll
    for (int j = 0; j < 4; j++) acc[j] = b1[lane * 4 + j];
    for (int k = 0; k < HDIM; k++) {
        const float hk = __ldg(&hrow[k]);
        const float4 w = *(const float4*)&w1[k * HDIM + lane * 4];
        acc[0] += hk * w.x; acc[1] += hk * w.y; acc[2] += hk * w.z; acc[3] += hk * w.w;
    }
    float o0 = 0.f, o1 = 0.f;
    #pragma unroll
    for (int j = 0; j < 4; j++) {
        const float hid = fmaxf(acc[j], 0.f);
        const int c = lane * 4 + j;
        o0 += hid * w2[c * 2 + 0];
        o1 += hid * w2[c * 2 + 1];
    }
    #pragma unroll
    for (int o = 16; o > 0; o >>= 1) {
        o0 += __shfl_xor_sync(0xffffffffu, o0, o);
        o1 += __shfl_xor_sync(0xffffffffu, o1, o);
    }
    if (lane == 0) {
        out[n * 2 + 0] = o0 + b2[0] - noise[n * 16 + 0];
        out[n * 2 + 1] = o1 + b2[1] - noise[n * 16 + 1];
    }
}

// ---------------- launch ----------------
extern "C" void kernel_launch(void* const* d_in, const int* in_sizes, int n_in,
                              void* d_out, int out_size)
{
    const float* x          = (const float*)d_in[0];
    const float* edge_attr  = (const float*)d_in[1];
    const int*   ei         = (const int*)d_in[2];
    const float* node_noise = (const float*)d_in[3];
    const float* edge_noise = (const float*)d_in[4];
    const float* nw1 = (const float*)d_in[5];  const float* nb1 = (const float*)d_in[6];
    const float* nw2 = (const float*)d_in[7];  const float* nb2 = (const float*)d_in[8];
    const float* ew1 = (const float*)d_in[9];  const float* eb1 = (const float*)d_in[10];
    const float* ew2 = (const float*)d_in[11]; const float* eb2 = (const float*)d_in[12];
    const float* gew1 = (const float*)d_in[13]; const float* geb1 = (const float*)d_in[14];
    const float* gew2 = (const float*)d_in[15]; const float* geb2 = (const float*)d_in[16];
    const float* gnw1 = (const float*)d_in[17]; const float* gnb1 = (const float*)d_in[18];
    const float* gnw2 = (const float*)d_in[19]; const float* gnb2 = (const float*)d_in[20];
    const float* xlg = (const float*)d_in[21]; const float* xlb = (const float*)d_in[22];
    const float* elg = (const float*)d_in[23]; const float* elb = (const float*)d_in[24];
    const float* dw1 = (const float*)d_in[25]; const float* db1 = (const float*)d_in[26];
    const float* dw2 = (const float*)d_in[27]; const float* db2 = (const float*)d_in[28];
    float* out = (float*)d_out;

    float *ph = nullptr, *pe = nullptr;
    cudaGetSymbolAddress((void**)&ph, g_h);
    cudaGetSymbolAddress((void**)&pe, g_e);

    const int gnn_smem = 4 * HDIM * HP * (int)sizeof(float);   // 73,728 B
    cudaFuncSetAttribute(gnn_layer_kernel,
                         cudaFuncAttributeMaxDynamicSharedMemorySize, gnn_smem);

    encoder_kernel<16><<<N_NODES / TR, 128>>>(x, node_noise, nw1, nb1, nw2, nb2, ph);
    encoder_kernel<8><<<N_EDGES / TR, 128>>>(edge_attr, edge_noise, ew1, eb1, ew2, eb2, pe);

    for (int l = 0; l < NLAYERS; l++) {
        gnn_layer_kernel<<<N_EDGES / TR, 128, gnn_smem>>>(
            ei, gew1, geb1, gew2, geb2, gnw1, gnb1, gnw2, gnb2,
            elg + (size_t)l * HDIM, elb + (size_t)l * HDIM);
        node_update_kernel<<<(N_NODES + 7) / 8, 256>>>(
            xlg + (size_t)l * HDIM, xlb + (size_t)l * HDIM);
    }

    decoder_kernel<<<(N_NODES + 7) / 8, 256>>>(dw1, db1, dw2, db2, node_noise, out);
}

// round 11
// speedup vs baseline: 6.4600x; 2.6595x over previous
/*
 * LearnedSimModel fused GNN - round 9: mma.sync bf16 2-term split (compute_103-safe).
 * gnn_layer_mma: 64-edge tiles, 4 warps, warp owns 16 rows x 128 cols.
 * 3-term split GEMMs (ah*Wh + al*Wh + ah*Wl), fp32 accum, in-register chaining:
 * accum fragment layout == next A fragment layout. Exact fp32 LN/residuals.
 * xi residual folded into node update via degree (deg trick).
 */
#include <cuda_runtime.h>
#include <cuda_bf16.h>
#include <cstdint>

#define N_NODES 20000
#define N_EDGES 640000
#define HDIM    128
#define NLAYERS 10
#define LN_EPS  1e-5f
#define TR      32
#define TE      64

// dynamic smem byte offsets (gnn kernel)
#define SXIH 0
#define SXIL 16384
#define STH  32768
#define STL  49152
#define SB   65536
#define SDST 98304
#define SSRC 98560
#define GNN_SMEM 98816

__device__ float g_h   [(size_t)N_NODES * HDIM];
__device__ float g_hagg[(size_t)N_NODES * HDIM];
__device__ float g_e   [(size_t)N_EDGES * HDIM];
__device__ float g_degf[N_NODES];
__device__ __nv_bfloat16 g_We1Th[128 * 384], g_We1Tl[128 * 384];
__device__ __nv_bfloat16 g_We2Th[128 * 128], g_We2Tl[128 * 128];
__device__ __nv_bfloat16 g_Wn1Th[128 * 256], g_Wn1Tl[128 * 256];
__device__ __nv_bfloat16 g_Wn2Th[128 * 128], g_Wn2Tl[128 * 128];

// ---------------- helpers ----------------
__device__ __forceinline__ uint32_t smem_u32(const void* p) {
    uint32_t a;
    asm("{ .reg .u64 t; cvta.to.shared.u64 t, %1; cvt.u32.u64 %0, t; }" : "=r"(a) : "l"(p));
    return a;
}
// pack two floats to bf16x2 (lo = a, hi = b)
__device__ __forceinline__ uint32_t pkhl(float a, float b) {
    uint32_t r; asm("cvt.rn.bf16x2.f32 %0,%1,%2;" : "=r"(r) : "f"(b), "f"(a)); return r;
}
// residual lo-pack: given hi-pack h of (a,b), return bf16x2 of (a-hi_a, b-hi_b)
__device__ __forceinline__ uint32_t lo2(uint32_t h, float a, float b) {
    const float ha = __uint_as_float(h << 16);
    const float hb = __uint_as_float(h & 0xFFFF0000u);
    return pkhl(a - ha, b - hb);
}
// swizzled byte offset: row r (0..127), 16B-group g (0..15) in a 256B-pitch tile
__device__ __forceinline__ uint32_t aoff(int r, int g) {
    return (uint32_t)(r * 256 + (((g & 8) | ((g ^ r) & 7)) << 4));
}
__device__ __forceinline__ void ldsm4(uint32_t a, uint32_t& r0, uint32_t& r1,
                                      uint32_t& r2, uint32_t& r3) {
    asm volatile("ldmatrix.sync.aligned.m8n8.x4.shared.b16 {%0,%1,%2,%3},[%4];"
                 : "=r"(r0), "=r"(r1), "=r"(r2), "=r"(r3) : "r"(a));
}
__device__ __forceinline__ void mma16816(float* c, uint32_t a0, uint32_t a1, uint32_t a2,
                                         uint32_t a3, uint32_t b0, uint32_t b1) {
    asm volatile(
        "mma.sync.aligned.m16n8k16.row.col.f32.bf16.bf16.f32 "
        "{%0,%1,%2,%3},{%4,%5,%6,%7},{%8,%9},{%0,%1,%2,%3};"
        : "+f"(c[0]), "+f"(c[1]), "+f"(c[2]), "+f"(c[3])
        : "r"(a0), "r"(a1), "r"(a2), "r"(a3), "r"(b0), "r"(b1));
}

// ---------------- GEMM passes ----------------
// A from smem tiles (hi [+ lo]) x staged B
template<bool LO>
__device__ __forceinline__ void pass_smemA(uint32_t sAhi, uint32_t sAlo, uint32_t sB,
                                           float (&acc)[16][4], int lane, int R0)
{
    const int bn = 8 * (lane >> 4) + (lane & 7);
    #pragma unroll 1
    for (int t = 0; t < 8; t++) {
        const uint32_t ar = aoff(R0 + (lane & 15), 2 * t + (lane >> 4));
        uint32_t ah0, ah1, ah2, ah3;
        ldsm4(sAhi + ar, ah0, ah1, ah2, ah3);
        uint32_t al0 = 0, al1 = 0, al2 = 0, al3 = 0;
        if (LO) ldsm4(sAlo + ar, al0, al1, al2, al3);
        const int bg = 2 * t + ((lane >> 3) & 1);
        #pragma unroll
        for (int j = 0; j < 8; j++) {
            uint32_t b0, b1, b2, b3;
            ldsm4(sB + aoff(16 * j + bn, bg), b0, b1, b2, b3);
            mma16816(acc[2 * j],     ah0, ah1, ah2, ah3, b0, b1);
            mma16816(acc[2 * j + 1], ah0, ah1, ah2, ah3, b2, b3);
            if (LO) {
                mma16816(acc[2 * j],     al0, al1, al2, al3, b0, b1);
                mma16816(acc[2 * j + 1], al0, al1, al2, al3, b2, b3);
            }
        }
    }
}
// A from register fragments (hi and lo) x staged B
__device__ __forceinline__ void pass_regA2(const uint32_t (&fh)[8][4], const uint32_t (&fl)[8][4],
                                           uint32_t sB, float (&acc)[16][4], int lane)
{
    const int bn = 8 * (lane >> 4) + (lane & 7);
    #pragma unroll
    for (int t = 0; t < 8; t++) {
        const int bg = 2 * t + ((lane >> 3) & 1);
        #pragma unroll
        for (int j = 0; j < 8; j++) {
            uint32_t b0, b1, b2, b3;
            ldsm4(sB + aoff(16 * j + bn, bg), b0, b1, b2, b3);
            mma16816(acc[2 * j],     fh[t][0], fh[t][1], fh[t][2], fh[t][3], b0, b1);
            mma16816(acc[2 * j + 1], fh[t][0], fh[t][1], fh[t][2], fh[t][3], b2, b3);
            mma16816(acc[2 * j],     fl[t][0], fl[t][1], fl[t][2], fl[t][3], b0, b1);
            mma16816(acc[2 * j + 1], fl[t][0], fl[t][1], fl[t][2], fl[t][3], b2, b3);
        }
    }
}
__device__ __forceinline__ void pass_regA1(const uint32_t (&fh)[8][4],
                                           uint32_t sB, float (&acc)[16][4], int lane)
{
    const int bn = 8 * (lane >> 4) + (lane & 7);
    #pragma unroll
    for (int t = 0; t < 8; t++) {
        const int bg = 2 * t + ((lane >> 3) & 1);
        #pragma unroll
        for (int j = 0; j < 8; j++) {
            uint32_t b0, b1, b2, b3;
            ldsm4(sB + aoff(16 * j + bn, bg), b0, b1, b2, b3);
            mma16816(acc[2 * j],     fh[t][0], fh[t][1], fh[t][2], fh[t][3], b0, b1);
            mma16816(acc[2 * j + 1], fh[t][0], fh[t][1], fh[t][2], fh[t][3], b2, b3);
        }
    }
}

// ---------------- staging ----------------
__device__ __forceinline__ void stageB(char* smem, const __nv_bfloat16* __restrict__ WT,
                                       int ktot, int k0, int tid)
{
    #pragma unroll 4
    for (int i = tid; i < 2048; i += 128) {
        const int n = i >> 4, g = i & 15;
        const uint4 v = *(const uint4*)(WT + (size_t)n * ktot + k0 + g * 8);
        *(uint4*)(smem + SB + aoff(n, g)) = v;
    }
}
__device__ __forceinline__ void stageA_rows(char* smem, uint32_t hiOff, uint32_t loOff,
                                            const float* __restrict__ src,
                                            const int* __restrict__ rows, int tid)
{
    #pragma unroll 2
    for (int i = tid; i < 1024; i += 128) {
        const int r = i >> 4, g = i & 15;
        const float4* p = (const float4*)(src + (size_t)rows[r] * HDIM + g * 8);
        const float4 u = p[0], v = p[1];
        const uint32_t h0 = pkhl(u.x, u.y), h1 = pkhl(u.z, u.w);
        const uint32_t h2 = pkhl(v.x, v.y), h3 = pkhl(v.z, v.w);
        uint4 H; H.x = h0; H.y = h1; H.z = h2; H.w = h3;
        uint4 L; L.x = lo2(h0, u.x, u.y); L.y = lo2(h1, u.z, u.w);
                 L.z = lo2(h2, v.x, v.y); L.w = lo2(h3, v.z, v.w);
        const uint32_t off = aoff(r, g);
        *(uint4*)(smem + hiOff + off) = H;
        *(uint4*)(smem + loOff + off) = L;
    }
}
__device__ __forceinline__ void stageA_lin(char* smem, uint32_t hiOff, uint32_t loOff,
                                           const float* __restrict__ base, int tid)
{
    #pragma unroll 2
    for (int i = tid; i < 1024; i += 128) {
        const int r = i >> 4, g = i & 15;
        const float4* p = (const float4*)(base + (size_t)r * HDIM + g * 8);
        const float4 u = p[0], v = p[1];
        const uint32_t h0 = pkhl(u.x, u.y), h1 = pkhl(u.z, u.w);
        const uint32_t h2 = pkhl(v.x, v.y), h3 = pkhl(v.z, v.w);
        uint4 H; H.x = h0; H.y = h1; H.z = h2; H.w = h3;
        uint4 L; L.x = lo2(h0, u.x, u.y); L.y = lo2(h1, u.z, u.w);
                 L.z = lo2(h2, v.x, v.y); L.w = lo2(h3, v.z, v.w);
        const uint32_t off = aoff(r, g);
        *(uint4*)(smem + hiOff + off) = H;
        *(uint4*)(smem + loOff + off) = L;
    }
}

// bias+relu on accums -> hi/lo A fragments for next GEMM
__device__ __forceinline__ void epi_relu_frag(float (&acc)[16][4], const float* __restrict__ bias,
                                              uint32_t (&fh)[8][4], uint32_t (&fl)[8][4], int lane)
{
    #pragma unroll
    for (int j = 0; j < 16; j++) {
        const int col = 8 * j + 2 * (lane & 3);
        const float b0 = bias[col], b1 = bias[col + 1];
        const float f0 = fmaxf(acc[j][0] + b0, 0.f);
        const float f1 = fmaxf(acc[j][1] + b1, 0.f);
        const float f2 = fmaxf(acc[j][2] + b0, 0.f);
        const float f3 = fmaxf(acc[j][3] + b1, 0.f);
        const int t = j >> 1, o = (j & 1) * 2;
        const uint32_t h01 = pkhl(f0, f1), h23 = pkhl(f2, f3);
        fh[t][o] = h01; fh[t][o + 1] = h23;
        fl[t][o] = lo2(h01, f0, f1); fl[t][o + 1] = lo2(h23, f2, f3);
    }
}
__device__ __forceinline__ void zacc(float (&acc)[16][4]) {
    #pragma unroll
    for (int j = 0; j < 16; j++)
        #pragma unroll
        for (int c = 0; c < 4; c++) acc[j][c] = 0.f;
}

// ---------------- fused GNN layer ----------------
__global__ void __launch_bounds__(128) gnn_layer_mma(
    const int* __restrict__ ei,
    const float* __restrict__ be1, const float* __restrict__ be2,
    const float* __restrict__ bn1, const float* __restrict__ bn2,
    const float* __restrict__ eg,  const float* __restrict__ eb)
{
    extern __shared__ char smem[];
    const uint32_t sb = smem_u32(smem);
    const int tid = threadIdx.x, lane = tid & 31, warp = tid >> 5;
    const int R0 = warp * 16;
    const int e0 = blockIdx.x * TE;
    int* s_dst = (int*)(smem + SDST);
    int* s_src = (int*)(smem + SSRC);

    if (tid < TE)            s_src[tid]      = ei[e0 + tid];
    else if (tid < 2 * TE)   s_dst[tid - TE] = ei[(size_t)N_EDGES + e0 + (tid - TE)];
    __syncthreads();

    float acc[16][4];
    uint32_t fh[8][4], fl[8][4];

    // ======== GEMM1: [xi | xj | e] @ We1 ========
    zacc(acc);
    stageA_rows(smem, SXIH, SXIL, g_h, s_dst, tid);          // xi (kept for GEMM3)
    stageB(smem, g_We1Th, 384, 0, tid);
    __syncthreads();
    pass_smemA<true>(sb + SXIH, sb + SXIL, sb + SB, acc, lane, R0);
    __syncthreads();
    stageB(smem, g_We1Tl, 384, 0, tid);
    __syncthreads();
    pass_smemA<false>(sb + SXIH, sb + SXIL, sb + SB, acc, lane, R0);
    __syncthreads();

    stageA_rows(smem, STH, STL, g_h, s_src, tid);            // xj
    stageB(smem, g_We1Th, 384, 128, tid);
    __syncthreads();
    pass_smemA<true>(sb + STH, sb + STL, sb + SB, acc, lane, R0);
    __syncthreads();
    stageB(smem, g_We1Tl, 384, 128, tid);
    __syncthreads();
    pass_smemA<false>(sb + STH, sb + STL, sb + SB, acc, lane, R0);
    __syncthreads();

    stageA_lin(smem, STH, STL, g_e + (size_t)e0 * HDIM, tid); // e
    stageB(smem, g_We1Th, 384, 256, tid);
    __syncthreads();
    pass_smemA<true>(sb + STH, sb + STL, sb + SB, acc, lane, R0);
    __syncthreads();
    stageB(smem, g_We1Tl, 384, 256, tid);
    __syncthreads();
    pass_smemA<false>(sb + STH, sb + STL, sb + SB, acc, lane, R0);

    epi_relu_frag(acc, be1, fh, fl, lane);   // hid -> fragments

    // ======== GEMM2: hid @ We2 ========
    zacc(acc);
    __syncthreads();
    stageB(smem, g_We2Th, 128, 0, tid);
    __syncthreads();
    pass_regA2(fh, fl, sb + SB, acc, lane);
    __syncthreads();
    stageB(smem, g_We2Tl, 128, 0, tid);
    __syncthreads();
    pass_regA1(fh, sb + SB, acc, lane);

    // ======== E2: e_new, edge LN ========
    {
        const int r0 = R0 + (lane >> 2);
        const int r1 = r0 + 8;
        float s0 = 0.f, q0 = 0.f, s1 = 0.f, q1 = 0.f;
        #pragma unroll
        for (int j = 0; j < 16; j++) {
            const int col = 8 * j + 2 * (lane & 3);
            const float b0 = be2[col], b1 = be2[col + 1];
            const float2 eA = *(const float2*)&g_e[(size_t)(e0 + r0) * HDIM + col];
            const float2 eB = *(const float2*)&g_e[(size_t)(e0 + r1) * HDIM + col];
            const float n0 = eA.x + acc[j][0] + b0;
            const float n1 = eA.y + acc[j][1] + b1;
            const float n2 = eB.x + acc[j][2] + b0;
            const float n3 = eB.y + acc[j][3] + b1;
            const int t = j >> 1, o = (j & 1) * 2;
            const uint32_t h01 = pkhl(n0, n1), h23 = pkhl(n2, n3);
            fh[t][o] = h01; fh[t][o + 1] = h23;
            fl[t][o] = lo2(h01, n0, n1); fl[t][o + 1] = lo2(h23, n2, n3);
            const float t0 = eA.x + n0, t1 = eA.y + n1;
            const float t2 = eB.x + n2, t3 = eB.y + n3;
            acc[j][0] = t0; acc[j][1] = t1; acc[j][2] = t2; acc[j][3] = t3;
            s0 += t0 + t1; q0 += t0 * t0 + t1 * t1;
            s1 += t2 + t3; q1 += t2 * t2 + t3 * t3;
        }
        s0 += __shfl_xor_sync(0xffffffffu, s0, 1); s0 += __shfl_xor_sync(0xffffffffu, s0, 2);
        q0 += __shfl_xor_sync(0xffffffffu, q0, 1); q0 += __shfl_xor_sync(0xffffffffu, q0, 2);
        s1 += __shfl_xor_sync(0xffffffffu, s1, 1); s1 += __shfl_xor_sync(0xffffffffu, s1, 2);
        q1 += __shfl_xor_sync(0xffffffffu, q1, 1); q1 += __shfl_xor_sync(0xffffffffu, q1, 2);
        const float m0 = s0 * (1.f / HDIM), m1 = s1 * (1.f / HDIM);
        const float r0std = rsqrtf(q0 * (1.f / HDIM) - m0 * m0 + LN_EPS);
        const float r1std = rsqrtf(q1 * (1.f / HDIM) - m1 * m1 + LN_EPS);
        #pragma unroll
        for (int j = 0; j < 16; j++) {
            const int col = 8 * j + 2 * (lane & 3);
            const float g0 = eg[col], g1 = eg[col + 1];
            const float bb0 = eb[col], bb1 = eb[col + 1];
            float2 oA, oB;
            oA.x = (acc[j][0] - m0) * r0std * g0 + bb0;
            oA.y = (acc[j][1] - m0) * r0std * g1 + bb1;
            oB.x = (acc[j][2] - m1) * r1std * g0 + bb0;
            oB.y = (acc[j][3] - m1) * r1std * g1 + bb1;
            *(float2*)&g_e[(size_t)(e0 + r0) * HDIM + col] = oA;
            *(float2*)&g_e[(size_t)(e0 + r1) * HDIM + col] = oB;
        }
    }

    // ======== GEMM3: [xi | e_new] @ Wn1 ========
    zacc(acc);
    __syncthreads();
    stageB(smem, g_Wn1Th, 256, 128, tid);       // e_new part (regs)
    __syncthreads();
    pass_regA2(fh, fl, sb + SB, acc, lane);
    __syncthreads();
    stageB(smem, g_Wn1Tl, 256, 128, tid);
    __syncthreads();
    pass_regA1(fh, sb + SB, acc, lane);
    __syncthreads();
    stageB(smem, g_Wn1Th, 256, 0, tid);         // xi part (smem tiles, kept)
    __syncthreads();
    pass_smemA<true>(sb + SXIH, sb + SXIL, sb + SB, acc, lane, R0);
    __syncthreads();
    stageB(smem, g_Wn1Tl, 256, 0, tid);
    __syncthreads();
    pass_smemA<false>(sb + SXIH, sb + SXIL, sb + SB, acc, lane, R0);

    epi_relu_frag(acc, bn1, fh, fl, lane);      // hid2 -> fragments

    // ======== GEMM4: hid2 @ Wn2 ========
    zacc(acc);
    __syncthreads();
    stageB(smem, g_Wn2Th, 128, 0, tid);
    __syncthreads();
    pass_regA2(fh, fl, sb + SB, acc, lane);
    __syncthreads();
    stageB(smem, g_Wn2Tl, 128, 0, tid);
    __syncthreads();
    pass_regA1(fh, sb + SB, acc, lane);

    // ======== E4: scatter msg-mlp (xi residual folded via deg) ========
    {
        const int r0 = R0 + (lane >> 2);
        const int r1 = r0 + 8;
        const int d0 = s_dst[r0], d1 = s_dst[r1];
        #pragma unroll
        for (int j = 0; j < 16; j++) {
            const int col = 8 * j + 2 * (lane & 3);
            const float b0 = bn2[col], b1 = bn2[col + 1];
            float* p0 = &g_hagg[(size_t)d0 * HDIM + col];
            float* p1 = &g_hagg[(size_t)d1 * HDIM + col];
            asm volatile("red.global.add.v2.f32 [%0], {%1,%2};"
                         :: "l"(p0), "f"(acc[j][0] + b0), "f"(acc[j][1] + b1) : "memory");
            asm volatile("red.global.add.v2.f32 [%0], {%1,%2};"
                         :: "l"(p1), "f"(acc[j][2] + b0), "f"(acc[j][3] + b1) : "memory");
        }
    }
}

// ---------------- prep kernels ----------------
__global__ void prep_w_kernel(const float* __restrict__ W, __nv_bfloat16* __restrict__ Wh,
                              __nv_bfloat16* __restrict__ Wl, int K)
{
    const int i = blockIdx.x * 256 + threadIdx.x;
    if (i < K * 128) {
        const int n = i & 127, k = i >> 7;
        const float v = W[(size_t)k * 128 + n];
        const __nv_bfloat16 h = __float2bfloat16(v);
        Wh[(size_t)n * K + k] = h;
        Wl[(size_t)n * K + k] = __float2bfloat16(v - __bfloat162float(h));
    }
}
__global__ void zero_deg_kernel() {
    const int i = blockIdx.x * 256 + threadIdx.x;
    if (i < N_NODES) g_degf[i] = 0.f;
}
__global__ void calc_deg_kernel(const int* __restrict__ ei) {
    const int i = blockIdx.x * 256 + threadIdx.x;
    if (i < N_EDGES) atomicAdd(&g_degf[ei[(size_t)N_EDGES + i]], 1.0f);
}

// ---------------- encoder (fp32 SIMT, exact) ----------------
template<int D>
__global__ void __launch_bounds__(128) encoder_kernel(
    const float* __restrict__ in, const float* __restrict__ noise,
    const float* __restrict__ w1, const float* __restrict__ b1,
    const float* __restrict__ w2, const float* __restrict__ b2,
    float* __restrict__ out)
{
    __shared__ float s_in [TR * D];
    __shared__ float s_hid[TR * HDIM];
    const int tid = threadIdx.x;
    const size_t row0 = (size_t)blockIdx.x * TR;

    for (int i = tid; i < TR * D; i += 128)
        s_in[i] = in[row0 * D + i] + noise[row0 * D + i];
    __syncthreads();

    float acc[TR];
    {
        const float bb = b1[tid];
        #pragma unroll
        for (int r = 0; r < TR; r++) acc[r] = bb;
    }
    #pragma unroll
    for (int k = 0; k < D; k++) {
        const float w = w1[k * HDIM + tid];
        #pragma unroll
        for (int r = 0; r < TR; r++) acc[r] += s_in[r * D + k] * w;
    }
    #pragma unroll
    for (int r = 0; r < TR; r++) s_hid[r * HDIM + tid] = fmaxf(acc[r], 0.f);
    __syncthreads();

    {
        const float bb = b2[tid];
        #pragma unroll
        for (int r = 0; r < TR; r++) acc[r] = bb;
    }
    for (int k = 0; k < HDIM; k++) {
        const float w = w2[k * HDIM + tid];
        #pragma unroll
        for (int r = 0; r < TR; r++) acc[r] += s_hid[r * HDIM + k] * w;
    }
    #pragma unroll
    for (int r = 0; r < TR; r++) out[(row0 + r) * HDIM + tid] = acc[r];
}

// ---------------- node update: g_h <- LN(h*(1+deg) + agg); g_hagg <- 0 ----------------
__global__ void __launch_bounds__(256) node_update_kernel(
    const float* __restrict__ xg, const float* __restrict__ xb)
{
    const int warp = threadIdx.x >> 5, lane = threadIdx.x & 31;
    const int n = blockIdx.x * 8 + warp;
    if (n >= N_NODES) return;
    const size_t base = (size_t)n * HDIM + lane * 4;
    const float dg1 = 1.f + g_degf[n];

    const float4 hv = *(const float4*)&g_h[base];
    const float4 av = *(const float4*)&g_hagg[base];
    float v[4] = { hv.x * dg1 + av.x, hv.y * dg1 + av.y,
                   hv.z * dg1 + av.z, hv.w * dg1 + av.w };
    float s = 0.f, q = 0.f;
    #pragma unroll
    for (int j = 0; j < 4; j++) { s += v[j]; q += v[j] * v[j]; }
    #pragma unroll
    for (int o = 16; o > 0; o >>= 1) {
        s += __shfl_xor_sync(0xffffffffu, s, o);
        q += __shfl_xor_sync(0xffffffffu, q, o);
    }
    const float mean = s * (1.f / HDIM);
    const float var  = q * (1.f / HDIM) - mean * mean;
    const float rstd = rsqrtf(var + LN_EPS);

    float4 o4;
    o4.x = (v[0] - mean) * rstd * xg[lane * 4 + 0] + xb[lane * 4 + 0];
    o4.y = (v[1] - mean) * rstd * xg[lane * 4 + 1] + xb[lane * 4 + 1];
    o4.z = (v[2] - mean) * rstd * xg[lane * 4 + 2] + xb[lane * 4 + 2];
    o4.w = (v[3] - mean) * rstd * xg[lane * 4 + 3] + xb[lane * 4 + 3];
    *(float4*)&g_h[base]    = o4;
    *(float4*)&g_hagg[base] = make_float4(0.f, 0.f, 0.f, 0.f);
}

// ---------------- decoder ----------------
__global__ void __launch_bounds__(256) decoder_kernel(
    const float* __restrict__ w1, const float* __restrict__ b1,
    const float* __restrict__ w2, const float* __restrict__ b2,
    const float* __restrict__ noise, float* __restrict__ out)
{
    const int warp = threadIdx.x >> 5, lane = threadIdx.x & 31;
    const int n = blockIdx.x * 8 + warp;
    if (n >= N_NODES) return;
    const float* hrow = &g_h[(size_t)n * HDIM];

    float acc[4];
    #pragma unroll
    for (int j = 0; j < 4; j++) acc[j] = b1[lane * 4 + j];
    for (int k = 0; k < HDIM; k++) {
        const float hk = __ldg(&hrow[k]);
        const float4 w = *(const float4*)&w1[k * HDIM + lane * 4];
        acc[0] += hk * w.x; acc[1] += hk * w.y; acc[2] += hk * w.z; acc[3] += hk * w.w;
    }
    float o0 = 0.f, o1 = 0.f;
    #pragma unroll
    for (int j = 0; j < 4; j++) {
        const float hid = fmaxf(acc[j], 0.f);
        const int c = lane * 4 + j;
        o0 += hid * w2[c * 2 + 0];
        o1 += hid * w2[c * 2 + 1];
    }
    #pragma unroll
    for (int o = 16; o > 0; o >>= 1) {
        o0 += __shfl_xor_sync(0xffffffffu, o0, o);
        o1 += __shfl_xor_sync(0xffffffffu, o1, o);
    }
    if (lane == 0) {
        out[n * 2 + 0] = o0 + b2[0] - noise[n * 16 + 0];
        out[n * 2 + 1] = o1 + b2[1] - noise[n * 16 + 1];
    }
}

// ---------------- launch ----------------
extern "C" void kernel_launch(void* const* d_in, const int* in_sizes, int n_in,
                              void* d_out, int out_size)
{
    const float* x          = (const float*)d_in[0];
    const float* edge_attr  = (const float*)d_in[1];
    const int*   ei         = (const int*)d_in[2];
    const float* node_noise = (const float*)d_in[3];
    const float* edge_noise = (const float*)d_in[4];
    const float* nw1 = (const float*)d_in[5];  const float* nb1 = (const float*)d_in[6];
    const float* nw2 = (const float*)d_in[7];  const float* nb2 = (const float*)d_in[8];
    const float* ew1 = (const float*)d_in[9];  const float* eb1 = (const float*)d_in[10];
    const float* ew2 = (const float*)d_in[11]; const float* eb2 = (const float*)d_in[12];
    const float* gew1 = (const float*)d_in[13]; const float* geb1 = (const float*)d_in[14];
    const float* gew2 = (const float*)d_in[15]; const float* geb2 = (const float*)d_in[16];
    const float* gnw1 = (const float*)d_in[17]; const float* gnb1 = (const float*)d_in[18];
    const float* gnw2 = (const float*)d_in[19]; const float* gnb2 = (const float*)d_in[20];
    const float* xlg = (const float*)d_in[21]; const float* xlb = (const float*)d_in[22];
    const float* elg = (const float*)d_in[23]; const float* elb = (const float*)d_in[24];
    const float* dw1 = (const float*)d_in[25]; const float* db1 = (const float*)d_in[26];
    const float* dw2 = (const float*)d_in[27]; const float* db2 = (const float*)d_in[28];
    float* out = (float*)d_out;

    float *ph = nullptr, *pe = nullptr;
    cudaGetSymbolAddress((void**)&ph, g_h);
    cudaGetSymbolAddress((void**)&pe, g_e);
    __nv_bfloat16 *w1h, *w1l, *w2h, *w2l, *w3h, *w3l, *w4h, *w4l;
    cudaGetSymbolAddress((void**)&w1h, g_We1Th); cudaGetSymbolAddress((void**)&w1l, g_We1Tl);
    cudaGetSymbolAddress((void**)&w2h, g_We2Th); cudaGetSymbolAddress((void**)&w2l, g_We2Tl);
    cudaGetSymbolAddress((void**)&w3h, g_Wn1Th); cudaGetSymbolAddress((void**)&w3l, g_Wn1Tl);
    cudaGetSymbolAddress((void**)&w4h, g_Wn2Th); cudaGetSymbolAddress((void**)&w4l, g_Wn2Tl);

    cudaFuncSetAttribute(gnn_layer_mma,
                         cudaFuncAttributeMaxDynamicSharedMemorySize, GNN_SMEM);

    zero_deg_kernel<<<(N_NODES + 255) / 256, 256>>>();
    calc_deg_kernel<<<(N_EDGES + 255) / 256, 256>>>(ei);
    prep_w_kernel<<<(384 * 128 + 255) / 256, 256>>>(gew1, w1h, w1l, 384);
    prep_w_kernel<<<(128 * 128 + 255) / 256, 256>>>(gew2, w2h, w2l, 128);
    prep_w_kernel<<<(256 * 128 + 255) / 256, 256>>>(gnw1, w3h, w3l, 256);
    prep_w_kernel<<<(128 * 128 + 255) / 256, 256>>>(gnw2, w4h, w4l, 128);

    encoder_kernel<16><<<N_NODES / TR, 128>>>(x, node_noise, nw1, nb1, nw2, nb2, ph);
    encoder_kernel<8><<<N_EDGES / TR, 128>>>(edge_attr, edge_noise, ew1, eb1, ew2, eb2, pe);

    for (int l = 0; l < NLAYERS; l++) {
        gnn_layer_mma<<<N_EDGES / TE, 128, GNN_SMEM>>>(
            ei, geb1, geb2, gnb1, gnb2,
            elg + (size_t)l * HDIM, elb + (size_t)l * HDIM);
        node_update_kernel<<<(N_NODES + 7) / 8, 256>>>(
            xlg + (size_t)l * HDIM, xlb + (size_t)l * HDIM);
    }

    decoder_kernel<<<(N_NODES + 7) / 8, 256>>>(dw1, db1, dw2, db2, node_noise, out);
}

// round 12
// speedup vs baseline: 6.7351x; 1.0426x over previous
/*
 * LearnedSimModel fused GNN - round 12: mma.sync bf16 3-term split, v2.
 * vs R11: co-resident Bh+Bl (single fused 3-term pass per K-block, half the
 * barriers), xi fragments kept in registers across GEMM1->GEMM3 (no xi smem
 * tile, no re-ldsm), cp.async B staging. Same math -> same rel_err.
 */
#include <cuda_runtime.h>
#include <cuda_bf16.h>
#include <cstdint>

#define N_NODES 20000
#define N_EDGES 640000
#define HDIM    128
#define NLAYERS 10
#define LN_EPS  1e-5f
#define TR      32
#define TE      64

// dynamic smem byte offsets (gnn kernel)
#define STH  0
#define STL  16384
#define SBH  32768
#define SBL  65536
#define SDST 98304
#define SSRC 98560
#define GNN_SMEM 98816

__device__ float g_h   [(size_t)N_NODES * HDIM];
__device__ float g_hagg[(size_t)N_NODES * HDIM];
__device__ float g_e   [(size_t)N_EDGES * HDIM];
__device__ float g_degf[N_NODES];
__device__ __nv_bfloat16 g_We1Th[128 * 384], g_We1Tl[128 * 384];
__device__ __nv_bfloat16 g_We2Th[128 * 128], g_We2Tl[128 * 128];
__device__ __nv_bfloat16 g_Wn1Th[128 * 256], g_Wn1Tl[128 * 256];
__device__ __nv_bfloat16 g_Wn2Th[128 * 128], g_Wn2Tl[128 * 128];

// ---------------- helpers ----------------
__device__ __forceinline__ uint32_t smem_u32(const void* p) {
    uint32_t a;
    asm("{ .reg .u64 t; cvta.to.shared.u64 t, %1; cvt.u32.u64 %0, t; }" : "=r"(a) : "l"(p));
    return a;
}
__device__ __forceinline__ uint32_t pkhl(float a, float b) {
    uint32_t r; asm("cvt.rn.bf16x2.f32 %0,%1,%2;" : "=r"(r) : "f"(b), "f"(a)); return r;
}
__device__ __forceinline__ uint32_t lo2(uint32_t h, float a, float b) {
    const float ha = __uint_as_float(h << 16);
    const float hb = __uint_as_float(h & 0xFFFF0000u);
    return pkhl(a - ha, b - hb);
}
// swizzled byte offset: row r (0..127), 16B-group g (0..15), 256B pitch
__device__ __forceinline__ uint32_t aoff(int r, int g) {
    return (uint32_t)(r * 256 + (((g & 8) | ((g ^ r) & 7)) << 4));
}
__device__ __forceinline__ void ldsm4(uint32_t a, uint32_t& r0, uint32_t& r1,
                                      uint32_t& r2, uint32_t& r3) {
    asm volatile("ldmatrix.sync.aligned.m8n8.x4.shared.b16 {%0,%1,%2,%3},[%4];"
                 : "=r"(r0), "=r"(r1), "=r"(r2), "=r"(r3) : "r"(a));
}
__device__ __forceinline__ void mma16816(float* c, uint32_t a0, uint32_t a1, uint32_t a2,
                                         uint32_t a3, uint32_t b0, uint32_t b1) {
    asm volatile(
        "mma.sync.aligned.m16n8k16.row.col.f32.bf16.bf16.f32 "
        "{%0,%1,%2,%3},{%4,%5,%6,%7},{%8,%9},{%0,%1,%2,%3};"
        : "+f"(c[0]), "+f"(c[1]), "+f"(c[2]), "+f"(c[3])
        : "r"(a0), "r"(a1), "r"(a2), "r"(a3), "r"(b0), "r"(b1));
}
__device__ __forceinline__ void cpa16(uint32_t dst, const void* src) {
    asm volatile("cp.async.cg.shared.global [%0], [%1], 16;" :: "r"(dst), "l"(src) : "memory");
}
__device__ __forceinline__ void cpa_commit_wait() {
    asm volatile("cp.async.commit_group;" ::: "memory");
    asm volatile("cp.async.wait_group 0;" ::: "memory");
}

// ---------------- fused 3-term GEMM passes (Bh+Bl co-resident) ----------------
// inner body for one (t) A-fragment against full N=128 of B (hi and lo)
#define PASS_J_BODY(A0,A1,A2,A3, L0,L1,L2,L3)                                   \
    _Pragma("unroll")                                                            \
    for (int j = 0; j < 8; j++) {                                                \
        uint32_t b0,b1,b2,b3,c0,c1,c2,c3;                                        \
        const uint32_t bo = aoff(16 * j + bn, bg);                               \
        ldsm4(sBh + bo, b0, b1, b2, b3);                                         \
        ldsm4(sBl + bo, c0, c1, c2, c3);                                         \
        mma16816(acc[2*j],   A0,A1,A2,A3, b0, b1);                               \
        mma16816(acc[2*j+1], A0,A1,A2,A3, b2, b3);                               \
        mma16816(acc[2*j],   L0,L1,L2,L3, b0, b1);                               \
        mma16816(acc[2*j+1], L0,L1,L2,L3, b2, b3);                               \
        mma16816(acc[2*j],   A0,A1,A2,A3, c0, c1);                               \
        mma16816(acc[2*j+1], A0,A1,A2,A3, c2, c3);                               \
    }

// A from smem; keep fragments in caller-provided arrays (xi path)
__device__ __forceinline__ void pass3_keep(uint32_t sAh, uint32_t sAl,
                                           uint32_t sBh, uint32_t sBl,
                                           float (&acc)[16][4], int lane, int R0,
                                           uint32_t (&kh)[8][4], uint32_t (&kl)[8][4])
{
    const int bn = 8 * (lane >> 4) + (lane & 7);
    #pragma unroll 1
    for (int t = 0; t < 8; t++) {
        const uint32_t ar = aoff(R0 + (lane & 15), 2 * t + (lane >> 4));
        ldsm4(sAh + ar, kh[t][0], kh[t][1], kh[t][2], kh[t][3]);
        ldsm4(sAl + ar, kl[t][0], kl[t][1], kl[t][2], kl[t][3]);
        const int bg = 2 * t + ((lane >> 3) & 1);
        PASS_J_BODY(kh[t][0], kh[t][1], kh[t][2], kh[t][3],
                    kl[t][0], kl[t][1], kl[t][2], kl[t][3])
    }
}
// A from smem; transient fragments (xj, e paths)
__device__ __forceinline__ void pass3_smem(uint32_t sAh, uint32_t sAl,
                                           uint32_t sBh, uint32_t sBl,
                                           float (&acc)[16][4], int lane, int R0)
{
    const int bn = 8 * (lane >> 4) + (lane & 7);
    #pragma unroll 1
    for (int t = 0; t < 8; t++) {
        const uint32_t ar = aoff(R0 + (lane & 15), 2 * t + (lane >> 4));
        uint32_t h0, h1, h2, h3, l0, l1, l2, l3;
        ldsm4(sAh + ar, h0, h1, h2, h3);
        ldsm4(sAl + ar, l0, l1, l2, l3);
        const int bg = 2 * t + ((lane >> 3) & 1);
        PASS_J_BODY(h0, h1, h2, h3, l0, l1, l2, l3)
    }
}
// A from registers
__device__ __forceinline__ void pass3_reg(const uint32_t (&fh)[8][4], const uint32_t (&fl)[8][4],
                                          uint32_t sBh, uint32_t sBl,
                                          float (&acc)[16][4], int lane)
{
    const int bn = 8 * (lane >> 4) + (lane & 7);
    #pragma unroll 1
    for (int t = 0; t < 8; t++) {
        const int bg = 2 * t + ((lane >> 3) & 1);
        PASS_J_BODY(fh[t][0], fh[t][1], fh[t][2], fh[t][3],
                    fl[t][0], fl[t][1], fl[t][2], fl[t][3])
    }
}

// ---------------- staging ----------------
__device__ __forceinline__ void stageB2(uint32_t sb, const __nv_bfloat16* __restrict__ Wh,
                                        const __nv_bfloat16* __restrict__ Wl,
                                        int ktot, int k0, int tid)
{
    #pragma unroll 4
    for (int i = tid; i < 2048; i += 128) {
        const int n = i >> 4, g = i & 15;
        const uint32_t o = aoff(n, g);
        const size_t gsrc = (size_t)n * ktot + k0 + g * 8;
        cpa16(sb + SBH + o, Wh + gsrc);
        cpa16(sb + SBL + o, Wl + gsrc);
    }
}
__device__ __forceinline__ void stageA_rows(char* smem, const float* __restrict__ src,
                                            const int* __restrict__ rows, int tid)
{
    #pragma unroll 2
    for (int i = tid; i < 1024; i += 128) {
        const int r = i >> 4, g = i & 15;
        const float4* p = (const float4*)(src + (size_t)rows[r] * HDIM + g * 8);
        const float4 u = p[0], v = p[1];
        const uint32_t h0 = pkhl(u.x, u.y), h1 = pkhl(u.z, u.w);
        const uint32_t h2 = pkhl(v.x, v.y), h3 = pkhl(v.z, v.w);
        uint4 H; H.x = h0; H.y = h1; H.z = h2; H.w = h3;
        uint4 L; L.x = lo2(h0, u.x, u.y); L.y = lo2(h1, u.z, u.w);
                 L.z = lo2(h2, v.x, v.y); L.w = lo2(h3, v.z, v.w);
        const uint32_t off = aoff(r, g);
        *(uint4*)(smem + STH + off) = H;
        *(uint4*)(smem + STL + off) = L;
    }
}
__device__ __forceinline__ void stageA_lin(char* smem, const float* __restrict__ base, int tid)
{
    #pragma unroll 2
    for (int i = tid; i < 1024; i += 128) {
        const int r = i >> 4, g = i & 15;
        const float4* p = (const float4*)(base + (size_t)r * HDIM + g * 8);
        const float4 u = p[0], v = p[1];
        const uint32_t h0 = pkhl(u.x, u.y), h1 = pkhl(u.z, u.w);
        const uint32_t h2 = pkhl(v.x, v.y), h3 = pkhl(v.z, v.w);
        uint4 H; H.x = h0; H.y = h1; H.z = h2; H.w = h3;
        uint4 L; L.x = lo2(h0, u.x, u.y); L.y = lo2(h1, u.z, u.w);
                 L.z = lo2(h2, v.x, v.y); L.w = lo2(h3, v.z, v.w);
        const uint32_t off = aoff(r, g);
        *(uint4*)(smem + STH + off) = H;
        *(uint4*)(smem + STL + off) = L;
    }
}
__device__ __forceinline__ void epi_relu_frag(float (&acc)[16][4], const float* __restrict__ bias,
                                              uint32_t (&fh)[8][4], uint32_t (&fl)[8][4], int lane)
{
    #pragma unroll
    for (int j = 0; j < 16; j++) {
        const int col = 8 * j + 2 * (lane & 3);
        const float b0 = bias[col], b1 = bias[col + 1];
        const float f0 = fmaxf(acc[j][0] + b0, 0.f);
        const float f1 = fmaxf(acc[j][1] + b1, 0.f);
        const float f2 = fmaxf(acc[j][2] + b0, 0.f);
        const float f3 = fmaxf(acc[j][3] + b1, 0.f);
        const int t = j >> 1, o = (j & 1) * 2;
        const uint32_t h01 = pkhl(f0, f1), h23 = pkhl(f2, f3);
        fh[t][o] = h01; fh[t][o + 1] = h23;
        fl[t][o] = lo2(h01, f0, f1); fl[t][o + 1] = lo2(h23, f2, f3);
    }
}
__device__ __forceinline__ void zacc(float (&acc)[16][4]) {
    #pragma unroll
    for (int j = 0; j < 16; j++)
        #pragma unroll
        for (int c = 0; c < 4; c++) acc[j][c] = 0.f;
}

// ---------------- fused GNN layer ----------------
__global__ void __launch_bounds__(128) gnn_layer_mma(
    const int* __restrict__ ei,
    const float* __restrict__ be1, const float* __restrict__ be2,
    const float* __restrict__ bn1, const float* __restrict__ bn2,
    const float* __restrict__ eg,  const float* __restrict__ eb)
{
    extern __shared__ char smem[];
    const uint32_t sb = smem_u32(smem);
    const int tid = threadIdx.x, lane = tid & 31, warp = tid >> 5;
    const int R0 = warp * 16;
    const int e0 = blockIdx.x * TE;
    int* s_dst = (int*)(smem + SDST);
    int* s_src = (int*)(smem + SSRC);

    if (tid < TE)            s_src[tid]      = ei[e0 + tid];
    else if (tid < 2 * TE)   s_dst[tid - TE] = ei[(size_t)N_EDGES + e0 + (tid - TE)];
    __syncthreads();

    float acc[16][4];
    uint32_t xih[8][4], xil[8][4];   // xi fragments, live GEMM1 -> GEMM3
    uint32_t enh[8][4], enl[8][4];   // e_new fragments, live E2 -> GEMM3
    uint32_t fh[8][4],  fl[8][4];    // hid / hid2 fragments

    // ======== GEMM1: [xi | xj | e] @ We1 ========
    zacc(acc);
    stageA_rows(smem, g_h, s_dst, tid);                       // xi
    stageB2(sb, g_We1Th, g_We1Tl, 384, 0, tid);
    cpa_commit_wait();
    __syncthreads();
    pass3_keep(sb + STH, sb + STL, sb + SBH, sb + SBL, acc, lane, R0, xih, xil);
    __syncthreads();

    stageA_rows(smem, g_h, s_src, tid);                       // xj
    stageB2(sb, g_We1Th, g_We1Tl, 384, 128, tid);
    cpa_commit_wait();
    __syncthreads();
    pass3_smem(sb + STH, sb + STL, sb + SBH, sb + SBL, acc, lane, R0);
    __syncthreads();

    stageA_lin(smem, g_e + (size_t)e0 * HDIM, tid);           // e
    stageB2(sb, g_We1Th, g_We1Tl, 384, 256, tid);
    cpa_commit_wait();
    __syncthreads();
    pass3_smem(sb + STH, sb + STL, sb + SBH, sb + SBL, acc, lane, R0);

    epi_relu_frag(acc, be1, fh, fl, lane);                    // hid

    // ======== GEMM2: hid @ We2 ========
    zacc(acc);
    __syncthreads();
    stageB2(sb, g_We2Th, g_We2Tl, 128, 0, tid);
    cpa_commit_wait();
    __syncthreads();
    pass3_reg(fh, fl, sb + SBH, sb + SBL, acc, lane);

    // ======== E2: e_new fragments + edge LN (global e re-read; no smem) ========
    {
        const int r0 = R0 + (lane >> 2);
        const int r1 = r0 + 8;
        float s0 = 0.f, q0 = 0.f, s1 = 0.f, q1 = 0.f;
        #pragma unroll
        for (int j = 0; j < 16; j++) {
            const int col = 8 * j + 2 * (lane & 3);
            const float b0 = be2[col], b1 = be2[col + 1];
            const float2 eA = *(const float2*)&g_e[(size_t)(e0 + r0) * HDIM + col];
            const float2 eB = *(const float2*)&g_e[(size_t)(e0 + r1) * HDIM + col];
            const float n0 = eA.x + acc[j][0] + b0;
            const float n1 = eA.y + acc[j][1] + b1;
            const float n2 = eB.x + acc[j][2] + b0;
            const float n3 = eB.y + acc[j][3] + b1;
            const int t = j >> 1, o = (j & 1) * 2;
            const uint32_t h01 = pkhl(n0, n1), h23 = pkhl(n2, n3);
            enh[t][o] = h01; enh[t][o + 1] = h23;
            enl[t][o] = lo2(h01, n0, n1); enl[t][o + 1] = lo2(h23, n2, n3);
            const float t0 = eA.x + n0, t1 = eA.y + n1;
            const float t2 = eB.x + n2, t3 = eB.y + n3;
            acc[j][0] = t0; acc[j][1] = t1; acc[j][2] = t2; acc[j][3] = t3;
            s0 += t0 + t1; q0 += t0 * t0 + t1 * t1;
            s1 += t2 + t3; q1 += t2 * t2 + t3 * t3;
        }
        s0 += __shfl_xor_sync(0xffffffffu, s0, 1); s0 += __shfl_xor_sync(0xffffffffu, s0, 2);
        q0 += __shfl_xor_sync(0xffffffffu, q0, 1); q0 += __shfl_xor_sync(0xffffffffu, q0, 2);
        s1 += __shfl_xor_sync(0xffffffffu, s1, 1); s1 += __shfl_xor_sync(0xffffffffu, s1, 2);
        q1 += __shfl_xor_sync(0xffffffffu, q1, 1); q1 += __shfl_xor_sync(0xffffffffu, q1, 2);
        const float m0 = s0 * (1.f / HDIM), m1 = s1 * (1.f / HDIM);
        const float r0std = rsqrtf(q0 * (1.f / HDIM) - m0 * m0 + LN_EPS);
        const float r1std = rsqrtf(q1 * (1.f / HDIM) - m1 * m1 + LN_EPS);
        #pragma unroll
        for (int j = 0; j < 16; j++) {
            const int col = 8 * j + 2 * (lane & 3);
            const float g0 = eg[col], g1 = eg[col + 1];
            const float bb0 = eb[col], bb1 = eb[col + 1];
            float2 oA, oB;
            oA.x = (acc[j][0] - m0) * r0std * g0 + bb0;
            oA.y = (acc[j][1] - m0) * r0std * g1 + bb1;
            oB.x = (acc[j][2] - m1) * r1std * g0 + bb0;
            oB.y = (acc[j][3] - m1) * r1std * g1 + bb1;
            *(float2*)&g_e[(size_t)(e0 + r0) * HDIM + col] = oA;
            *(float2*)&g_e[(size_t)(e0 + r1) * HDIM + col] = oB;
        }
    }

    // ======== GEMM3: [xi | e_new] @ Wn1 (both from registers) ========
    zacc(acc);
    __syncthreads();
    stageB2(sb, g_Wn1Th, g_Wn1Tl, 256, 0, tid);               // xi part
    cpa_commit_wait();
    __syncthreads();
    pass3_reg(xih, xil, sb + SBH, sb + SBL, acc, lane);
    __syncthreads();
    stageB2(sb, g_Wn1Th, g_Wn1Tl, 256, 128, tid);             // e_new part
    cpa_commit_wait();
    __syncthreads();
    pass3_reg(enh, enl, sb + SBH, sb + SBL, acc, lane);

    epi_relu_frag(acc, bn1, fh, fl, lane);                    // hid2

    // ======== GEMM4: hid2 @ Wn2 ========
    zacc(acc);
    __syncthreads();
    stageB2(sb, g_Wn2Th, g_Wn2Tl, 128, 0, tid);
    cpa_commit_wait();
    __syncthreads();
    pass3_reg(fh, fl, sb + SBH, sb + SBL, acc, lane);

    // ======== E4: scatter msg-mlp (xi residual folded via deg) ========
    {
        const int r0 = R0 + (lane >> 2);
        const int r1 = r0 + 8;
        const int d0 = s_dst[r0], d1 = s_dst[r1];
        #pragma unroll
        for (int j = 0; j < 16; j++) {
            const int col = 8 * j + 2 * (lane & 3);
            const float b0 = bn2[col], b1 = bn2[col + 1];
            float* p0 = &g_hagg[(size_t)d0 * HDIM + col];
            float* p1 = &g_hagg[(size_t)d1 * HDIM + col];
            asm volatile("red.global.add.v2.f32 [%0], {%1,%2};"
                         :: "l"(p0), "f"(acc[j][0] + b0), "f"(acc[j][1] + b1) : "memory");
            asm volatile("red.global.add.v2.f32 [%0], {%1,%2};"
                         :: "l"(p1), "f"(acc[j][2] + b0), "f"(acc[j][3] + b1) : "memory");
        }
    }
}

// ---------------- prep kernels ----------------
__global__ void prep_w_kernel(const float* __restrict__ W, __nv_bfloat16* __restrict__ Wh,
                              __nv_bfloat16* __restrict__ Wl, int K)
{
    const int i = blockIdx.x * 256 + threadIdx.x;
    if (i < K * 128) {
        const int n = i & 127, k = i >> 7;
        const float v = W[(size_t)k * 128 + n];
        const __nv_bfloat16 h = __float2bfloat16(v);
        Wh[(size_t)n * K + k] = h;
        Wl[(size_t)n * K + k] = __float2bfloat16(v - __bfloat162float(h));
    }
}
__global__ void zero_deg_kernel() {
    const int i = blockIdx.x * 256 + threadIdx.x;
    if (i < N_NODES) g_degf[i] = 0.f;
}
__global__ void calc_deg_kernel(const int* __restrict__ ei) {
    const int i = blockIdx.x * 256 + threadIdx.x;
    if (i < N_EDGES) atomicAdd(&g_degf[ei[(size_t)N_EDGES + i]], 1.0f);
}

// ---------------- encoder (fp32 SIMT, exact) ----------------
template<int D>
__global__ void __launch_bounds__(128) encoder_kernel(
    const float* __restrict__ in, const float* __restrict__ noise,
    const float* __restrict__ w1, const float* __restrict__ b1,
    const float* __restrict__ w2, const float* __restrict__ b2,
    float* __restrict__ out)
{
    __shared__ float s_in [TR * D];
    __shared__ float s_hid[TR * HDIM];
    const int tid = threadIdx.x;
    const size_t row0 = (size_t)blockIdx.x * TR;

    for (int i = tid; i < TR * D; i += 128)
        s_in[i] = in[row0 * D + i] + noise[row0 * D + i];
    __syncthreads();

    float acc[TR];
    {
        const float bb = b1[tid];
        #pragma unroll
        for (int r = 0; r < TR; r++) acc[r] = bb;
    }
    #pragma unroll
    for (int k = 0; k < D; k++) {
        const float w = w1[k * HDIM + tid];
        #pragma unroll
        for (int r = 0; r < TR; r++) acc[r] += s_in[r * D + k] * w;
    }
    #pragma unroll
    for (int r = 0; r < TR; r++) s_hid[r * HDIM + tid] = fmaxf(acc[r], 0.f);
    __syncthreads();

    {
        const float bb = b2[tid];
        #pragma unroll
        for (int r = 0; r < TR; r++) acc[r] = bb;
    }
    for (int k = 0; k < HDIM; k++) {
        const float w = w2[k * HDIM + tid];
        #pragma unroll
        for (int r = 0; r < TR; r++) acc[r] += s_hid[r * HDIM + k] * w;
    }
    #pragma unroll
    for (int r = 0; r < TR; r++) out[(row0 + r) * HDIM + tid] = acc[r];
}

// ---------------- node update: g_h <- LN(h*(1+deg) + agg); g_hagg <- 0 ----------------
__global__ void __launch_bounds__(256) node_update_kernel(
    const float* __restrict__ xg, const float* __restrict__ xb)
{
    const int warp = threadIdx.x >> 5, lane = threadIdx.x & 31;
    const int n = blockIdx.x * 8 + warp;
    if (n >= N_NODES) return;
    const size_t base = (size_t)n * HDIM + lane * 4;
    const float dg1 = 1.f + g_degf[n];

    const float4 hv = *(const float4*)&g_h[base];
    const float4 av = *(const float4*)&g_hagg[base];
    float v[4] = { hv.x * dg1 + av.x, hv.y * dg1 + av.y,
                   hv.z * dg1 + av.z, hv.w * dg1 + av.w };
    float s = 0.f, q = 0.f;
    #pragma unroll
    for (int j = 0; j < 4; j++) { s += v[j]; q += v[j] * v[j]; }
    #pragma unroll
    for (int o = 16; o > 0; o >>= 1) {
        s += __shfl_xor_sync(0xffffffffu, s, o);
        q += __shfl_xor_sync(0xffffffffu, q, o);
    }
    const float mean = s * (1.f / HDIM);
    const float var  = q * (1.f / HDIM) - mean * mean;
    const float rstd = rsqrtf(var + LN_EPS);

    float4 o4;
    o4.x = (v[0] - mean) * rstd * xg[lane * 4 + 0] + xb[lane * 4 + 0];
    o4.y = (v[1] - mean) * rstd * xg[lane * 4 + 1] + xb[lane * 4 + 1];
    o4.z = (v[2] - mean) * rstd * xg[lane * 4 + 2] + xb[lane * 4 + 2];
    o4.w = (v[3] - mean) * rstd * xg[lane * 4 + 3] + xb[lane * 4 + 3];
    *(float4*)&g_h[base]    = o4;
    *(float4*)&g_hagg[base] = make_float4(0.f, 0.f, 0.f, 0.f);
}

// ---------------- decoder ----------------
__global__ void __launch_bounds__(256) decoder_kernel(
    const float* __restrict__ w1, const float* __restrict__ b1,
    const float* __restrict__ w2, const float* __restrict__ b2,
    const float* __restrict__ noise, float* __restrict__ out)
{
    const int warp = threadIdx.x >> 5, lane = threadIdx.x & 31;
    const int n = blockIdx.x * 8 + warp;
    if (n >= N_NODES) return;
    const float* hrow = &g_h[(size_t)n * HDIM];

    float acc[4];
    #pragma unroll
    for (int j = 0; j < 4; j++) acc[j] = b1[lane * 4 + j];
    for (int k = 0; k < HDIM; k++) {
        const float hk = __ldg(&hrow[k]);
        const float4 w = *(const float4*)&w1[k * HDIM + lane * 4];
        acc[0] += hk * w.x; acc[1] += hk * w.y; acc[2] += hk * w.z; acc[3] += hk * w.w;
    }
    float o0 = 0.f, o1 = 0.f;
    #pragma unroll
    for (int j = 0; j < 4; j++) {
        const float hid = fmaxf(acc[j], 0.f);
        const int c = lane * 4 + j;
        o0 += hid * w2[c * 2 + 0];
        o1 += hid * w2[c * 2 + 1];
    }
    #pragma unroll
    for (int o = 16; o > 0; o >>= 1) {
        o0 += __shfl_xor_sync(0xffffffffu, o0, o);
        o1 += __shfl_xor_sync(0xffffffffu, o1, o);
    }
    if (lane == 0) {
        out[n * 2 + 0] = o0 + b2[0] - noise[n * 16 + 0];
        out[n * 2 + 1] = o1 + b2[1] - noise[n * 16 + 1];
    }
}

// ---------------- launch ----------------
extern "C" void kernel_launch(void* const* d_in, const int* in_sizes, int n_in,
                              void* d_out, int out_size)
{
    const float* x          = (const float*)d_in[0];
    const float* edge_attr  = (const float*)d_in[1];
    const int*   ei         = (const int*)d_in[2];
    const float* node_noise = (const float*)d_in[3];
    const float* edge_noise = (const float*)d_in[4];
    const float* nw1 = (const float*)d_in[5];  const float* nb1 = (const float*)d_in[6];
    const float* nw2 = (const float*)d_in[7];  const float* nb2 = (const float*)d_in[8];
    const float* ew1 = (const float*)d_in[9];  const float* eb1 = (const float*)d_in[10];
    const float* ew2 = (const float*)d_in[11]; const float* eb2 = (const float*)d_in[12];
    const float* gew1 = (const float*)d_in[13]; const float* geb1 = (const float*)d_in[14];
    const float* gew2 = (const float*)d_in[15]; const float* geb2 = (const float*)d_in[16];
    const float* gnw1 = (const float*)d_in[17]; const float* gnb1 = (const float*)d_in[18];
    const float* gnw2 = (const float*)d_in[19]; const float* gnb2 = (const float*)d_in[20];
    const float* xlg = (const float*)d_in[21]; const float* xlb = (const float*)d_in[22];
    const float* elg = (const float*)d_in[23]; const float* elb = (const float*)d_in[24];
    const float* dw1 = (const float*)d_in[25]; const float* db1 = (const float*)d_in[26];
    const float* dw2 = (const float*)d_in[27]; const float* db2 = (const float*)d_in[28];
    float* out = (float*)d_out;

    float *ph = nullptr, *pe = nullptr;
    cudaGetSymbolAddress((void**)&ph, g_h);
    cudaGetSymbolAddress((void**)&pe, g_e);
    __nv_bfloat16 *w1h, *w1l, *w2h, *w2l, *w3h, *w3l, *w4h, *w4l;
    cudaGetSymbolAddress((void**)&w1h, g_We1Th); cudaGetSymbolAddress((void**)&w1l, g_We1Tl);
    cudaGetSymbolAddress((void**)&w2h, g_We2Th); cudaGetSymbolAddress((void**)&w2l, g_We2Tl);
    cudaGetSymbolAddress((void**)&w3h, g_Wn1Th); cudaGetSymbolAddress((void**)&w3l, g_Wn1Tl);
    cudaGetSymbolAddress((void**)&w4h, g_Wn2Th); cudaGetSymbolAddress((void**)&w4l, g_Wn2Tl);

    cudaFuncSetAttribute(gnn_layer_mma,
                         cudaFuncAttributeMaxDynamicSharedMemorySize, GNN_SMEM);

    zero_deg_kernel<<<(N_NODES + 255) / 256, 256>>>();
    calc_deg_kernel<<<(N_EDGES + 255) / 256, 256>>>(ei);
    prep_w_kernel<<<(384 * 128 + 255) / 256, 256>>>(gew1, w1h, w1l, 384);
    prep_w_kernel<<<(128 * 128 + 255) / 256, 256>>>(gew2, w2h, w2l, 128);
    prep_w_kernel<<<(256 * 128 + 255) / 256, 256>>>(gnw1, w3h, w3l, 256);
    prep_w_kernel<<<(128 * 128 + 255) / 256, 256>>>(gnw2, w4h, w4l, 128);

    encoder_kernel<16><<<N_NODES / TR, 128>>>(x, node_noise, nw1, nb1, nw2, nb2, ph);
    encoder_kernel<8><<<N_EDGES / TR, 128>>>(edge_attr, edge_noise, ew1, eb1, ew2, eb2, pe);

    for (int l = 0; l < NLAYERS; l++) {
        gnn_layer_mma<<<N_EDGES / TE, 128, GNN_SMEM>>>(
            ei, geb1, geb2, gnb1, gnb2,
            elg + (size_t)l * HDIM, elb + (size_t)l * HDIM);
        node_update_kernel<<<(N_NODES + 7) / 8, 256>>>(
            xlg + (size_t)l * HDIM, xlb + (size_t)l * HDIM);
    }

    decoder_kernel<<<(N_NODES + 7) / 8, 256>>>(dw1, db1, dw2, db2, node_noise, out);
}

// round 13
// speedup vs baseline: 7.2842x; 1.0815x over previous
/*
 * LearnedSimModel fused GNN - round 13: mma.sync bf16 3-term split, v3.
 * vs R12: TE=128 (256 thr, 8 warps, warp owns 16 rows - per-warp math identical),
 * double-buffered B staging via cp.async commit/wait_group(1) so weight loads
 * overlap MMA compute; B L2 traffic and barrier count per edge halved.
 */
#include <cuda_runtime.h>
#include <cuda_bf16.h>
#include <cstdint>

#define N_NODES 20000
#define N_EDGES 640000
#define HDIM    128
#define NLAYERS 10
#define LN_EPS  1e-5f
#define TR      32
#define TE      128
#define THREADS 256

// dynamic smem byte offsets (gnn kernel)
#define STH   0
#define STL   32768
#define SB0H  65536
#define SB0L  98304
#define SB1H  131072
#define SB1L  163840
#define SDST  196608
#define SSRC  197120
#define GNN_SMEM 197632

__device__ float g_h   [(size_t)N_NODES * HDIM];
__device__ float g_hagg[(size_t)N_NODES * HDIM];
__device__ float g_e   [(size_t)N_EDGES * HDIM];
__device__ float g_degf[N_NODES];
__device__ __nv_bfloat16 g_We1Th[128 * 384], g_We1Tl[128 * 384];
__device__ __nv_bfloat16 g_We2Th[128 * 128], g_We2Tl[128 * 128];
__device__ __nv_bfloat16 g_Wn1Th[128 * 256], g_Wn1Tl[128 * 256];
__device__ __nv_bfloat16 g_Wn2Th[128 * 128], g_Wn2Tl[128 * 128];

// ---------------- helpers ----------------
__device__ __forceinline__ uint32_t smem_u32(const void* p) {
    uint32_t a;
    asm("{ .reg .u64 t; cvta.to.shared.u64 t, %1; cvt.u32.u64 %0, t; }" : "=r"(a) : "l"(p));
    return a;
}
__device__ __forceinline__ uint32_t pkhl(float a, float b) {
    uint32_t r; asm("cvt.rn.bf16x2.f32 %0,%1,%2;" : "=r"(r) : "f"(b), "f"(a)); return r;
}
__device__ __forceinline__ uint32_t lo2(uint32_t h, float a, float b) {
    const float ha = __uint_as_float(h << 16);
    const float hb = __uint_as_float(h & 0xFFFF0000u);
    return pkhl(a - ha, b - hb);
}
// swizzled byte offset: row r (0..127), 16B-group g (0..15), 256B pitch
__device__ __forceinline__ uint32_t aoff(int r, int g) {
    return (uint32_t)(r * 256 + (((g & 8) | ((g ^ r) & 7)) << 4));
}
__device__ __forceinline__ void ldsm4(uint32_t a, uint32_t& r0, uint32_t& r1,
                                      uint32_t& r2, uint32_t& r3) {
    asm volatile("ldmatrix.sync.aligned.m8n8.x4.shared.b16 {%0,%1,%2,%3},[%4];"
                 : "=r"(r0), "=r"(r1), "=r"(r2), "=r"(r3) : "r"(a));
}
__device__ __forceinline__ void mma16816(float* c, uint32_t a0, uint32_t a1, uint32_t a2,
                                         uint32_t a3, uint32_t b0, uint32_t b1) {
    asm volatile(
        "mma.sync.aligned.m16n8k16.row.col.f32.bf16.bf16.f32 "
        "{%0,%1,%2,%3},{%4,%5,%6,%7},{%8,%9},{%0,%1,%2,%3};"
        : "+f"(c[0]), "+f"(c[1]), "+f"(c[2]), "+f"(c[3])
        : "r"(a0), "r"(a1), "r"(a2), "r"(a3), "r"(b0), "r"(b1));
}
__device__ __forceinline__ void cpa16(uint32_t dst, const void* src) {
    asm volatile("cp.async.cg.shared.global [%0], [%1], 16;" :: "r"(dst), "l"(src) : "memory");
}
__device__ __forceinline__ void cpa_commit() {
    asm volatile("cp.async.commit_group;" ::: "memory");
}
__device__ __forceinline__ void cpa_wait1() {
    asm volatile("cp.async.wait_group 1;" ::: "memory");
}
__device__ __forceinline__ void cpa_wait0() {
    asm volatile("cp.async.wait_group 0;" ::: "memory");
}

// ---------------- fused 3-term GEMM passes (Bh+Bl co-resident) ----------------
#define PASS_J_BODY(A0,A1,A2,A3, L0,L1,L2,L3)                                   \
    _Pragma("unroll")                                                            \
    for (int j = 0; j < 8; j++) {                                                \
        uint32_t b0,b1,b2,b3,c0,c1,c2,c3;                                        \
        const uint32_t bo = aoff(16 * j + bn, bg);                               \
        ldsm4(sBh + bo, b0, b1, b2, b3);                                         \
        ldsm4(sBl + bo, c0, c1, c2, c3);                                         \
        mma16816(acc[2*j],   A0,A1,A2,A3, b0, b1);                               \
        mma16816(acc[2*j+1], A0,A1,A2,A3, b2, b3);                               \
        mma16816(acc[2*j],   L0,L1,L2,L3, b0, b1);                               \
        mma16816(acc[2*j+1], L0,L1,L2,L3, b2, b3);                               \
        mma16816(acc[2*j],   A0,A1,A2,A3, c0, c1);                               \
        mma16816(acc[2*j+1], A0,A1,A2,A3, c2, c3);                               \
    }

__device__ __forceinline__ void pass3_keep(uint32_t sAh, uint32_t sAl,
                                           uint32_t sBh, uint32_t sBl,
                                           float (&acc)[16][4], int lane, int R0,
                                           uint32_t (&kh)[8][4], uint32_t (&kl)[8][4])
{
    const int bn = 8 * (lane >> 4) + (lane & 7);
    #pragma unroll 1
    for (int t = 0; t < 8; t++) {
        const uint32_t ar = aoff(R0 + (lane & 15), 2 * t + (lane >> 4));
        ldsm4(sAh + ar, kh[t][0], kh[t][1], kh[t][2], kh[t][3]);
        ldsm4(sAl + ar, kl[t][0], kl[t][1], kl[t][2], kl[t][3]);
        const int bg = 2 * t + ((lane >> 3) & 1);
        PASS_J_BODY(kh[t][0], kh[t][1], kh[t][2], kh[t][3],
                    kl[t][0], kl[t][1], kl[t][2], kl[t][3])
    }
}
__device__ __forceinline__ void pass3_smem(uint32_t sAh, uint32_t sAl,
                                           uint32_t sBh, uint32_t sBl,
                                           float (&acc)[16][4], int lane, int R0)
{
    const int bn = 8 * (lane >> 4) + (lane & 7);
    #pragma unroll 1
    for (int t = 0; t < 8; t++) {
        const uint32_t ar = aoff(R0 + (lane & 15), 2 * t + (lane >> 4));
        uint32_t h0, h1, h2, h3, l0, l1, l2, l3;
        ldsm4(sAh + ar, h0, h1, h2, h3);
        ldsm4(sAl + ar, l0, l1, l2, l3);
        const int bg = 2 * t + ((lane >> 3) & 1);
        PASS_J_BODY(h0, h1, h2, h3, l0, l1, l2, l3)
    }
}
__device__ __forceinline__ void pass3_reg(const uint32_t (&fh)[8][4], const uint32_t (&fl)[8][4],
                                          uint32_t sBh, uint32_t sBl,
                                          float (&acc)[16][4], int lane)
{
    const int bn = 8 * (lane >> 4) + (lane & 7);
    #pragma unroll 1
    for (int t = 0; t < 8; t++) {
        const int bg = 2 * t + ((lane >> 3) & 1);
        PASS_J_BODY(fh[t][0], fh[t][1], fh[t][2], fh[t][3],
                    fl[t][0], fl[t][1], fl[t][2], fl[t][3])
    }
}

// ---------------- staging ----------------
__device__ __forceinline__ void stageB2(uint32_t sb, uint32_t bH, uint32_t bL,
                                        const __nv_bfloat16* __restrict__ Wh,
                                        const __nv_bfloat16* __restrict__ Wl,
                                        int ktot, int k0, int tid)
{
    #pragma unroll 4
    for (int i = tid; i < 2048; i += THREADS) {
        const int n = i >> 4, g = i & 15;
        const uint32_t o = aoff(n, g);
        const size_t gsrc = (size_t)n * ktot + k0 + g * 8;
        cpa16(sb + bH + o, Wh + gsrc);
        cpa16(sb + bL + o, Wl + gsrc);
    }
}
__device__ __forceinline__ void stageA_rows(char* smem, const float* __restrict__ src,
                                            const int* __restrict__ rows, int tid)
{
    #pragma unroll 2
    for (int i = tid; i < 2048; i += THREADS) {
        const int r = i >> 4, g = i & 15;
        const float4* p = (const float4*)(src + (size_t)rows[r] * HDIM + g * 8);
        const float4 u = p[0], v = p[1];
        const uint32_t h0 = pkhl(u.x, u.y), h1 = pkhl(u.z, u.w);
        const uint32_t h2 = pkhl(v.x, v.y), h3 = pkhl(v.z, v.w);
        uint4 H; H.x = h0; H.y = h1; H.z = h2; H.w = h3;
        uint4 L; L.x = lo2(h0, u.x, u.y); L.y = lo2(h1, u.z, u.w);
                 L.z = lo2(h2, v.x, v.y); L.w = lo2(h3, v.z, v.w);
        const uint32_t off = aoff(r, g);
        *(uint4*)(smem + STH + off) = H;
        *(uint4*)(smem + STL + off) = L;
    }
}
__device__ __forceinline__ void stageA_lin(char* smem, const float* __restrict__ base, int tid)
{
    #pragma unroll 2
    for (int i = tid; i < 2048; i += THREADS) {
        const int r = i >> 4, g = i & 15;
        const float4* p = (const float4*)(base + (size_t)r * HDIM + g * 8);
        const float4 u = p[0], v = p[1];
        const uint32_t h0 = pkhl(u.x, u.y), h1 = pkhl(u.z, u.w);
        const uint32_t h2 = pkhl(v.x, v.y), h3 = pkhl(v.z, v.w);
        uint4 H; H.x = h0; H.y = h1; H.z = h2; H.w = h3;
        uint4 L; L.x = lo2(h0, u.x, u.y); L.y = lo2(h1, u.z, u.w);
                 L.z = lo2(h2, v.x, v.y); L.w = lo2(h3, v.z, v.w);
        const uint32_t off = aoff(r, g);
        *(uint4*)(smem + STH + off) = H;
        *(uint4*)(smem + STL + off) = L;
    }
}
__device__ __forceinline__ void epi_relu_frag(float (&acc)[16][4], const float* __restrict__ bias,
                                              uint32_t (&fh)[8][4], uint32_t (&fl)[8][4], int lane)
{
    #pragma unroll
    for (int j = 0; j < 16; j++) {
        const int col = 8 * j + 2 * (lane & 3);
        const float b0 = bias[col], b1 = bias[col + 1];
        const float f0 = fmaxf(acc[j][0] + b0, 0.f);
        const float f1 = fmaxf(acc[j][1] + b1, 0.f);
        const float f2 = fmaxf(acc[j][2] + b0, 0.f);
        const float f3 = fmaxf(acc[j][3] + b1, 0.f);
        const int t = j >> 1, o = (j & 1) * 2;
        const uint32_t h01 = pkhl(f0, f1), h23 = pkhl(f2, f3);
        fh[t][o] = h01; fh[t][o + 1] = h23;
        fl[t][o] = lo2(h01, f0, f1); fl[t][o + 1] = lo2(h23, f2, f3);
    }
}
__device__ __forceinline__ void zacc(float (&acc)[16][4]) {
    #pragma unroll
    for (int j = 0; j < 16; j++)
        #pragma unroll
        for (int c = 0; c < 4; c++) acc[j][c] = 0.f;
}

// ---------------- fused GNN layer ----------------
__global__ void __launch_bounds__(THREADS, 1) gnn_layer_mma(
    const int* __restrict__ ei,
    const float* __restrict__ be1, const float* __restrict__ be2,
    const float* __restrict__ bn1, const float* __restrict__ bn2,
    const float* __restrict__ eg,  const float* __restrict__ eb)
{
    extern __shared__ char smem[];
    const uint32_t sb = smem_u32(smem);
    const int tid = threadIdx.x, lane = tid & 31, warp = tid >> 5;
    const int R0 = warp * 16;
    const int e0 = blockIdx.x * TE;
    int* s_dst = (int*)(smem + SDST);
    int* s_src = (int*)(smem + SSRC);

    if (tid < TE)            s_src[tid]      = ei[e0 + tid];
    else                     s_dst[tid - TE] = ei[(size_t)N_EDGES + e0 + (tid - TE)];
    __syncthreads();

    float acc[16][4];
    uint32_t xih[8][4], xil[8][4];   // xi fragments, live GEMM1 -> GEMM3
    uint32_t enh[8][4], enl[8][4];   // e_new fragments, live E2 -> GEMM3
    uint32_t fh[8][4],  fl[8][4];    // hid / hid2 fragments

    // prologue: prefetch B stage0 (buf0) + stage1 (buf1)
    stageB2(sb, SB0H, SB0L, g_We1Th, g_We1Tl, 384, 0, tid);
    cpa_commit();
    stageB2(sb, SB1H, SB1L, g_We1Th, g_We1Tl, 384, 128, tid);
    cpa_commit();

    // ======== GEMM1: [xi | xj | e] @ We1 ========
    zacc(acc);
    stageA_rows(smem, g_h, s_dst, tid);                       // xi
    cpa_wait1();                                              // stage0 ready
    __syncthreads();
    pass3_keep(sb + STH, sb + STL, sb + SB0H, sb + SB0L, acc, lane, R0, xih, xil);
    __syncthreads();                                          // buf0 + A free
    stageB2(sb, SB0H, SB0L, g_We1Th, g_We1Tl, 384, 256, tid); // stage2 -> buf0
    cpa_commit();
    stageA_rows(smem, g_h, s_src, tid);                       // xj
    cpa_wait1();                                              // stage1 ready
    __syncthreads();
    pass3_smem(sb + STH, sb + STL, sb + SB1H, sb + SB1L, acc, lane, R0);
    __syncthreads();                                          // buf1 + A free
    stageB2(sb, SB1H, SB1L, g_We2Th, g_We2Tl, 128, 0, tid);   // stage3 -> buf1
    cpa_commit();
    stageA_lin(smem, g_e + (size_t)e0 * HDIM, tid);           // e
    cpa_wait1();                                              // stage2 ready
    __syncthreads();
    pass3_smem(sb + STH, sb + STL, sb + SB0H, sb + SB0L, acc, lane, R0);

    epi_relu_frag(acc, be1, fh, fl, lane);                    // hid

    // ======== GEMM2: hid @ We2 ========
    zacc(acc);
    __syncthreads();                                          // buf0 free
    stageB2(sb, SB0H, SB0L, g_Wn1Th, g_Wn1Tl, 256, 0, tid);   // stage4 -> buf0
    cpa_commit();
    cpa_wait1();                                              // stage3 ready
    __syncthreads();
    pass3_reg(fh, fl, sb + SB1H, sb + SB1L, acc, lane);

    // ======== E2: e_new fragments + edge LN ========
    {
        const int r0 = R0 + (lane >> 2);
        const int r1 = r0 + 8;
        float s0 = 0.f, q0 = 0.f, s1 = 0.f, q1 = 0.f;
        #pragma unroll
        for (int j = 0; j < 16; j++) {
            const int col = 8 * j + 2 * (lane & 3);
            const float b0 = be2[col], b1 = be2[col + 1];
            const float2 eA = *(const float2*)&g_e[(size_t)(e0 + r0) * HDIM + col];
            const float2 eB = *(const float2*)&g_e[(size_t)(e0 + r1) * HDIM + col];
            const float n0 = eA.x + acc[j][0] + b0;
            const float n1 = eA.y + acc[j][1] + b1;
            const float n2 = eB.x + acc[j][2] + b0;
            const float n3 = eB.y + acc[j][3] + b1;
            const int t = j >> 1, o = (j & 1) * 2;
            const uint32_t h01 = pkhl(n0, n1), h23 = pkhl(n2, n3);
            enh[t][o] = h01; enh[t][o + 1] = h23;
            enl[t][o] = lo2(h01, n0, n1); enl[t][o + 1] = lo2(h23, n2, n3);
            const float t0 = eA.x + n0, t1 = eA.y + n1;
            const float t2 = eB.x + n2, t3 = eB.y + n3;
            acc[j][0] = t0; acc[j][1] = t1; acc[j][2] = t2; acc[j][3] = t3;
            s0 += t0 + t1; q0 += t0 * t0 + t1 * t1;
            s1 += t2 + t3; q1 += t2 * t2 + t3 * t3;
        }
        s0 += __shfl_xor_sync(0xffffffffu, s0, 1); s0 += __shfl_xor_sync(0xffffffffu, s0, 2);
        q0 += __shfl_xor_sync(0xffffffffu, q0, 1); q0 += __shfl_xor_sync(0xffffffffu, q0, 2);
        s1 += __shfl_xor_sync(0xffffffffu, s1, 1); s1 += __shfl_xor_sync(0xffffffffu, s1, 2);
        q1 += __shfl_xor_sync(0xffffffffu, q1, 1); q1 += __shfl_xor_sync(0xffffffffu, q1, 2);
        const float m0 = s0 * (1.f / HDIM), m1 = s1 * (1.f / HDIM);
        const float r0std = rsqrtf(q0 * (1.f / HDIM) - m0 * m0 + LN_EPS);
        const float r1std = rsqrtf(q1 * (1.f / HDIM) - m1 * m1 + LN_EPS);
        #pragma unroll
        for (int j = 0; j < 16; j++) {
            const int col = 8 * j + 2 * (lane & 3);
            const float g0 = eg[col], g1 = eg[col + 1];
            const float bb0 = eb[col], bb1 = eb[col + 1];
            float2 oA, oB;
            oA.x = (acc[j][0] - m0) * r0std * g0 + bb0;
            oA.y = (acc[j][1] - m0) * r0std * g1 + bb1;
            oB.x = (acc[j][2] - m1) * r1std * g0 + bb0;
            oB.y = (acc[j][3] - m1) * r1std * g1 + bb1;
            *(float2*)&g_e[(size_t)(e0 + r0) * HDIM + col] = oA;
            *(float2*)&g_e[(size_t)(e0 + r1) * HDIM + col] = oB;
        }
    }

    // ======== GEMM3: [xi | e_new] @ Wn1 (both from registers) ========
    zacc(acc);
    __syncthreads();                                          // buf1 free
    stageB2(sb, SB1H, SB1L, g_Wn1Th, g_Wn1Tl, 256, 128, tid); // stage5 -> buf1
    cpa_commit();
    cpa_wait1();                                              // stage4 ready
    __syncthreads();
    pass3_reg(xih, xil, sb + SB0H, sb + SB0L, acc, lane);
    __syncthreads();                                          // buf0 free
    stageB2(sb, SB0H, SB0L, g_Wn2Th, g_Wn2Tl, 128, 0, tid);   // stage6 -> buf0
    cpa_commit();
    cpa_wait1();                                              // stage5 ready
    __syncthreads();
    pass3_reg(enh, enl, sb + SB1H, sb + SB1L, acc, lane);

    epi_relu_frag(acc, bn1, fh, fl, lane);                    // hid2

    // ======== GEMM4: hid2 @ Wn2 ========
    zacc(acc);
    cpa_wait0();                                              // stage6 ready
    __syncthreads();
    pass3_reg(fh, fl, sb + SB0H, sb + SB0L, acc, lane);

    // ======== E4: scatter msg-mlp (xi residual folded via deg) ========
    {
        const int r0 = R0 + (lane >> 2);
        const int r1 = r0 + 8;
        const int d0 = s_dst[r0], d1 = s_dst[r1];
        #pragma unroll
        for (int j = 0; j < 16; j++) {
            const int col = 8 * j + 2 * (lane & 3);
            const float b0 = bn2[col], b1 = bn2[col + 1];
            float* p0 = &g_hagg[(size_t)d0 * HDIM + col];
            float* p1 = &g_hagg[(size_t)d1 * HDIM + col];
            asm volatile("red.global.add.v2.f32 [%0], {%1,%2};"
                         :: "l"(p0), "f"(acc[j][0] + b0), "f"(acc[j][1] + b1) : "memory");
            asm volatile("red.global.add.v2.f32 [%0], {%1,%2};"
                         :: "l"(p1), "f"(acc[j][2] + b0), "f"(acc[j][3] + b1) : "memory");
        }
    }
}

// ---------------- prep kernels ----------------
__global__ void prep_w_kernel(const float* __restrict__ W, __nv_bfloat16* __restrict__ Wh,
                              __nv_bfloat16* __restrict__ Wl, int K)
{
    const int i = blockIdx.x * 256 + threadIdx.x;
    if (i < K * 128) {
        const int n = i & 127, k = i >> 7;
        const float v = W[(size_t)k * 128 + n];
        const __nv_bfloat16 h = __float2bfloat16(v);
        Wh[(size_t)n * K + k] = h;
        Wl[(size_t)n * K + k] = __float2bfloat16(v - __bfloat162float(h));
    }
}
__global__ void zero_deg_kernel() {
    const int i = blockIdx.x * 256 + threadIdx.x;
    if (i < N_NODES) g_degf[i] = 0.f;
}
__global__ void calc_deg_kernel(const int* __restrict__ ei) {
    const int i = blockIdx.x * 256 + threadIdx.x;
    if (i < N_EDGES) atomicAdd(&g_degf[ei[(size_t)N_EDGES + i]], 1.0f);
}

// ---------------- encoder (fp32 SIMT, exact) ----------------
template<int D>
__global__ void __launch_bounds__(128) encoder_kernel(
    const float* __restrict__ in, const float* __restrict__ noise,
    const float* __restrict__ w1, const float* __restrict__ b1,
    const float* __restrict__ w2, const float* __restrict__ b2,
    float* __restrict__ out)
{
    __shared__ float s_in [TR * D];
    __shared__ float s_hid[TR * HDIM];
    const int tid = threadIdx.x;
    const size_t row0 = (size_t)blockIdx.x * TR;

    for (int i = tid; i < TR * D; i += 128)
        s_in[i] = in[row0 * D + i] + noise[row0 * D + i];
    __syncthreads();

    float acc[TR];
    {
        const float bb = b1[tid];
        #pragma unroll
        for (int r = 0; r < TR; r++) acc[r] = bb;
    }
    #pragma unroll
    for (int k = 0; k < D; k++) {
        const float w = w1[k * HDIM + tid];
        #pragma unroll
        for (int r = 0; r < TR; r++) acc[r] += s_in[r * D + k] * w;
    }
    #pragma unroll
    for (int r = 0; r < TR; r++) s_hid[r * HDIM + tid] = fmaxf(acc[r], 0.f);
    __syncthreads();

    {
        const float bb = b2[tid];
        #pragma unroll
        for (int r = 0; r < TR; r++) acc[r] = bb;
    }
    for (int k = 0; k < HDIM; k++) {
        const float w = w2[k * HDIM + tid];
        #pragma unroll
        for (int r = 0; r < TR; r++) acc[r] += s_hid[r * HDIM + k] * w;
    }
    #pragma unroll
    for (int r = 0; r < TR; r++) out[(row0 + r) * HDIM + tid] = acc[r];
}

// ---------------- node update: g_h <- LN(h*(1+deg) + agg); g_hagg <- 0 ----------------
__global__ void __launch_bounds__(256) node_update_kernel(
    const float* __restrict__ xg, const float* __restrict__ xb)
{
    const int warp = threadIdx.x >> 5, lane = threadIdx.x & 31;
    const int n = blockIdx.x * 8 + warp;
    if (n >= N_NODES) return;
    const size_t base = (size_t)n * HDIM + lane * 4;
    const float dg1 = 1.f + g_degf[n];

    const float4 hv = *(const float4*)&g_h[base];
    const float4 av = *(const float4*)&g_hagg[base];
    float v[4] = { hv.x * dg1 + av.x, hv.y * dg1 + av.y,
                   hv.z * dg1 + av.z, hv.w * dg1 + av.w };
    float s = 0.f, q = 0.f;
    #pragma unroll
    for (int j = 0; j < 4; j++) { s += v[j]; q += v[j] * v[j]; }
    #pragma unroll
    for (int o = 16; o > 0; o >>= 1) {
        s += __shfl_xor_sync(0xffffffffu, s, o);
        q += __shfl_xor_sync(0xffffffffu, q, o);
    }
    const float mean = s * (1.f / HDIM);
    const float var  = q * (1.f / HDIM) - mean * mean;
    const float rstd = rsqrtf(var + LN_EPS);

    float4 o4;
    o4.x = (v[0] - mean) * rstd * xg[lane * 4 + 0] + xb[lane * 4 + 0];
    o4.y = (v[1] - mean) * rstd * xg[lane * 4 + 1] + xb[lane * 4 + 1];
    o4.z = (v[2] - mean) * rstd * xg[lane * 4 + 2] + xb[lane * 4 + 2];
    o4.w = (v[3] - mean) * rstd * xg[lane * 4 + 3] + xb[lane * 4 + 3];
    *(float4*)&g_h[base]    = o4;
    *(float4*)&g_hagg[base] = make_float4(0.f, 0.f, 0.f, 0.f);
}

// ---------------- decoder ----------------
__global__ void __launch_bounds__(256) decoder_kernel(
    const float* __restrict__ w1, const float* __restrict__ b1,
    const float* __restrict__ w2, const float* __restrict__ b2,
    const float* __restrict__ noise, float* __restrict__ out)
{
    const int warp = threadIdx.x >> 5, lane = threadIdx.x & 31;
    const int n = blockIdx.x * 8 + warp;
    if (n >= N_NODES) return;
    const float* hrow = &g_h[(size_t)n * HDIM];

    float acc[4];
    #pragma unroll
    for (int j = 0; j < 4; j++) acc[j] = b1[lane * 4 + j];
    for (int k = 0; k < HDIM; k++) {
        const float hk = __ldg(&hrow[k]);
        const float4 w = *(const float4*)&w1[k * HDIM + lane * 4];
        acc[0] += hk * w.x; acc[1] += hk * w.y; acc[2] += hk * w.z; acc[3] += hk * w.w;
    }
    float o0 = 0.f, o1 = 0.f;
    #pragma unroll
    for (int j = 0; j < 4; j++) {
        const float hid = fmaxf(acc[j], 0.f);
        const int c = lane * 4 + j;
        o0 += hid * w2[c * 2 + 0];
        o1 += hid * w2[c * 2 + 1];
    }
    #pragma unroll
    for (int o = 16; o > 0; o >>= 1) {
        o0 += __shfl_xor_sync(0xffffffffu, o0, o);
        o1 += __shfl_xor_sync(0xffffffffu, o1, o);
    }
    if (lane == 0) {
        out[n * 2 + 0] = o0 + b2[0] - noise[n * 16 + 0];
        out[n * 2 + 1] = o1 + b2[1] - noise[n * 16 + 1];
    }
}

// ---------------- launch ----------------
extern "C" void kernel_launch(void* const* d_in, const int* in_sizes, int n_in,
                              void* d_out, int out_size)
{
    const float* x          = (const float*)d_in[0];
    const float* edge_attr  = (const float*)d_in[1];
    const int*   ei         = (const int*)d_in[2];
    const float* node_noise = (const float*)d_in[3];
    const float* edge_noise = (const float*)d_in[4];
    const float* nw1 = (const float*)d_in[5];  const float* nb1 = (const float*)d_in[6];
    const float* nw2 = (const float*)d_in[7];  const float* nb2 = (const float*)d_in[8];
    const float* ew1 = (const float*)d_in[9];  const float* eb1 = (const float*)d_in[10];
    const float* ew2 = (const float*)d_in[11]; const float* eb2 = (const float*)d_in[12];
    const float* gew1 = (const float*)d_in[13]; const float* geb1 = (const float*)d_in[14];
    const float* gew2 = (const float*)d_in[15]; const float* geb2 = (const float*)d_in[16];
    const float* gnw1 = (const float*)d_in[17]; const float* gnb1 = (const float*)d_in[18];
    const float* gnw2 = (const float*)d_in[19]; const float* gnb2 = (const float*)d_in[20];
    const float* xlg = (const float*)d_in[21]; const float* xlb = (const float*)d_in[22];
    const float* elg = (const float*)d_in[23]; const float* elb = (const float*)d_in[24];
    const float* dw1 = (const float*)d_in[25]; const float* db1 = (const float*)d_in[26];
    const float* dw2 = (const float*)d_in[27]; const float* db2 = (const float*)d_in[28];
    float* out = (float*)d_out;

    float *ph = nullptr, *pe = nullptr;
    cudaGetSymbolAddress((void**)&ph, g_h);
    cudaGetSymbolAddress((void**)&pe, g_e);
    __nv_bfloat16 *w1h, *w1l, *w2h, *w2l, *w3h, *w3l, *w4h, *w4l;
    cudaGetSymbolAddress((void**)&w1h, g_We1Th); cudaGetSymbolAddress((void**)&w1l, g_We1Tl);
    cudaGetSymbolAddress((void**)&w2h, g_We2Th); cudaGetSymbolAddress((void**)&w2l, g_We2Tl);
    cudaGetSymbolAddress((void**)&w3h, g_Wn1Th); cudaGetSymbolAddress((void**)&w3l, g_Wn1Tl);
    cudaGetSymbolAddress((void**)&w4h, g_Wn2Th); cudaGetSymbolAddress((void**)&w4l, g_Wn2Tl);

    cudaFuncSetAttribute(gnn_layer_mma,
                         cudaFuncAttributeMaxDynamicSharedMemorySize, GNN_SMEM);

    zero_deg_kernel<<<(N_NODES + 255) / 256, 256>>>();
    calc_deg_kernel<<<(N_EDGES + 255) / 256, 256>>>(ei);
    prep_w_kernel<<<(384 * 128 + 255) / 256, 256>>>(gew1, w1h, w1l, 384);
    prep_w_kernel<<<(128 * 128 + 255) / 256, 256>>>(gew2, w2h, w2l, 128);
    prep_w_kernel<<<(256 * 128 + 255) / 256, 256>>>(gnw1, w3h, w3l, 256);
    prep_w_kernel<<<(128 * 128 + 255) / 256, 256>>>(gnw2, w4h, w4l, 128);

    encoder_kernel<16><<<N_NODES / TR, 128>>>(x, node_noise, nw1, nb1, nw2, nb2, ph);
    encoder_kernel<8><<<N_EDGES / TR, 128>>>(edge_attr, edge_noise, ew1, eb1, ew2, eb2, pe);

    for (int l = 0; l < NLAYERS; l++) {
        gnn_layer_mma<<<N_EDGES / TE, THREADS, GNN_SMEM>>>(
            ei, geb1, geb2, gnb1, gnb2,
            elg + (size_t)l * HDIM, elb + (size_t)l * HDIM);
        node_update_kernel<<<(N_NODES + 7) / 8, 256>>>(
            xlg + (size_t)l * HDIM, xlb + (size_t)l * HDIM);
    }

    decoder_kernel<<<(N_NODES + 7) / 8, 256>>>(dw1, db1, dw2, db2, node_noise, out);
}

// round 14
// speedup vs baseline: 10.6564x; 1.4630x over previous
/*
 * LearnedSimModel fused GNN - round 14: node-side precompute factorization.
 * P1=h@We1_xi+be1, P2=h@We1_xj, P3=h@Wn1_xi+bn1 computed per NODE (32x less
 * work than per-edge); per-edge passes drop 7->4. Edge encoder moved onto the
 * same bf16 3-term mma machinery. Same split math -> rel_err ~1e-5.
 */
#include <cuda_runtime.h>
#include <cuda_bf16.h>
#include <cstdint>

#define N_NODES 20000
#define N_EDGES 640000
#define HDIM    128
#define NLAYERS 10
#define LN_EPS  1e-5f
#define TR      32
#define TE      128
#define THREADS 256

// dynamic smem byte offsets
#define STH   0
#define STL   32768
#define SB0H  65536
#define SB0L  98304
#define SB1H  131072
#define SB1L  163840
#define SDST  196608
#define SSRC  197120
#define GNN_SMEM 197632
#define SW1   197632
#define SEB1  201728
#define ENC_SMEM 202240

__device__ float g_h   [(size_t)N_NODES * HDIM];
__device__ float g_hagg[(size_t)N_NODES * HDIM];
__device__ float g_e   [(size_t)N_EDGES * HDIM];
__device__ float g_P1  [(size_t)N_NODES * HDIM];
__device__ float g_P2  [(size_t)N_NODES * HDIM];
__device__ float g_P3  [(size_t)N_NODES * HDIM];
__device__ float g_degf[N_NODES];
__device__ __nv_bfloat16 g_We1Th[128 * 384], g_We1Tl[128 * 384];
__device__ __nv_bfloat16 g_We2Th[128 * 128], g_We2Tl[128 * 128];
__device__ __nv_bfloat16 g_Wn1Th[128 * 256], g_Wn1Tl[128 * 256];
__device__ __nv_bfloat16 g_Wn2Th[128 * 128], g_Wn2Tl[128 * 128];
__device__ __nv_bfloat16 g_Ee2Th[128 * 128], g_Ee2Tl[128 * 128];

// ---------------- helpers ----------------
__device__ __forceinline__ uint32_t smem_u32(const void* p) {
    uint32_t a;
    asm("{ .reg .u64 t; cvta.to.shared.u64 t, %1; cvt.u32.u64 %0, t; }" : "=r"(a) : "l"(p));
    return a;
}
__device__ __forceinline__ uint32_t pkhl(float a, float b) {
    uint32_t r; asm("cvt.rn.bf16x2.f32 %0,%1,%2;" : "=r"(r) : "f"(b), "f"(a)); return r;
}
__device__ __forceinline__ uint32_t lo2(uint32_t h, float a, float b) {
    const float ha = __uint_as_float(h << 16);
    const float hb = __uint_as_float(h & 0xFFFF0000u);
    return pkhl(a - ha, b - hb);
}
__device__ __forceinline__ uint32_t aoff(int r, int g) {
    return (uint32_t)(r * 256 + (((g & 8) | ((g ^ r) & 7)) << 4));
}
__device__ __forceinline__ void ldsm4(uint32_t a, uint32_t& r0, uint32_t& r1,
                                      uint32_t& r2, uint32_t& r3) {
    asm volatile("ldmatrix.sync.aligned.m8n8.x4.shared.b16 {%0,%1,%2,%3},[%4];"
                 : "=r"(r0), "=r"(r1), "=r"(r2), "=r"(r3) : "r"(a));
}
__device__ __forceinline__ void mma16816(float* c, uint32_t a0, uint32_t a1, uint32_t a2,
                                         uint32_t a3, uint32_t b0, uint32_t b1) {
    asm volatile(
        "mma.sync.aligned.m16n8k16.row.col.f32.bf16.bf16.f32 "
        "{%0,%1,%2,%3},{%4,%5,%6,%7},{%8,%9},{%0,%1,%2,%3};"
        : "+f"(c[0]), "+f"(c[1]), "+f"(c[2]), "+f"(c[3])
        : "r"(a0), "r"(a1), "r"(a2), "r"(a3), "r"(b0), "r"(b1));
}
__device__ __forceinline__ void cpa16(uint32_t dst, const void* src) {
    asm volatile("cp.async.cg.shared.global [%0], [%1], 16;" :: "r"(dst), "l"(src) : "memory");
}
__device__ __forceinline__ void cpa_commit() { asm volatile("cp.async.commit_group;" ::: "memory"); }
__device__ __forceinline__ void cpa_wait1()  { asm volatile("cp.async.wait_group 1;" ::: "memory"); }
__device__ __forceinline__ void cpa_wait0()  { asm volatile("cp.async.wait_group 0;" ::: "memory"); }

// ---------------- fused 3-term GEMM passes ----------------
#define PASS_J_BODY(A0,A1,A2,A3, L0,L1,L2,L3)                                   \
    _Pragma("unroll")                                                            \
    for (int j = 0; j < 8; j++) {                                                \
        uint32_t b0,b1,b2,b3,c0,c1,c2,c3;                                        \
        const uint32_t bo = aoff(16 * j + bn, bg);                               \
        ldsm4(sBh + bo, b0, b1, b2, b3);                                         \
        ldsm4(sBl + bo, c0, c1, c2, c3);                                         \
        mma16816(acc[2*j],   A0,A1,A2,A3, b0, b1);                               \
        mma16816(acc[2*j+1], A0,A1,A2,A3, b2, b3);                               \
        mma16816(acc[2*j],   L0,L1,L2,L3, b0, b1);                               \
        mma16816(acc[2*j+1], L0,L1,L2,L3, b2, b3);                               \
        mma16816(acc[2*j],   A0,A1,A2,A3, c0, c1);                               \
        mma16816(acc[2*j+1], A0,A1,A2,A3, c2, c3);                               \
    }

__device__ __forceinline__ void pass3_smem(uint32_t sAh, uint32_t sAl,
                                           uint32_t sBh, uint32_t sBl,
                                           float (&acc)[16][4], int lane, int R0)
{
    const int bn = 8 * (lane >> 4) + (lane & 7);
    #pragma unroll 1
    for (int t = 0; t < 8; t++) {
        const uint32_t ar = aoff(R0 + (lane & 15), 2 * t + (lane >> 4));
        uint32_t h0, h1, h2, h3, l0, l1, l2, l3;
        ldsm4(sAh + ar, h0, h1, h2, h3);
        ldsm4(sAl + ar, l0, l1, l2, l3);
        const int bg = 2 * t + ((lane >> 3) & 1);
        PASS_J_BODY(h0, h1, h2, h3, l0, l1, l2, l3)
    }
}
__device__ __forceinline__ void pass3_reg(const uint32_t (&fh)[8][4], const uint32_t (&fl)[8][4],
                                          uint32_t sBh, uint32_t sBl,
                                          float (&acc)[16][4], int lane)
{
    const int bn = 8 * (lane >> 4) + (lane & 7);
    #pragma unroll 1
    for (int t = 0; t < 8; t++) {
        const int bg = 2 * t + ((lane >> 3) & 1);
        PASS_J_BODY(fh[t][0], fh[t][1], fh[t][2], fh[t][3],
                    fl[t][0], fl[t][1], fl[t][2], fl[t][3])
    }
}

// ---------------- staging ----------------
__device__ __forceinline__ void stageB2(uint32_t sb, uint32_t bH, uint32_t bL,
                                        const __nv_bfloat16* __restrict__ Wh,
                                        const __nv_bfloat16* __restrict__ Wl,
                                        int ktot, int k0, int tid)
{
    #pragma unroll 4
    for (int i = tid; i < 2048; i += THREADS) {
        const int n = i >> 4, g = i & 15;
        const uint32_t o = aoff(n, g);
        const size_t gsrc = (size_t)n * ktot + k0 + g * 8;
        cpa16(sb + bH + o, Wh + gsrc);
        cpa16(sb + bL + o, Wl + gsrc);
    }
}
__device__ __forceinline__ void stageA_split(char* smem, const float* __restrict__ rowptr,
                                             int r, int g)
{
    const float4* p = (const float4*)(rowptr + g * 8);
    const float4 u = p[0], v = p[1];
    const uint32_t h0 = pkhl(u.x, u.y), h1 = pkhl(u.z, u.w);
    const uint32_t h2 = pkhl(v.x, v.y), h3 = pkhl(v.z, v.w);
    uint4 H; H.x = h0; H.y = h1; H.z = h2; H.w = h3;
    uint4 L; L.x = lo2(h0, u.x, u.y); L.y = lo2(h1, u.z, u.w);
             L.z = lo2(h2, v.x, v.y); L.w = lo2(h3, v.z, v.w);
    const uint32_t off = aoff(r, g);
    *(uint4*)(smem + STH + off) = H;
    *(uint4*)(smem + STL + off) = L;
}
__device__ __forceinline__ void stageA_lin(char* smem, const float* __restrict__ base, int tid)
{
    #pragma unroll 2
    for (int i = tid; i < 2048; i += THREADS) {
        const int r = i >> 4, g = i & 15;
        stageA_split(smem, base + (size_t)r * HDIM, r, g);
    }
}
__device__ __forceinline__ void stageA_nodes(char* smem, const float* __restrict__ src,
                                             int row0, int tid)
{
    #pragma unroll 2
    for (int i = tid; i < 2048; i += THREADS) {
        const int r = i >> 4, g = i & 15;
        int rr = row0 + r; if (rr >= N_NODES) rr = N_NODES - 1;
        stageA_split(smem, src + (size_t)rr * HDIM, r, g);
    }
}
__device__ __forceinline__ void zacc(float (&acc)[16][4]) {
    #pragma unroll
    for (int j = 0; j < 16; j++)
        #pragma unroll
        for (int c = 0; c < 4; c++) acc[j][c] = 0.f;
}

// ---------------- node precompute: P = h @ Wblk (+bias), per node ----------------
__device__ __forceinline__ void epi_writeP(float (&acc)[16][4], float* __restrict__ P,
                                           const float* __restrict__ bias,
                                           int row0, int lane, int R0)
{
    const int r0 = R0 + (lane >> 2), r1 = r0 + 8;
    const int n0 = row0 + r0, n1 = row0 + r1;
    #pragma unroll
    for (int j = 0; j < 16; j++) {
        const int col = 8 * j + 2 * (lane & 3);
        const float b0 = bias ? bias[col] : 0.f;
        const float b1 = bias ? bias[col + 1] : 0.f;
        if (n0 < N_NODES)
            *(float2*)&P[(size_t)n0 * HDIM + col] = make_float2(acc[j][0] + b0, acc[j][1] + b1);
        if (n1 < N_NODES)
            *(float2*)&P[(size_t)n1 * HDIM + col] = make_float2(acc[j][2] + b0, acc[j][3] + b1);
    }
}

__global__ void __launch_bounds__(THREADS, 1) node_pre_mma(
    const float* __restrict__ be1, const float* __restrict__ bn1)
{
    extern __shared__ char smem[];
    const uint32_t sb = smem_u32(smem);
    const int tid = threadIdx.x, lane = tid & 31, warp = tid >> 5;
    const int R0 = warp * 16;
    const int row0 = blockIdx.x * TE;
    float acc[16][4];

    stageB2(sb, SB0H, SB0L, g_We1Th, g_We1Tl, 384, 0, tid);   cpa_commit();
    stageB2(sb, SB1H, SB1L, g_We1Th, g_We1Tl, 384, 128, tid); cpa_commit();
    stageA_nodes(smem, g_h, row0, tid);

    zacc(acc);
    cpa_wait1(); __syncthreads();
    pass3_smem(sb + STH, sb + STL, sb + SB0H, sb + SB0L, acc, lane, R0);
    epi_writeP(acc, g_P1, be1, row0, lane, R0);
    __syncthreads();
    stageB2(sb, SB0H, SB0L, g_Wn1Th, g_Wn1Tl, 256, 0, tid);   cpa_commit();

    zacc(acc);
    cpa_wait1(); __syncthreads();
    pass3_smem(sb + STH, sb + STL, sb + SB1H, sb + SB1L, acc, lane, R0);
    epi_writeP(acc, g_P2, nullptr, row0, lane, R0);

    zacc(acc);
    cpa_wait0(); __syncthreads();
    pass3_smem(sb + STH, sb + STL, sb + SB0H, sb + SB0L, acc, lane, R0);
    epi_writeP(acc, g_P3, bn1, row0, lane, R0);
}

// ---------------- fused GNN layer (4 passes) ----------------
__global__ void __launch_bounds__(THREADS, 1) gnn_layer_mma(
    const int* __restrict__ ei,
    const float* __restrict__ be2, const float* __restrict__ bn2,
    const float* __restrict__ eg,  const float* __restrict__ eb)
{
    extern __shared__ char smem[];
    const uint32_t sb = smem_u32(smem);
    const int tid = threadIdx.x, lane = tid & 31, warp = tid >> 5;
    const int R0 = warp * 16;
    const int e0 = blockIdx.x * TE;
    int* s_dst = (int*)(smem + SDST);
    int* s_src = (int*)(smem + SSRC);

    if (tid < TE) s_src[tid]      = ei[e0 + tid];
    else          s_dst[tid - TE] = ei[(size_t)N_EDGES + e0 + (tid - TE)];

    float acc[16][4];
    uint32_t enh[8][4], enl[8][4];
    uint32_t fh[8][4],  fl[8][4];

    stageB2(sb, SB0H, SB0L, g_We1Th, g_We1Tl, 384, 256, tid); cpa_commit();   // We1_e
    stageB2(sb, SB1H, SB1L, g_We2Th, g_We2Tl, 128, 0, tid);   cpa_commit();   // We2
    stageA_lin(smem, g_e + (size_t)e0 * HDIM, tid);

    // ======== GEMM_e: e @ We1_e ========
    zacc(acc);
    cpa_wait1(); __syncthreads();
    pass3_smem(sb + STH, sb + STL, sb + SB0H, sb + SB0L, acc, lane, R0);

    // E1: + P1[dst] + P2[src] (be1 folded into P1), relu -> fragments
    {
        const int r0 = R0 + (lane >> 2), r1 = r0 + 8;
        const int d0 = s_dst[r0], d1 = s_dst[r1];
        const int u0 = s_src[r0], u1 = s_src[r1];
        #pragma unroll
        for (int j = 0; j < 16; j++) {
            const int col = 8 * j + 2 * (lane & 3);
            const float2 p1A = *(const float2*)&g_P1[(size_t)d0 * HDIM + col];
            const float2 p1B = *(const float2*)&g_P1[(size_t)d1 * HDIM + col];
            const float2 p2A = *(const float2*)&g_P2[(size_t)u0 * HDIM + col];
            const float2 p2B = *(const float2*)&g_P2[(size_t)u1 * HDIM + col];
            const float f0 = fmaxf(acc[j][0] + p1A.x + p2A.x, 0.f);
            const float f1 = fmaxf(acc[j][1] + p1A.y + p2A.y, 0.f);
            const float f2 = fmaxf(acc[j][2] + p1B.x + p2B.x, 0.f);
            const float f3 = fmaxf(acc[j][3] + p1B.y + p2B.y, 0.f);
            const int t = j >> 1, o = (j & 1) * 2;
            const uint32_t h01 = pkhl(f0, f1), h23 = pkhl(f2, f3);
            fh[t][o] = h01; fh[t][o + 1] = h23;
            fl[t][o] = lo2(h01, f0, f1); fl[t][o + 1] = lo2(h23, f2, f3);
        }
    }
    __syncthreads();                                          // buf0 free
    stageB2(sb, SB0H, SB0L, g_Wn1Th, g_Wn1Tl, 256, 128, tid); cpa_commit();   // Wn1_en

    // ======== GEMM2: hid @ We2 ========
    zacc(acc);
    cpa_wait1(); __syncthreads();
    pass3_reg(fh, fl, sb + SB1H, sb + SB1L, acc, lane);

    // E2: e_new fragments + edge LN
    {
        const int r0 = R0 + (lane >> 2), r1 = r0 + 8;
        float s0 = 0.f, q0 = 0.f, s1 = 0.f, q1 = 0.f;
        #pragma unroll
        for (int j = 0; j < 16; j++) {
            const int col = 8 * j + 2 * (lane & 3);
            const float b0 = be2[col], b1 = be2[col + 1];
            const float2 eA = *(const float2*)&g_e[(size_t)(e0 + r0) * HDIM + col];
            const float2 eB = *(const float2*)&g_e[(size_t)(e0 + r1) * HDIM + col];
            const float n0 = eA.x + acc[j][0] + b0;
            const float n1 = eA.y + acc[j][1] + b1;
            const float n2 = eB.x + acc[j][2] + b0;
            const float n3 = eB.y + acc[j][3] + b1;
            const int t = j >> 1, o = (j & 1) * 2;
            const uint32_t h01 = pkhl(n0, n1), h23 = pkhl(n2, n3);
            enh[t][o] = h01; enh[t][o + 1] = h23;
            enl[t][o] = lo2(h01, n0, n1); enl[t][o + 1] = lo2(h23, n2, n3);
            const float t0 = eA.x + n0, t1 = eA.y + n1;
            const float t2 = eB.x + n2, t3 = eB.y + n3;
            acc[j][0] = t0; acc[j][1] = t1; acc[j][2] = t2; acc[j][3] = t3;
            s0 += t0 + t1; q0 += t0 * t0 + t1 * t1;
            s1 += t2 + t3; q1 += t2 * t2 + t3 * t3;
        }
        s0 += __shfl_xor_sync(0xffffffffu, s0, 1); s0 += __shfl_xor_sync(0xffffffffu, s0, 2);
        q0 += __shfl_xor_sync(0xffffffffu, q0, 1); q0 += __shfl_xor_sync(0xffffffffu, q0, 2);
        s1 += __shfl_xor_sync(0xffffffffu, s1, 1); s1 += __shfl_xor_sync(0xffffffffu, s1, 2);
        q1 += __shfl_xor_sync(0xffffffffu, q1, 1); q1 += __shfl_xor_sync(0xffffffffu, q1, 2);
        const float m0 = s0 * (1.f / HDIM), m1 = s1 * (1.f / HDIM);
        const float r0std = rsqrtf(q0 * (1.f / HDIM) - m0 * m0 + LN_EPS);
        const float r1std = rsqrtf(q1 * (1.f / HDIM) - m1 * m1 + LN_EPS);
        #pragma unroll
        for (int j = 0; j < 16; j++) {
            const int col = 8 * j + 2 * (lane & 3);
            float2 oA, oB;
            oA.x = (acc[j][0] - m0) * r0std * eg[col] + eb[col];
            oA.y = (acc[j][1] - m0) * r0std * eg[col + 1] + eb[col + 1];
            oB.x = (acc[j][2] - m1) * r1std * eg[col] + eb[col];
            oB.y = (acc[j][3] - m1) * r1std * eg[col + 1] + eb[col + 1];
            *(float2*)&g_e[(size_t)(e0 + r0) * HDIM + col] = oA;
            *(float2*)&g_e[(size_t)(e0 + r1) * HDIM + col] = oB;
        }
    }
    __syncthreads();                                          // buf1 free
    stageB2(sb, SB1H, SB1L, g_Wn2Th, g_Wn2Tl, 128, 0, tid);   cpa_commit();   // Wn2

    // ======== GEMM3: e_new @ Wn1_en ========
    zacc(acc);
    cpa_wait1(); __syncthreads();
    pass3_reg(enh, enl, sb + SB0H, sb + SB0L, acc, lane);

    // E3: + P3[dst] (bn1 folded), relu -> fragments
    {
        const int r0 = R0 + (lane >> 2), r1 = r0 + 8;
        const int d0 = s_dst[r0], d1 = s_dst[r1];
        #pragma unroll
        for (int j = 0; j < 16; j++) {
            const int col = 8 * j + 2 * (lane & 3);
            const float2 pA = *(const float2*)&g_P3[(size_t)d0 * HDIM + col];
            const float2 pB = *(const float2*)&g_P3[(size_t)d1 * HDIM + col];
            const float f0 = fmaxf(acc[j][0] + pA.x, 0.f);
            const float f1 = fmaxf(acc[j][1] + pA.y, 0.f);
            const float f2 = fmaxf(acc[j][2] + pB.x, 0.f);
            const float f3 = fmaxf(acc[j][3] + pB.y, 0.f);
            const int t = j >> 1, o = (j & 1) * 2;
            const uint32_t h01 = pkhl(f0, f1), h23 = pkhl(f2, f3);
            fh[t][o] = h01; fh[t][o + 1] = h23;
            fl[t][o] = lo2(h01, f0, f1); fl[t][o + 1] = lo2(h23, f2, f3);
        }
    }

    // ======== GEMM4: hid2 @ Wn2 ========
    zacc(acc);
    cpa_wait0(); __syncthreads();
    pass3_reg(fh, fl, sb + SB1H, sb + SB1L, acc, lane);

    // E4: scatter (xi residual folded via deg)
    {
        const int r0 = R0 + (lane >> 2), r1 = r0 + 8;
        const int d0 = s_dst[r0], d1 = s_dst[r1];
        #pragma unroll
        for (int j = 0; j < 16; j++) {
            const int col = 8 * j + 2 * (lane & 3);
            const float b0 = bn2[col], b1 = bn2[col + 1];
            float* p0 = &g_hagg[(size_t)d0 * HDIM + col];
            float* p1 = &g_hagg[(size_t)d1 * HDIM + col];
            asm volatile("red.global.add.v2.f32 [%0], {%1,%2};"
                         :: "l"(p0), "f"(acc[j][0] + b0), "f"(acc[j][1] + b1) : "memory");
            asm volatile("red.global.add.v2.f32 [%0], {%1,%2};"
                         :: "l"(p1), "f"(acc[j][2] + b0), "f"(acc[j][3] + b1) : "memory");
        }
    }
}

// ---------------- edge encoder (mma): g_e = relu((ea+noise)@W1+b1)@W2+b2 ----------------
__global__ void __launch_bounds__(THREADS, 1) edge_enc_mma(
    const float* __restrict__ ea, const float* __restrict__ noise,
    const float* __restrict__ w1, const float* __restrict__ b1,
    const float* __restrict__ b2)
{
    extern __shared__ char smem[];
    const uint32_t sb = smem_u32(smem);
    const int tid = threadIdx.x, lane = tid & 31, warp = tid >> 5;
    const int R0 = warp * 16;
    const int e0 = blockIdx.x * TE;
    float* sw1 = (float*)(smem + SW1);
    float* sb1 = (float*)(smem + SEB1);

    stageB2(sb, SB0H, SB0L, g_Ee2Th, g_Ee2Tl, 128, 0, tid); cpa_commit();

    for (int i = tid; i < 1024; i += THREADS) sw1[i] = w1[i];
    if (tid < 128) sb1[tid] = b1[tid];
    __syncthreads();

    // layer 1 (K=8, fp32 exact) -> hid hi/lo tiles
    {
        const int row = tid & 127, half = tid >> 7;
        const size_t grow = (size_t)(e0 + row) * 8;
        float in8[8];
        #pragma unroll
        for (int k = 0; k < 8; k++) in8[k] = ea[grow + k] + noise[grow + k];
        #pragma unroll 1
        for (int gg = 0; gg < 8; gg++) {
            const int g = half * 8 + gg;
            uint32_t H[4], L[4];
            #pragma unroll
            for (int p = 0; p < 4; p++) {
                const int col = g * 8 + p * 2;
                float v0 = sb1[col], v1 = sb1[col + 1];
                #pragma unroll
                for (int k = 0; k < 8; k++) {
                    v0 += in8[k] * sw1[k * 128 + col];
                    v1 += in8[k] * sw1[k * 128 + col + 1];
                }
                v0 = fmaxf(v0, 0.f); v1 = fmaxf(v1, 0.f);
                H[p] = pkhl(v0, v1); L[p] = lo2(H[p], v0, v1);
            }
            *(uint4*)(smem + STH + aoff(row, g)) = make_uint4(H[0], H[1], H[2], H[3]);
            *(uint4*)(smem + STL + aoff(row, g)) = make_uint4(L[0], L[1], L[2], L[3]);
        }
    }
    float acc[16][4];
    zacc(acc);
    cpa_wait0(); __syncthreads();
    pass3_smem(sb + STH, sb + STL, sb + SB0H, sb + SB0L, acc, lane, R0);

    {
        const int r0 = R0 + (lane >> 2), r1 = r0 + 8;
        #pragma unroll
        for (int j = 0; j < 16; j++) {
            const int col = 8 * j + 2 * (lane & 3);
            const float b0 = b2[col], b1v = b2[col + 1];
            *(float2*)&g_e[(size_t)(e0 + r0) * HDIM + col] =
                make_float2(acc[j][0] + b0, acc[j][1] + b1v);
            *(float2*)&g_e[(size_t)(e0 + r1) * HDIM + col] =
                make_float2(acc[j][2] + b0, acc[j][3] + b1v);
        }
    }
}

// ---------------- prep kernels ----------------
__global__ void prep_w_kernel(const float* __restrict__ W, __nv_bfloat16* __restrict__ Wh,
                              __nv_bfloat16* __restrict__ Wl, int K)
{
    const int i = blockIdx.x * 256 + threadIdx.x;
    if (i < K * 128) {
        const int n = i & 127, k = i >> 7;
        const float v = W[(size_t)k * 128 + n];
        const __nv_bfloat16 h = __float2bfloat16(v);
        Wh[(size_t)n * K + k] = h;
        Wl[(size_t)n * K + k] = __float2bfloat16(v - __bfloat162float(h));
    }
}
__global__ void zero_deg_kernel() {
    const int i = blockIdx.x * 256 + threadIdx.x;
    if (i < N_NODES) g_degf[i] = 0.f;
}
__global__ void calc_deg_kernel(const int* __restrict__ ei) {
    const int i = blockIdx.x * 256 + threadIdx.x;
    if (i < N_EDGES) atomicAdd(&g_degf[ei[(size_t)N_EDGES + i]], 1.0f);
}

// ---------------- node encoder (fp32 SIMT, tiny) ----------------
__global__ void __launch_bounds__(128) node_enc_kernel(
    const float* __restrict__ in, const float* __restrict__ noise,
    const float* __restrict__ w1, const float* __restrict__ b1,
    const float* __restrict__ w2, const float* __restrict__ b2,
    float* __restrict__ out)
{
    __shared__ float s_in [TR * 16];
    __shared__ float s_hid[TR * HDIM];
    const int tid = threadIdx.x;
    const size_t row0 = (size_t)blockIdx.x * TR;

    for (int i = tid; i < TR * 16; i += 128)
        s_in[i] = in[row0 * 16 + i] + noise[row0 * 16 + i];
    __syncthreads();

    float acc[TR];
    {
        const float bb = b1[tid];
        #pragma unroll
        for (int r = 0; r < TR; r++) acc[r] = bb;
    }
    #pragma unroll
    for (int k = 0; k < 16; k++) {
        const float w = w1[k * HDIM + tid];
        #pragma unroll
        for (int r = 0; r < TR; r++) acc[r] += s_in[r * 16 + k] * w;
    }
    #pragma unroll
    for (int r = 0; r < TR; r++) s_hid[r * HDIM + tid] = fmaxf(acc[r], 0.f);
    __syncthreads();

    {
        const float bb = b2[tid];
        #pragma unroll
        for (int r = 0; r < TR; r++) acc[r] = bb;
    }
    for (int k = 0; k < HDIM; k++) {
        const float w = w2[k * HDIM + tid];
        #pragma unroll
        for (int r = 0; r < TR; r++) acc[r] += s_hid[r * HDIM + k] * w;
    }
    #pragma unroll
    for (int r = 0; r < TR; r++) out[(row0 + r) * HDIM + tid] = acc[r];
}

// ---------------- node update: g_h <- LN(h*(1+deg) + agg); g_hagg <- 0 ----------------
__global__ void __launch_bounds__(256) node_update_kernel(
    const float* __restrict__ xg, const float* __restrict__ xb)
{
    const int warp = threadIdx.x >> 5, lane = threadIdx.x & 31;
    const int n = blockIdx.x * 8 + warp;
    if (n >= N_NODES) return;
    const size_t base = (size_t)n * HDIM + lane * 4;
    const float dg1 = 1.f + g_degf[n];

    const float4 hv = *(const float4*)&g_h[base];
    const float4 av = *(const float4*)&g_hagg[base];
    float v[4] = { hv.x * dg1 + av.x, hv.y * dg1 + av.y,
                   hv.z * dg1 + av.z, hv.w * dg1 + av.w };
    float s = 0.f, q = 0.f;
    #pragma unroll
    for (int j = 0; j < 4; j++) { s += v[j]; q += v[j] * v[j]; }
    #pragma unroll
    for (int o = 16; o > 0; o >>= 1) {
        s += __shfl_xor_sync(0xffffffffu, s, o);
        q += __shfl_xor_sync(0xffffffffu, q, o);
    }
    const float mean = s * (1.f / HDIM);
    const float var  = q * (1.f / HDIM) - mean * mean;
    const float rstd = rsqrtf(var + LN_EPS);

    float4 o4;
    o4.x = (v[0] - mean) * rstd * xg[lane * 4 + 0] + xb[lane * 4 + 0];
    o4.y = (v[1] - mean) * rstd * xg[lane * 4 + 1] + xb[lane * 4 + 1];
    o4.z = (v[2] - mean) * rstd * xg[lane * 4 + 2] + xb[lane * 4 + 2];
    o4.w = (v[3] - mean) * rstd * xg[lane * 4 + 3] + xb[lane * 4 + 3];
    *(float4*)&g_h[base]    = o4;
    *(float4*)&g_hagg[base] = make_float4(0.f, 0.f, 0.f, 0.f);
}

// ---------------- decoder ----------------
__global__ void __launch_bounds__(256) decoder_kernel(
    const float* __restrict__ w1, const float* __restrict__ b1,
    const float* __restrict__ w2, const float* __restrict__ b2,
    const float* __restrict__ noise, float* __restrict__ out)
{
    const int warp = threadIdx.x >> 5, lane = threadIdx.x & 31;
    const int n = blockIdx.x * 8 + warp;
    if (n >= N_NODES) return;
    const float* hrow = &g_h[(size_t)n * HDIM];

    float acc[4];
    #pragma unroll
    for (int j = 0; j < 4; j++) acc[j] = b1[lane * 4 + j];
    for (int k = 0; k < HDIM; k++) {
        const float hk = __ldg(&hrow[k]);
        const float4 w = *(const float4*)&w1[k * HDIM + lane * 4];
        acc[0] += hk * w.x; acc[1] += hk * w.y; acc[2] += hk * w.z; acc[3] += hk * w.w;
    }
    float o0 = 0.f, o1 = 0.f;
    #pragma unroll
    for (int j = 0; j < 4; j++) {
        const float hid = fmaxf(acc[j], 0.f);
        const int c = lane * 4 + j;
        o0 += hid * w2[c * 2 + 0];
        o1 += hid * w2[c * 2 + 1];
    }
    #pragma unroll
    for (int o = 16; o > 0; o >>= 1) {
        o0 += __shfl_xor_sync(0xffffffffu, o0, o);
        o1 += __shfl_xor_sync(0xffffffffu, o1, o);
    }
    if (lane == 0) {
        out[n * 2 + 0] = o0 + b2[0] - noise[n * 16 + 0];
        out[n * 2 + 1] = o1 + b2[1] - noise[n * 16 + 1];
    }
}

// ---------------- launch ----------------
extern "C" void kernel_launch(void* const* d_in, const int* in_sizes, int n_in,
                              void* d_out, int out_size)
{
    const float* x          = (const float*)d_in[0];
    const float* edge_attr  = (const float*)d_in[1];
    const int*   ei         = (const int*)d_in[2];
    const float* node_noise = (const float*)d_in[3];
    const float* edge_noise = (const float*)d_in[4];
    const float* nw1 = (const float*)d_in[5];  const float* nb1 = (const float*)d_in[6];
    const float* nw2 = (const float*)d_in[7];  const float* nb2 = (const float*)d_in[8];
    const float* ew1 = (const float*)d_in[9];  const float* eb1 = (const float*)d_in[10];
    const float* ew2 = (const float*)d_in[11]; const float* eb2 = (const float*)d_in[12];
    const float* gew1 = (const float*)d_in[13]; const float* geb1 = (const float*)d_in[14];
    const float* gew2 = (const float*)d_in[15]; const float* geb2 = (const float*)d_in[16];
    const float* gnw1 = (const float*)d_in[17]; const float* gnb1 = (const float*)d_in[18];
    const float* gnw2 = (const float*)d_in[19]; const float* gnb2 = (const float*)d_in[20];
    const float* xlg = (const float*)d_in[21]; const float* xlb = (const float*)d_in[22];
    const float* elg = (const float*)d_in[23]; const float* elb = (const float*)d_in[24];
    const float* dw1 = (const float*)d_in[25]; const float* db1 = (const float*)d_in[26];
    const float* dw2 = (const float*)d_in[27]; const float* db2 = (const float*)d_in[28];
    float* out = (float*)d_out;

    float* ph = nullptr;
    cudaGetSymbolAddress((void**)&ph, g_h);
    __nv_bfloat16 *w1h, *w1l, *w2h, *w2l, *w3h, *w3l, *w4h, *w4l, *e2h, *e2l;
    cudaGetSymbolAddress((void**)&w1h, g_We1Th); cudaGetSymbolAddress((void**)&w1l, g_We1Tl);
    cudaGetSymbolAddress((void**)&w2h, g_We2Th); cudaGetSymbolAddress((void**)&w2l, g_We2Tl);
    cudaGetSymbolAddress((void**)&w3h, g_Wn1Th); cudaGetSymbolAddress((void**)&w3l, g_Wn1Tl);
    cudaGetSymbolAddress((void**)&w4h, g_Wn2Th); cudaGetSymbolAddress((void**)&w4l, g_Wn2Tl);
    cudaGetSymbolAddress((void**)&e2h, g_Ee2Th); cudaGetSymbolAddress((void**)&e2l, g_Ee2Tl);

    cudaFuncSetAttribute(gnn_layer_mma, cudaFuncAttributeMaxDynamicSharedMemorySize, GNN_SMEM);
    cudaFuncSetAttribute(node_pre_mma,  cudaFuncAttributeMaxDynamicSharedMemorySize, GNN_SMEM);
    cudaFuncSetAttribute(edge_enc_mma,  cudaFuncAttributeMaxDynamicSharedMemorySize, ENC_SMEM);

    zero_deg_kernel<<<(N_NODES + 255) / 256, 256>>>();
    calc_deg_kernel<<<(N_EDGES + 255) / 256, 256>>>(ei);
    prep_w_kernel<<<(384 * 128 + 255) / 256, 256>>>(gew1, w1h, w1l, 384);
    prep_w_kernel<<<(128 * 128 + 255) / 256, 256>>>(gew2, w2h, w2l, 128);
    prep_w_kernel<<<(256 * 128 + 255) / 256, 256>>>(gnw1, w3h, w3l, 256);
    prep_w_kernel<<<(128 * 128 + 255) / 256, 256>>>(gnw2, w4h, w4l, 128);
    prep_w_kernel<<<(128 * 128 + 255) / 256, 256>>>(ew2,  e2h, e2l, 128);

    node_enc_kernel<<<N_NODES / TR, 128>>>(x, node_noise, nw1, nb1, nw2, nb2, ph);
    edge_enc_mma<<<N_EDGES / TE, THREADS, ENC_SMEM>>>(edge_attr, edge_noise, ew1, eb1, eb2);

    for (int l = 0; l < NLAYERS; l++) {
        node_pre_mma<<<(N_NODES + TE - 1) / TE, THREADS, GNN_SMEM>>>(geb1, gnb1);
        gnn_layer_mma<<<N_EDGES / TE, THREADS, GNN_SMEM>>>(
            ei, geb2, gnb2, elg + (size_t)l * HDIM, elb + (size_t)l * HDIM);
        node_update_kernel<<<(N_NODES + 7) / 8, 256>>>(
            xlg + (size_t)l * HDIM, xlb + (size_t)l * HDIM);
    }

    decoder_kernel<<<(N_NODES + 7) / 8, 256>>>(dw1, db1, dw2, db2, node_noise, out);
}

// round 15
// speedup vs baseline: 13.0410x; 1.2238x over previous
/*
 * LearnedSimModel fused GNN - round 15: fp16 2-term split (ah*w + al*w).
 * Weights truncated to fp16 (error ~2^-12, the new rel_err floor ~2e-4);
 * activations exact as fp16 hi+lo pairs. 33% fewer MMAs than bf16 3-term,
 * B-lo tiles gone (staging+smem halved). e stored globally as split fp16
 * pairs -> stage A is pure cp.async; E2 reconstructs e from smem tiles.
 */
#include <cuda_runtime.h>
#include <cuda_fp16.h>
#include <cstdint>

#define N_NODES 20000
#define N_EDGES 640000
#define HDIM    128
#define NLAYERS 10
#define LN_EPS  1e-5f
#define TR      32
#define TE      128
#define THREADS 256

// dynamic smem byte offsets
#define STH   0
#define STL   32768
#define SB0   65536
#define SB1   98304
#define SDST  131072
#define SSRC  131584
#define GNN_SMEM 132096
#define SW1   131072
#define SEB1  135168
#define ENC_SMEM 135680

__device__ float g_h   [(size_t)N_NODES * HDIM];
__device__ float g_hagg[(size_t)N_NODES * HDIM];
__device__ __half g_eh [(size_t)N_EDGES * HDIM];
__device__ __half g_el [(size_t)N_EDGES * HDIM];
__device__ float g_P1  [(size_t)N_NODES * HDIM];
__device__ float g_P2  [(size_t)N_NODES * HDIM];
__device__ float g_P3  [(size_t)N_NODES * HDIM];
__device__ float g_degf[N_NODES];
__device__ __half g_We1T[128 * 384];
__device__ __half g_We2T[128 * 128];
__device__ __half g_Wn1T[128 * 256];
__device__ __half g_Wn2T[128 * 128];
__device__ __half g_Ee2T[128 * 128];

// ---------------- helpers ----------------
__device__ __forceinline__ uint32_t smem_u32(const void* p) {
    uint32_t a;
    asm("{ .reg .u64 t; cvta.to.shared.u64 t, %1; cvt.u32.u64 %0, t; }" : "=r"(a) : "l"(p));
    return a;
}
// pack two floats to f16x2 (lo = a, hi = b)
__device__ __forceinline__ uint32_t pkhl(float a, float b) {
    uint32_t r; asm("cvt.rn.f16x2.f32 %0,%1,%2;" : "=r"(r) : "f"(b), "f"(a)); return r;
}
__device__ __forceinline__ void upk(uint32_t h, float& a, float& b) {
    asm("{ .reg .f16 x,y; mov.b32 {x,y}, %2; cvt.f32.f16 %0, x; cvt.f32.f16 %1, y; }"
        : "=f"(a), "=f"(b) : "r"(h));
}
__device__ __forceinline__ uint32_t lo2(uint32_t h, float a, float b) {
    float ha, hb; upk(h, ha, hb);
    return pkhl(a - ha, b - hb);
}
// swizzled byte offset: row r (0..127), 16B-group g (0..15), 256B pitch
__device__ __forceinline__ uint32_t aoff(int r, int g) {
    return (uint32_t)(r * 256 + (((g & 8) | ((g ^ r) & 7)) << 4));
}
__device__ __forceinline__ void ldsm4(uint32_t a, uint32_t& r0, uint32_t& r1,
                                      uint32_t& r2, uint32_t& r3) {
    asm volatile("ldmatrix.sync.aligned.m8n8.x4.shared.b16 {%0,%1,%2,%3},[%4];"
                 : "=r"(r0), "=r"(r1), "=r"(r2), "=r"(r3) : "r"(a));
}
__device__ __forceinline__ void mma16816(float* c, uint32_t a0, uint32_t a1, uint32_t a2,
                                         uint32_t a3, uint32_t b0, uint32_t b1) {
    asm volatile(
        "mma.sync.aligned.m16n8k16.row.col.f32.f16.f16.f32 "
        "{%0,%1,%2,%3},{%4,%5,%6,%7},{%8,%9},{%0,%1,%2,%3};"
        : "+f"(c[0]), "+f"(c[1]), "+f"(c[2]), "+f"(c[3])
        : "r"(a0), "r"(a1), "r"(a2), "r"(a3), "r"(b0), "r"(b1));
}
__device__ __forceinline__ void cpa16(uint32_t dst, const void* src) {
    asm volatile("cp.async.cg.shared.global [%0], [%1], 16;" :: "r"(dst), "l"(src) : "memory");
}
__device__ __forceinline__ void cpa_commit() { asm volatile("cp.async.commit_group;" ::: "memory"); }
__device__ __forceinline__ void cpa_wait1()  { asm volatile("cp.async.wait_group 1;" ::: "memory"); }
__device__ __forceinline__ void cpa_wait0()  { asm volatile("cp.async.wait_group 0;" ::: "memory"); }

// ---------------- fused 2-term GEMM passes (single B, fp16) ----------------
#define PASS_J_BODY(A0,A1,A2,A3, L0,L1,L2,L3)                                   \
    _Pragma("unroll")                                                            \
    for (int j = 0; j < 8; j++) {                                                \
        uint32_t b0,b1,b2,b3;                                                    \
        ldsm4(sB + aoff(16 * j + bn, bg), b0, b1, b2, b3);                       \
        mma16816(acc[2*j],   A0,A1,A2,A3, b0, b1);                               \
        mma16816(acc[2*j+1], A0,A1,A2,A3, b2, b3);                               \
        mma16816(acc[2*j],   L0,L1,L2,L3, b0, b1);                               \
        mma16816(acc[2*j+1], L0,L1,L2,L3, b2, b3);                               \
    }

__device__ __forceinline__ void pass2_smem(uint32_t sAh, uint32_t sAl, uint32_t sB,
                                           float (&acc)[16][4], int lane, int R0)
{
    const int bn = 8 * (lane >> 4) + (lane & 7);
    #pragma unroll 1
    for (int t = 0; t < 8; t++) {
        const uint32_t ar = aoff(R0 + (lane & 15), 2 * t + (lane >> 4));
        uint32_t h0, h1, h2, h3, l0, l1, l2, l3;
        ldsm4(sAh + ar, h0, h1, h2, h3);
        ldsm4(sAl + ar, l0, l1, l2, l3);
        const int bg = 2 * t + ((lane >> 3) & 1);
        PASS_J_BODY(h0, h1, h2, h3, l0, l1, l2, l3)
    }
}
__device__ __forceinline__ void pass2_reg(const uint32_t (&fh)[8][4], const uint32_t (&fl)[8][4],
                                          uint32_t sB, float (&acc)[16][4], int lane)
{
    const int bn = 8 * (lane >> 4) + (lane & 7);
    #pragma unroll 1
    for (int t = 0; t < 8; t++) {
        const int bg = 2 * t + ((lane >> 3) & 1);
        PASS_J_BODY(fh[t][0], fh[t][1], fh[t][2], fh[t][3],
                    fl[t][0], fl[t][1], fl[t][2], fl[t][3])
    }
}

// ---------------- staging ----------------
__device__ __forceinline__ void stageB(uint32_t sb, uint32_t bOff,
                                       const __half* __restrict__ Wh,
                                       int ktot, int k0, int tid)
{
    #pragma unroll 4
    for (int i = tid; i < 2048; i += THREADS) {
        const int n = i >> 4, g = i & 15;
        cpa16(sb + bOff + aoff(n, g), Wh + (size_t)n * ktot + k0 + g * 8);
    }
}
__device__ __forceinline__ void stageA_e(uint32_t sb, int e0, int tid)
{
    #pragma unroll 4
    for (int i = tid; i < 2048; i += THREADS) {
        const int r = i >> 4, g = i & 15;
        const uint32_t o = aoff(r, g);
        const size_t gsrc = (size_t)(e0 + r) * HDIM + g * 8;
        cpa16(sb + STH + o, g_eh + gsrc);
        cpa16(sb + STL + o, g_el + gsrc);
    }
}
__device__ __forceinline__ void stageA_split(char* smem, const float* __restrict__ rowptr,
                                             int r, int g)
{
    const float4* p = (const float4*)(rowptr + g * 8);
    const float4 u = p[0], v = p[1];
    const uint32_t h0 = pkhl(u.x, u.y), h1 = pkhl(u.z, u.w);
    const uint32_t h2 = pkhl(v.x, v.y), h3 = pkhl(v.z, v.w);
    uint4 H; H.x = h0; H.y = h1; H.z = h2; H.w = h3;
    uint4 L; L.x = lo2(h0, u.x, u.y); L.y = lo2(h1, u.z, u.w);
             L.z = lo2(h2, v.x, v.y); L.w = lo2(h3, v.z, v.w);
    const uint32_t off = aoff(r, g);
    *(uint4*)(smem + STH + off) = H;
    *(uint4*)(smem + STL + off) = L;
}
__device__ __forceinline__ void stageA_nodes(char* smem, const float* __restrict__ src,
                                             int row0, int tid)
{
    #pragma unroll 2
    for (int i = tid; i < 2048; i += THREADS) {
        const int r = i >> 4, g = i & 15;
        int rr = row0 + r; if (rr >= N_NODES) rr = N_NODES - 1;
        stageA_split(smem, src + (size_t)rr * HDIM, r, g);
    }
}
__device__ __forceinline__ void epi_relu_frag(float (&acc)[16][4], const float* __restrict__ bias,
                                              uint32_t (&fh)[8][4], uint32_t (&fl)[8][4], int lane)
{
    #pragma unroll
    for (int j = 0; j < 16; j++) {
        const int col = 8 * j + 2 * (lane & 3);
        const float b0 = bias[col], b1 = bias[col + 1];
        const float f0 = fmaxf(acc[j][0] + b0, 0.f);
        const float f1 = fmaxf(acc[j][1] + b1, 0.f);
        const float f2 = fmaxf(acc[j][2] + b0, 0.f);
        const float f3 = fmaxf(acc[j][3] + b1, 0.f);
        const int t = j >> 1, o = (j & 1) * 2;
        const uint32_t h01 = pkhl(f0, f1), h23 = pkhl(f2, f3);
        fh[t][o] = h01; fh[t][o + 1] = h23;
        fl[t][o] = lo2(h01, f0, f1); fl[t][o + 1] = lo2(h23, f2, f3);
    }
}
__device__ __forceinline__ void zacc(float (&acc)[16][4]) {
    #pragma unroll
    for (int j = 0; j < 16; j++)
        #pragma unroll
        for (int c = 0; c < 4; c++) acc[j][c] = 0.f;
}
// read exact e (hi+lo) for (row r, word j, quad c4) from smem tiles
__device__ __forceinline__ float2 eread(const char* smem, int r, int j, int c4)
{
    const uint32_t hh = *(const uint32_t*)(smem + STH + aoff(r, j) + c4 * 4);
    const uint32_t ll = *(const uint32_t*)(smem + STL + aoff(r, j) + c4 * 4);
    float h0, h1, l0, l1;
    upk(hh, h0, h1); upk(ll, l0, l1);
    return make_float2(h0 + l0, h1 + l1);
}
// write value pair as split fp16 to global e arrays
__device__ __forceinline__ void ewrite(size_t idx, float x, float y)
{
    const uint32_t hp = pkhl(x, y);
    *(uint32_t*)&g_eh[idx] = hp;
    *(uint32_t*)&g_el[idx] = lo2(hp, x, y);
}

// ---------------- node precompute: P1/P2/P3 ----------------
__device__ __forceinline__ void epi_writeP(float (&acc)[16][4], float* __restrict__ P,
                                           const float* __restrict__ bias,
                                           int row0, int lane, int R0)
{
    const int r0 = R0 + (lane >> 2), r1 = r0 + 8;
    const int n0 = row0 + r0, n1 = row0 + r1;
    #pragma unroll
    for (int j = 0; j < 16; j++) {
        const int col = 8 * j + 2 * (lane & 3);
        const float b0 = bias ? bias[col] : 0.f;
        const float b1 = bias ? bias[col + 1] : 0.f;
        if (n0 < N_NODES)
            *(float2*)&P[(size_t)n0 * HDIM + col] = make_float2(acc[j][0] + b0, acc[j][1] + b1);
        if (n1 < N_NODES)
            *(float2*)&P[(size_t)n1 * HDIM + col] = make_float2(acc[j][2] + b0, acc[j][3] + b1);
    }
}

__global__ void __launch_bounds__(THREADS, 1) node_pre_mma(
    const float* __restrict__ be1, const float* __restrict__ bn1)
{
    extern __shared__ char smem[];
    const uint32_t sb = smem_u32(smem);
    const int tid = threadIdx.x, lane = tid & 31, warp = tid >> 5;
    const int R0 = warp * 16;
    const int row0 = blockIdx.x * TE;
    float acc[16][4];

    stageB(sb, SB0, g_We1T, 384, 0, tid);   cpa_commit();
    stageB(sb, SB1, g_We1T, 384, 128, tid); cpa_commit();
    stageA_nodes(smem, g_h, row0, tid);

    zacc(acc);
    cpa_wait1(); __syncthreads();
    pass2_smem(sb + STH, sb + STL, sb + SB0, acc, lane, R0);
    epi_writeP(acc, g_P1, be1, row0, lane, R0);
    __syncthreads();
    stageB(sb, SB0, g_Wn1T, 256, 0, tid);   cpa_commit();

    zacc(acc);
    cpa_wait1(); __syncthreads();
    pass2_smem(sb + STH, sb + STL, sb + SB1, acc, lane, R0);
    epi_writeP(acc, g_P2, nullptr, row0, lane, R0);

    zacc(acc);
    cpa_wait0(); __syncthreads();
    pass2_smem(sb + STH, sb + STL, sb + SB0, acc, lane, R0);
    epi_writeP(acc, g_P3, bn1, row0, lane, R0);
}

// ---------------- fused GNN layer (4 passes, 2-term) ----------------
__global__ void __launch_bounds__(THREADS, 1) gnn_layer_mma(
    const int* __restrict__ ei,
    const float* __restrict__ be2, const float* __restrict__ bn2,
    const float* __restrict__ eg,  const float* __restrict__ eb)
{
    extern __shared__ char smem[];
    const uint32_t sb = smem_u32(smem);
    const int tid = threadIdx.x, lane = tid & 31, warp = tid >> 5;
    const int R0 = warp * 16;
    const int e0 = blockIdx.x * TE;
    int* s_dst = (int*)(smem + SDST);
    int* s_src = (int*)(smem + SSRC);

    if (tid < TE) s_src[tid]      = ei[e0 + tid];
    else          s_dst[tid - TE] = ei[(size_t)N_EDGES + e0 + (tid - TE)];

    float acc[16][4];
    uint32_t enh[8][4], enl[8][4];
    uint32_t fh[8][4],  fl[8][4];

    stageB(sb, SB0, g_We1T, 384, 256, tid);   // We1_e
    stageA_e(sb, e0, tid);
    cpa_commit();                             // group0: B0 + A
    stageB(sb, SB1, g_We2T, 128, 0, tid);
    cpa_commit();                             // group1: We2

    // ======== GEMM_e: e @ We1_e ========
    zacc(acc);
    cpa_wait1(); __syncthreads();
    pass2_smem(sb + STH, sb + STL, sb + SB0, acc, lane, R0);
    __syncthreads();                          // SB0 free
    stageB(sb, SB0, g_Wn1T, 256, 128, tid);
    cpa_commit();                             // group2: Wn1_en

    // E1: + P1[dst] + P2[src], relu -> fragments
    {
        const int r0 = R0 + (lane >> 2), r1 = r0 + 8;
        const int d0 = s_dst[r0], d1 = s_dst[r1];
        const int u0 = s_src[r0], u1 = s_src[r1];
        #pragma unroll
        for (int j = 0; j < 16; j++) {
            const int col = 8 * j + 2 * (lane & 3);
            const float2 p1A = *(const float2*)&g_P1[(size_t)d0 * HDIM + col];
            const float2 p1B = *(const float2*)&g_P1[(size_t)d1 * HDIM + col];
            const float2 p2A = *(const float2*)&g_P2[(size_t)u0 * HDIM + col];
            const float2 p2B = *(const float2*)&g_P2[(size_t)u1 * HDIM + col];
            const float f0 = fmaxf(acc[j][0] + p1A.x + p2A.x, 0.f);
            const float f1 = fmaxf(acc[j][1] + p1A.y + p2A.y, 0.f);
            const float f2 = fmaxf(acc[j][2] + p1B.x + p2B.x, 0.f);
            const float f3 = fmaxf(acc[j][3] + p1B.y + p2B.y, 0.f);
            const int t = j >> 1, o = (j & 1) * 2;
            const uint32_t h01 = pkhl(f0, f1), h23 = pkhl(f2, f3);
            fh[t][o] = h01; fh[t][o + 1] = h23;
            fl[t][o] = lo2(h01, f0, f1); fl[t][o + 1] = lo2(h23, f2, f3);
        }
    }

    // ======== GEMM2: hid @ We2 ========
    zacc(acc);
    cpa_wait1(); __syncthreads();
    pass2_reg(fh, fl, sb + SB1, acc, lane);
    __syncthreads();                          // SB1 free
    stageB(sb, SB1, g_Wn2T, 128, 0, tid);
    cpa_commit();                             // group3: Wn2

    // E2: e_new fragments + edge LN (e reconstructed from smem tiles)
    {
        const int r0 = R0 + (lane >> 2), r1 = r0 + 8;
        const int c4 = lane & 3;
        float s0 = 0.f, q0 = 0.f, s1 = 0.f, q1 = 0.f;
        #pragma unroll
        for (int j = 0; j < 16; j++) {
            const float b0 = be2[8 * j + 2 * c4], b1 = be2[8 * j + 2 * c4 + 1];
            const float2 eA = eread(smem, r0, j, c4);
            const float2 eB = eread(smem, r1, j, c4);
            const float n0 = eA.x + acc[j][0] + b0;
            const float n1 = eA.y + acc[j][1] + b1;
            const float n2 = eB.x + acc[j][2] + b0;
            const float n3 = eB.y + acc[j][3] + b1;
            const int t = j >> 1, o = (j & 1) * 2;
            const uint32_t h01 = pkhl(n0, n1), h23 = pkhl(n2, n3);
            enh[t][o] = h01; enh[t][o + 1] = h23;
            enl[t][o] = lo2(h01, n0, n1); enl[t][o + 1] = lo2(h23, n2, n3);
            const float t0 = eA.x + n0, t1 = eA.y + n1;
            const float t2 = eB.x + n2, t3 = eB.y + n3;
            acc[j][0] = t0; acc[j][1] = t1; acc[j][2] = t2; acc[j][3] = t3;
            s0 += t0 + t1; q0 += t0 * t0 + t1 * t1;
            s1 += t2 + t3; q1 += t2 * t2 + t3 * t3;
        }
        s0 += __shfl_xor_sync(0xffffffffu, s0, 1); s0 += __shfl_xor_sync(0xffffffffu, s0, 2);
        q0 += __shfl_xor_sync(0xffffffffu, q0, 1); q0 += __shfl_xor_sync(0xffffffffu, q0, 2);
        s1 += __shfl_xor_sync(0xffffffffu, s1, 1); s1 += __shfl_xor_sync(0xffffffffu, s1, 2);
        q1 += __shfl_xor_sync(0xffffffffu, q1, 1); q1 += __shfl_xor_sync(0xffffffffu, q1, 2);
        const float m0 = s0 * (1.f / HDIM), m1 = s1 * (1.f / HDIM);
        const float r0std = rsqrtf(q0 * (1.f / HDIM) - m0 * m0 + LN_EPS);
        const float r1std = rsqrtf(q1 * (1.f / HDIM) - m1 * m1 + LN_EPS);
        #pragma unroll
        for (int j = 0; j < 16; j++) {
            const int col = 8 * j + 2 * c4;
            const float g0 = eg[col], g1 = eg[col + 1];
            const float bb0 = eb[col], bb1 = eb[col + 1];
            ewrite((size_t)(e0 + r0) * HDIM + col,
                   (acc[j][0] - m0) * r0std * g0 + bb0,
                   (acc[j][1] - m0) * r0std * g1 + bb1);
            ewrite((size_t)(e0 + r1) * HDIM + col,
                   (acc[j][2] - m1) * r1std * g0 + bb0,
                   (acc[j][3] - m1) * r1std * g1 + bb1);
        }
    }

    // ======== GEMM3: e_new @ Wn1_en ========
    zacc(acc);
    cpa_wait1(); __syncthreads();
    pass2_reg(enh, enl, sb + SB0, acc, lane);

    // E3: + P3[dst], relu -> fragments
    {
        const int r0 = R0 + (lane >> 2), r1 = r0 + 8;
        const int d0 = s_dst[r0], d1 = s_dst[r1];
        #pragma unroll
        for (int j = 0; j < 16; j++) {
            const int col = 8 * j + 2 * (lane & 3);
            const float2 pA = *(const float2*)&g_P3[(size_t)d0 * HDIM + col];
            const float2 pB = *(const float2*)&g_P3[(size_t)d1 * HDIM + col];
            const float f0 = fmaxf(acc[j][0] + pA.x, 0.f);
            const float f1 = fmaxf(acc[j][1] + pA.y, 0.f);
            const float f2 = fmaxf(acc[j][2] + pB.x, 0.f);
            const float f3 = fmaxf(acc[j][3] + pB.y, 0.f);
            const int t = j >> 1, o = (j & 1) * 2;
            const uint32_t h01 = pkhl(f0, f1), h23 = pkhl(f2, f3);
            fh[t][o] = h01; fh[t][o + 1] = h23;
            fl[t][o] = lo2(h01, f0, f1); fl[t][o + 1] = lo2(h23, f2, f3);
        }
    }

    // ======== GEMM4: hid2 @ Wn2 ========
    zacc(acc);
    cpa_wait0(); __syncthreads();
    pass2_reg(fh, fl, sb + SB1, acc, lane);

    // E4: scatter (xi residual folded via deg)
    {
        const int r0 = R0 + (lane >> 2), r1 = r0 + 8;
        const int d0 = s_dst[r0], d1 = s_dst[r1];
        #pragma unroll
        for (int j = 0; j < 16; j++) {
            const int col = 8 * j + 2 * (lane & 3);
            const float b0 = bn2[col], b1 = bn2[col + 1];
            float* p0 = &g_hagg[(size_t)d0 * HDIM + col];
            float* p1 = &g_hagg[(size_t)d1 * HDIM + col];
            asm volatile("red.global.add.v2.f32 [%0], {%1,%2};"
                         :: "l"(p0), "f"(acc[j][0] + b0), "f"(acc[j][1] + b1) : "memory");
            asm volatile("red.global.add.v2.f32 [%0], {%1,%2};"
                         :: "l"(p1), "f"(acc[j][2] + b0), "f"(acc[j][3] + b1) : "memory");
        }
    }
}

// ---------------- edge encoder (mma, 2-term) ----------------
__global__ void __launch_bounds__(THREADS, 1) edge_enc_mma(
    const float* __restrict__ ea, const float* __restrict__ noise,
    const float* __restrict__ w1, const float* __restrict__ b1,
    const float* __restrict__ b2)
{
    extern __shared__ char smem[];
    const uint32_t sb = smem_u32(smem);
    const int tid = threadIdx.x, lane = tid & 31, warp = tid >> 5;
    const int R0 = warp * 16;
    const int e0 = blockIdx.x * TE;
    float* sw1 = (float*)(smem + SW1);
    float* sb1 = (float*)(smem + SEB1);

    stageB(sb, SB0, g_Ee2T, 128, 0, tid); cpa_commit();

    for (int i = tid; i < 1024; i += THREADS) sw1[i] = w1[i];
    if (tid < 128) sb1[tid] = b1[tid];
    __syncthreads();

    // layer 1 (K=8, fp32 exact) -> hid hi/lo fp16 tiles
    {
        const int row = tid & 127, half = tid >> 7;
        const size_t grow = (size_t)(e0 + row) * 8;
        float in8[8];
        #pragma unroll
        for (int k = 0; k < 8; k++) in8[k] = ea[grow + k] + noise[grow + k];
        #pragma unroll 1
        for (int gg = 0; gg < 8; gg++) {
            const int g = half * 8 + gg;
            uint32_t H[4], L[4];
            #pragma unroll
            for (int p = 0; p < 4; p++) {
                const int col = g * 8 + p * 2;
                float v0 = sb1[col], v1 = sb1[col + 1];
                #pragma unroll
                for (int k = 0; k < 8; k++) {
                    v0 += in8[k] * sw1[k * 128 + col];
                    v1 += in8[k] * sw1[k * 128 + col + 1];
                }
                v0 = fmaxf(v0, 0.f); v1 = fmaxf(v1, 0.f);
                H[p] = pkhl(v0, v1); L[p] = lo2(H[p], v0, v1);
            }
            *(uint4*)(smem + STH + aoff(row, g)) = make_uint4(H[0], H[1], H[2], H[3]);
            *(uint4*)(smem + STL + aoff(row, g)) = make_uint4(L[0], L[1], L[2], L[3]);
        }
    }
    float acc[16][4];
    zacc(acc);
    cpa_wait0(); __syncthreads();
    pass2_smem(sb + STH, sb + STL, sb + SB0, acc, lane, R0);

    {
        const int r0 = R0 + (lane >> 2), r1 = r0 + 8;
        #pragma unroll
        for (int j = 0; j < 16; j++) {
            const int col = 8 * j + 2 * (lane & 3);
            const float b0 = b2[col], b1v = b2[col + 1];
            ewrite((size_t)(e0 + r0) * HDIM + col, acc[j][0] + b0, acc[j][1] + b1v);
            ewrite((size_t)(e0 + r1) * HDIM + col, acc[j][2] + b0, acc[j][3] + b1v);
        }
    }
}

// ---------------- prep kernels ----------------
__global__ void prep_w_kernel(const float* __restrict__ W, __half* __restrict__ Wh, int K)
{
    const int i = blockIdx.x * 256 + threadIdx.x;
    if (i < K * 128) {
        const int n = i & 127, k = i >> 7;
        Wh[(size_t)n * K + k] = __float2half_rn(W[(size_t)k * 128 + n]);
    }
}
__global__ void zero_deg_kernel() {
    const int i = blockIdx.x * 256 + threadIdx.x;
    if (i < N_NODES) g_degf[i] = 0.f;
}
__global__ void calc_deg_kernel(const int* __restrict__ ei) {
    const int i = blockIdx.x * 256 + threadIdx.x;
    if (i < N_EDGES) atomicAdd(&g_degf[ei[(size_t)N_EDGES + i]], 1.0f);
}

// ---------------- node encoder (fp32 SIMT, tiny) ----------------
__global__ void __launch_bounds__(128) node_enc_kernel(
    const float* __restrict__ in, const float* __restrict__ noise,
    const float* __restrict__ w1, const float* __restrict__ b1,
    const float* __restrict__ w2, const float* __restrict__ b2,
    float* __restrict__ out)
{
    __shared__ float s_in [TR * 16];
    __shared__ float s_hid[TR * HDIM];
    const int tid = threadIdx.x;
    const size_t row0 = (size_t)blockIdx.x * TR;

    for (int i = tid; i < TR * 16; i += 128)
        s_in[i] = in[row0 * 16 + i] + noise[row0 * 16 + i];
    __syncthreads();

    float acc[TR];
    {
        const float bb = b1[tid];
        #pragma unroll
        for (int r = 0; r < TR; r++) acc[r] = bb;
    }
    #pragma unroll
    for (int k = 0; k < 16; k++) {
        const float w = w1[k * HDIM + tid];
        #pragma unroll
        for (int r = 0; r < TR; r++) acc[r] += s_in[r * 16 + k] * w;
    }
    #pragma unroll
    for (int r = 0; r < TR; r++) s_hid[r * HDIM + tid] = fmaxf(acc[r], 0.f);
    __syncthreads();

    {
        const float bb = b2[tid];
        #pragma unroll
        for (int r = 0; r < TR; r++) acc[r] = bb;
    }
    for (int k = 0; k < HDIM; k++) {
        const float w = w2[k * HDIM + tid];
        #pragma unroll
        for (int r = 0; r < TR; r++) acc[r] += s_hid[r * HDIM + k] * w;
    }
    #pragma unroll
    for (int r = 0; r < TR; r++) out[(row0 + r) * HDIM + tid] = acc[r];
}

// ---------------- node update: g_h <- LN(h*(1+deg) + agg); g_hagg <- 0 ----------------
__global__ void __launch_bounds__(256) node_update_kernel(
    const float* __restrict__ xg, const float* __restrict__ xb)
{
    const int warp = threadIdx.x >> 5, lane = threadIdx.x & 31;
    const int n = blockIdx.x * 8 + warp;
    if (n >= N_NODES) return;
    const size_t base = (size_t)n * HDIM + lane * 4;
    const float dg1 = 1.f + g_degf[n];

    const float4 hv = *(const float4*)&g_h[base];
    const float4 av = *(const float4*)&g_hagg[base];
    float v[4] = { hv.x * dg1 + av.x, hv.y * dg1 + av.y,
                   hv.z * dg1 + av.z, hv.w * dg1 + av.w };
    float s = 0.f, q = 0.f;
    #pragma unroll
    for (int j = 0; j < 4; j++) { s += v[j]; q += v[j] * v[j]; }
    #pragma unroll
    for (int o = 16; o > 0; o >>= 1) {
        s += __shfl_xor_sync(0xffffffffu, s, o);
        q += __shfl_xor_sync(0xffffffffu, q, o);
    }
    const float mean = s * (1.f / HDIM);
    const float var  = q * (1.f / HDIM) - mean * mean;
    const float rstd = rsqrtf(var + LN_EPS);

    float4 o4;
    o4.x = (v[0] - mean) * rstd * xg[lane * 4 + 0] + xb[lane * 4 + 0];
    o4.y = (v[1] - mean) * rstd * xg[lane * 4 + 1] + xb[lane * 4 + 1];
    o4.z = (v[2] - mean) * rstd * xg[lane * 4 + 2] + xb[lane * 4 + 2];
    o4.w = (v[3] - mean) * rstd * xg[lane * 4 + 3] + xb[lane * 4 + 3];
    *(float4*)&g_h[base]    = o4;
    *(float4*)&g_hagg[base] = make_float4(0.f, 0.f, 0.f, 0.f);
}

// ---------------- decoder ----------------
__global__ void __launch_bounds__(256) decoder_kernel(
    const float* __restrict__ w1, const float* __restrict__ b1,
    const float* __restrict__ w2, const float* __restrict__ b2,
    const float* __restrict__ noise, float* __restrict__ out)
{
    const int warp = threadIdx.x >> 5, lane = threadIdx.x & 31;
    const int n = blockIdx.x * 8 + warp;
    if (n >= N_NODES) return;
    const float* hrow = &g_h[(size_t)n * HDIM];

    float acc[4];
    #pragma unroll
    for (int j = 0; j < 4; j++) acc[j] = b1[lane * 4 + j];
    for (int k = 0; k < HDIM; k++) {
        const float hk = __ldg(&hrow[k]);
        const float4 w = *(const float4*)&w1[k * HDIM + lane * 4];
        acc[0] += hk * w.x; acc[1] += hk * w.y; acc[2] += hk * w.z; acc[3] += hk * w.w;
    }
    float o0 = 0.f, o1 = 0.f;
    #pragma unroll
    for (int j = 0; j < 4; j++) {
        const float hid = fmaxf(acc[j], 0.f);
        const int c = lane * 4 + j;
        o0 += hid * w2[c * 2 + 0];
        o1 += hid * w2[c * 2 + 1];
    }
    #pragma unroll
    for (int o = 16; o > 0; o >>= 1) {
        o0 += __shfl_xor_sync(0xffffffffu, o0, o);
        o1 += __shfl_xor_sync(0xffffffffu, o1, o);
    }
    if (lane == 0) {
        out[n * 2 + 0] = o0 + b2[0] - noise[n * 16 + 0];
        out[n * 2 + 1] = o1 + b2[1] - noise[n * 16 + 1];
    }
}

// ---------------- launch ----------------
extern "C" void kernel_launch(void* const* d_in, const int* in_sizes, int n_in,
                              void* d_out, int out_size)
{
    const float* x          = (const float*)d_in[0];
    const float* edge_attr  = (const float*)d_in[1];
    const int*   ei         = (const int*)d_in[2];
    const float* node_noise = (const float*)d_in[3];
    const float* edge_noise = (const float*)d_in[4];
    const float* nw1 = (const float*)d_in[5];  const float* nb1 = (const float*)d_in[6];
    const float* nw2 = (const float*)d_in[7];  const float* nb2 = (const float*)d_in[8];
    const float* ew1 = (const float*)d_in[9];  const float* eb1 = (const float*)d_in[10];
    const float* ew2 = (const float*)d_in[11]; const float* eb2 = (const float*)d_in[12];
    const float* gew1 = (const float*)d_in[13]; const float* geb1 = (const float*)d_in[14];
    const float* gew2 = (const float*)d_in[15]; const float* geb2 = (const float*)d_in[16];
    const float* gnw1 = (const float*)d_in[17]; const float* gnb1 = (const float*)d_in[18];
    const float* gnw2 = (const float*)d_in[19]; const float* gnb2 = (const float*)d_in[20];
    const float* xlg = (const float*)d_in[21]; const float* xlb = (const float*)d_in[22];
    const float* elg = (const float*)d_in[23]; const float* elb = (const float*)d_in[24];
    const float* dw1 = (const float*)d_in[25]; const float* db1 = (const float*)d_in[26];
    const float* dw2 = (const float*)d_in[27]; const float* db2 = (const float*)d_in[28];
    float* out = (float*)d_out;

    float* ph = nullptr;
    cudaGetSymbolAddress((void**)&ph, g_h);
    __half *w1h, *w2h, *w3h, *w4h, *e2h;
    cudaGetSymbolAddress((void**)&w1h, g_We1T);
    cudaGetSymbolAddress((void**)&w2h, g_We2T);
    cudaGetSymbolAddress((void**)&w3h, g_Wn1T);
    cudaGetSymbolAddress((void**)&w4h, g_Wn2T);
    cudaGetSymbolAddress((void**)&e2h, g_Ee2T);

    cudaFuncSetAttribute(gnn_layer_mma, cudaFuncAttributeMaxDynamicSharedMemorySize, GNN_SMEM);
    cudaFuncSetAttribute(node_pre_mma,  cudaFuncAttributeMaxDynamicSharedMemorySize, GNN_SMEM);
    cudaFuncSetAttribute(edge_enc_mma,  cudaFuncAttributeMaxDynamicSharedMemorySize, ENC_SMEM);

    zero_deg_kernel<<<(N_NODES + 255) / 256, 256>>>();
    calc_deg_kernel<<<(N_EDGES + 255) / 256, 256>>>(ei);
    prep_w_kernel<<<(384 * 128 + 255) / 256, 256>>>(gew1, w1h, 384);
    prep_w_kernel<<<(128 * 128 + 255) / 256, 256>>>(gew2, w2h, 128);
    prep_w_kernel<<<(256 * 128 + 255) / 256, 256>>>(gnw1, w3h, 256);
    prep_w_kernel<<<(128 * 128 + 255) / 256, 256>>>(gnw2, w4h, 128);
    prep_w_kernel<<<(128 * 128 + 255) / 256, 256>>>(ew2,  e2h, 128);

    node_enc_kernel<<<N_NODES / TR, 128>>>(x, node_noise, nw1, nb1, nw2, nb2, ph);
    edge_enc_mma<<<N_EDGES / TE, THREADS, ENC_SMEM>>>(edge_attr, edge_noise, ew1, eb1, eb2);

    for (int l = 0; l < NLAYERS; l++) {
        node_pre_mma<<<(N_NODES + TE - 1) / TE, THREADS, GNN_SMEM>>>(geb1, gnb1);
        gnn_layer_mma<<<N_EDGES / TE, THREADS, GNN_SMEM>>>(
            ei, geb2, gnb2, elg + (size_t)l * HDIM, elb + (size_t)l * HDIM);
        node_update_kernel<<<(N_NODES + 7) / 8, 256>>>(
            xlg + (size_t)l * HDIM, xlb + (size_t)l * HDIM);
    }

    decoder_kernel<<<(N_NODES + 7) / 8, 256>>>(dw1, db1, dw2, db2, node_noise, out);
}

// round 16
// speedup vs baseline: 15.8504x; 1.2154x over previous
/*
 * LearnedSimModel fused GNN - round 16: 2 CTAs/SM via register diet.
 * All inter-GEMM fragments flow through the smem A-tiles (hi/lo fp16),
 * deleting ~128 frag registers; single 32KB B buffer -> 97KB smem.
 * __launch_bounds__(256,2) => 2 resident CTAs overlap MMA with staging,
 * P-gathers, LN and scatter. Math value-identical to R15.
 */
#include <cuda_runtime.h>
#include <cuda_fp16.h>
#include <cstdint>

#define N_NODES 20000
#define N_EDGES 640000
#define HDIM    128
#define NLAYERS 10
#define LN_EPS  1e-5f
#define TR      32
#define TE      128
#define THREADS 256

// dynamic smem byte offsets
#define STH   0
#define STL   32768
#define SB    65536
#define SDST  98304
#define SSRC  98816
#define GNN_SMEM 99328
#define SW1   98304
#define SEB1  102400
#define ENC_SMEM 102912

__device__ float g_h   [(size_t)N_NODES * HDIM];
__device__ float g_hagg[(size_t)N_NODES * HDIM];
__device__ __half g_eh [(size_t)N_EDGES * HDIM];
__device__ __half g_el [(size_t)N_EDGES * HDIM];
__device__ float g_P1  [(size_t)N_NODES * HDIM];
__device__ float g_P2  [(size_t)N_NODES * HDIM];
__device__ float g_P3  [(size_t)N_NODES * HDIM];
__device__ float g_degf[N_NODES];
__device__ __half g_We1T[128 * 384];
__device__ __half g_We2T[128 * 128];
__device__ __half g_Wn1T[128 * 256];
__device__ __half g_Wn2T[128 * 128];
__device__ __half g_Ee2T[128 * 128];

// ---------------- helpers ----------------
__device__ __forceinline__ uint32_t smem_u32(const void* p) {
    uint32_t a;
    asm("{ .reg .u64 t; cvta.to.shared.u64 t, %1; cvt.u32.u64 %0, t; }" : "=r"(a) : "l"(p));
    return a;
}
__device__ __forceinline__ uint32_t pkhl(float a, float b) {
    uint32_t r; asm("cvt.rn.f16x2.f32 %0,%1,%2;" : "=r"(r) : "f"(b), "f"(a)); return r;
}
__device__ __forceinline__ void upk(uint32_t h, float& a, float& b) {
    asm("{ .reg .f16 x,y; mov.b32 {x,y}, %2; cvt.f32.f16 %0, x; cvt.f32.f16 %1, y; }"
        : "=f"(a), "=f"(b) : "r"(h));
}
__device__ __forceinline__ uint32_t lo2(uint32_t h, float a, float b) {
    float ha, hb; upk(h, ha, hb);
    return pkhl(a - ha, b - hb);
}
// swizzled byte offset: row r (0..127), 16B-group g (0..15), 256B pitch
__device__ __forceinline__ uint32_t aoff(int r, int g) {
    return (uint32_t)(r * 256 + (((g & 8) | ((g ^ r) & 7)) << 4));
}
__device__ __forceinline__ void ldsm4(uint32_t a, uint32_t& r0, uint32_t& r1,
                                      uint32_t& r2, uint32_t& r3) {
    asm volatile("ldmatrix.sync.aligned.m8n8.x4.shared.b16 {%0,%1,%2,%3},[%4];"
                 : "=r"(r0), "=r"(r1), "=r"(r2), "=r"(r3) : "r"(a));
}
__device__ __forceinline__ void mma16816(float* c, uint32_t a0, uint32_t a1, uint32_t a2,
                                         uint32_t a3, uint32_t b0, uint32_t b1) {
    asm volatile(
        "mma.sync.aligned.m16n8k16.row.col.f32.f16.f16.f32 "
        "{%0,%1,%2,%3},{%4,%5,%6,%7},{%8,%9},{%0,%1,%2,%3};"
        : "+f"(c[0]), "+f"(c[1]), "+f"(c[2]), "+f"(c[3])
        : "r"(a0), "r"(a1), "r"(a2), "r"(a3), "r"(b0), "r"(b1));
}
__device__ __forceinline__ void cpa16(uint32_t dst, const void* src) {
    asm volatile("cp.async.cg.shared.global [%0], [%1], 16;" :: "r"(dst), "l"(src) : "memory");
}
__device__ __forceinline__ void cpa_commit() { asm volatile("cp.async.commit_group;" ::: "memory"); }
__device__ __forceinline__ void cpa_wait0()  { asm volatile("cp.async.wait_group 0;" ::: "memory"); }

// ---------------- 2-term GEMM pass: A (hi/lo tiles) x B (single) ----------------
__device__ __forceinline__ void pass2_smem(uint32_t sAh, uint32_t sAl, uint32_t sB,
                                           float (&acc)[16][4], int lane, int R0)
{
    const int bn = 8 * (lane >> 4) + (lane & 7);
    #pragma unroll 1
    for (int t = 0; t < 8; t++) {
        const uint32_t ar = aoff(R0 + (lane & 15), 2 * t + (lane >> 4));
        uint32_t h0, h1, h2, h3, l0, l1, l2, l3;
        ldsm4(sAh + ar, h0, h1, h2, h3);
        ldsm4(sAl + ar, l0, l1, l2, l3);
        const int bg = 2 * t + ((lane >> 3) & 1);
        #pragma unroll
        for (int j = 0; j < 8; j++) {
            uint32_t b0, b1, b2, b3;
            ldsm4(sB + aoff(16 * j + bn, bg), b0, b1, b2, b3);
            mma16816(acc[2*j],   h0, h1, h2, h3, b0, b1);
            mma16816(acc[2*j+1], h0, h1, h2, h3, b2, b3);
            mma16816(acc[2*j],   l0, l1, l2, l3, b0, b1);
            mma16816(acc[2*j+1], l0, l1, l2, l3, b2, b3);
        }
    }
}

// ---------------- staging ----------------
__device__ __forceinline__ void stageB(uint32_t sb, const __half* __restrict__ Wh,
                                       int ktot, int k0, int tid)
{
    #pragma unroll 4
    for (int i = tid; i < 2048; i += THREADS) {
        const int n = i >> 4, g = i & 15;
        cpa16(sb + SB + aoff(n, g), Wh + (size_t)n * ktot + k0 + g * 8);
    }
}
__device__ __forceinline__ void stageA_e(uint32_t sb, int e0, int tid)
{
    #pragma unroll 4
    for (int i = tid; i < 2048; i += THREADS) {
        const int r = i >> 4, g = i & 15;
        const uint32_t o = aoff(r, g);
        const size_t gsrc = (size_t)(e0 + r) * HDIM + g * 8;
        cpa16(sb + STH + o, g_eh + gsrc);
        cpa16(sb + STL + o, g_el + gsrc);
    }
}
__device__ __forceinline__ void stageA_split(char* smem, const float* __restrict__ rowptr,
                                             int r, int g)
{
    const float4* p = (const float4*)(rowptr + g * 8);
    const float4 u = p[0], v = p[1];
    const uint32_t h0 = pkhl(u.x, u.y), h1 = pkhl(u.z, u.w);
    const uint32_t h2 = pkhl(v.x, v.y), h3 = pkhl(v.z, v.w);
    uint4 H; H.x = h0; H.y = h1; H.z = h2; H.w = h3;
    uint4 L; L.x = lo2(h0, u.x, u.y); L.y = lo2(h1, u.z, u.w);
             L.z = lo2(h2, v.x, v.y); L.w = lo2(h3, v.z, v.w);
    const uint32_t off = aoff(r, g);
    *(uint4*)(smem + STH + off) = H;
    *(uint4*)(smem + STL + off) = L;
}
__device__ __forceinline__ void stageA_nodes(char* smem, const float* __restrict__ src,
                                             int row0, int tid)
{
    #pragma unroll 2
    for (int i = tid; i < 2048; i += THREADS) {
        const int r = i >> 4, g = i & 15;
        int rr = row0 + r; if (rr >= N_NODES) rr = N_NODES - 1;
        stageA_split(smem, src + (size_t)rr * HDIM, r, g);
    }
}
__device__ __forceinline__ void zacc(float (&acc)[16][4]) {
    #pragma unroll
    for (int j = 0; j < 16; j++)
        #pragma unroll
        for (int c = 0; c < 4; c++) acc[j][c] = 0.f;
}
// write a value pair as split fp16 into the A tiles at (row r, group j, word c4)
__device__ __forceinline__ void twrite(char* smem, int r, int j, int c4, float x, float y)
{
    const uint32_t hp = pkhl(x, y);
    *(uint32_t*)(smem + STH + aoff(r, j) + c4 * 4) = hp;
    *(uint32_t*)(smem + STL + aoff(r, j) + c4 * 4) = lo2(hp, x, y);
}
// write value pair as split fp16 to global e arrays
__device__ __forceinline__ void ewrite(size_t idx, float x, float y)
{
    const uint32_t hp = pkhl(x, y);
    *(uint32_t*)&g_eh[idx] = hp;
    *(uint32_t*)&g_el[idx] = lo2(hp, x, y);
}
// read exact e (hi+lo) from global split arrays
__device__ __forceinline__ float2 egread(size_t idx)
{
    const uint32_t hh = *(const uint32_t*)&g_eh[idx];
    const uint32_t ll = *(const uint32_t*)&g_el[idx];
    float h0, h1, l0, l1;
    upk(hh, h0, h1); upk(ll, l0, l1);
    return make_float2(h0 + l0, h1 + l1);
}

// ---------------- node precompute: P1/P2/P3 ----------------
__device__ __forceinline__ void epi_writeP(float (&acc)[16][4], float* __restrict__ P,
                                           const float* __restrict__ bias,
                                           int row0, int lane, int R0)
{
    const int r0 = R0 + (lane >> 2), r1 = r0 + 8;
    const int n0 = row0 + r0, n1 = row0 + r1;
    #pragma unroll
    for (int j = 0; j < 16; j++) {
        const int col = 8 * j + 2 * (lane & 3);
        const float b0 = bias ? bias[col] : 0.f;
        const float b1 = bias ? bias[col + 1] : 0.f;
        if (n0 < N_NODES)
            *(float2*)&P[(size_t)n0 * HDIM + col] = make_float2(acc[j][0] + b0, acc[j][1] + b1);
        if (n1 < N_NODES)
            *(float2*)&P[(size_t)n1 * HDIM + col] = make_float2(acc[j][2] + b0, acc[j][3] + b1);
    }
}

__global__ void __launch_bounds__(THREADS, 2) node_pre_mma(
    const float* __restrict__ be1, const float* __restrict__ bn1)
{
    extern __shared__ char smem[];
    const uint32_t sb = smem_u32(smem);
    const int tid = threadIdx.x, lane = tid & 31, warp = tid >> 5;
    const int R0 = warp * 16;
    const int row0 = blockIdx.x * TE;
    float acc[16][4];

    stageB(sb, g_We1T, 384, 0, tid); cpa_commit();
    stageA_nodes(smem, g_h, row0, tid);

    zacc(acc);
    cpa_wait0(); __syncthreads();
    pass2_smem(sb + STH, sb + STL, sb + SB, acc, lane, R0);
    __syncthreads();
    stageB(sb, g_We1T, 384, 128, tid); cpa_commit();
    epi_writeP(acc, g_P1, be1, row0, lane, R0);

    zacc(acc);
    cpa_wait0(); __syncthreads();
    pass2_smem(sb + STH, sb + STL, sb + SB, acc, lane, R0);
    __syncthreads();
    stageB(sb, g_Wn1T, 256, 0, tid); cpa_commit();
    epi_writeP(acc, g_P2, nullptr, row0, lane, R0);

    zacc(acc);
    cpa_wait0(); __syncthreads();
    pass2_smem(sb + STH, sb + STL, sb + SB, acc, lane, R0);
    epi_writeP(acc, g_P3, bn1, row0, lane, R0);
}

// ---------------- fused GNN layer (4 passes, fragments via tiles) ----------------
__global__ void __launch_bounds__(THREADS, 2) gnn_layer_mma(
    const int* __restrict__ ei,
    const float* __restrict__ be2, const float* __restrict__ bn2,
    const float* __restrict__ eg,  const float* __restrict__ eb)
{
    extern __shared__ char smem[];
    const uint32_t sb = smem_u32(smem);
    const int tid = threadIdx.x, lane = tid & 31, warp = tid >> 5;
    const int R0 = warp * 16;
    const int e0 = blockIdx.x * TE;
    int* s_dst = (int*)(smem + SDST);
    int* s_src = (int*)(smem + SSRC);

    if (tid < TE) s_src[tid]      = ei[e0 + tid];
    else          s_dst[tid - TE] = ei[(size_t)N_EDGES + e0 + (tid - TE)];

    float acc[16][4];

    stageB(sb, g_We1T, 384, 256, tid);   // We1_e
    stageA_e(sb, e0, tid);
    cpa_commit();

    // ======== pass1: e @ We1_e ========
    zacc(acc);
    cpa_wait0(); __syncthreads();
    pass2_smem(sb + STH, sb + STL, sb + SB, acc, lane, R0);
    __syncthreads();                      // tiles read + SB free
    stageB(sb, g_We2T, 128, 0, tid); cpa_commit();

    // E1: + P1[dst] + P2[src], relu -> tiles (overwrite e; e re-read from global in E2)
    {
        const int r0 = R0 + (lane >> 2), r1 = r0 + 8;
        const int d0 = s_dst[r0], d1 = s_dst[r1];
        const int u0 = s_src[r0], u1 = s_src[r1];
        const int c4 = lane & 3;
        #pragma unroll
        for (int j = 0; j < 16; j++) {
            const int col = 8 * j + 2 * c4;
            const float2 p1A = *(const float2*)&g_P1[(size_t)d0 * HDIM + col];
            const float2 p1B = *(const float2*)&g_P1[(size_t)d1 * HDIM + col];
            const float2 p2A = *(const float2*)&g_P2[(size_t)u0 * HDIM + col];
            const float2 p2B = *(const float2*)&g_P2[(size_t)u1 * HDIM + col];
            twrite(smem, r0, j, c4, fmaxf(acc[j][0] + p1A.x + p2A.x, 0.f),
                                    fmaxf(acc[j][1] + p1A.y + p2A.y, 0.f));
            twrite(smem, r1, j, c4, fmaxf(acc[j][2] + p1B.x + p2B.x, 0.f),
                                    fmaxf(acc[j][3] + p1B.y + p2B.y, 0.f));
        }
    }

    // ======== pass2: hid @ We2 ========
    zacc(acc);
    cpa_wait0(); __syncthreads();
    pass2_smem(sb + STH, sb + STL, sb + SB, acc, lane, R0);
    __syncthreads();
    stageB(sb, g_Wn1T, 256, 128, tid); cpa_commit();

    // E2: e_new = e + mlp; t = e + e_new; LN(t) -> global; e_new -> tiles
    {
        const int r0 = R0 + (lane >> 2), r1 = r0 + 8;
        const int c4 = lane & 3;
        float s0 = 0.f, q0 = 0.f, s1 = 0.f, q1 = 0.f;
        float tv[16][4];
        #pragma unroll
        for (int j = 0; j < 16; j++) {
            const int col = 8 * j + 2 * c4;
            const float b0 = be2[col], b1 = be2[col + 1];
            const float2 eA = egread((size_t)(e0 + r0) * HDIM + col);
            const float2 eB = egread((size_t)(e0 + r1) * HDIM + col);
            const float n0 = eA.x + acc[j][0] + b0;
            const float n1 = eA.y + acc[j][1] + b1;
            const float n2 = eB.x + acc[j][2] + b0;
            const float n3 = eB.y + acc[j][3] + b1;
            twrite(smem, r0, j, c4, n0, n1);
            twrite(smem, r1, j, c4, n2, n3);
            tv[j][0] = eA.x + n0; tv[j][1] = eA.y + n1;
            tv[j][2] = eB.x + n2; tv[j][3] = eB.y + n3;
            s0 += tv[j][0] + tv[j][1]; q0 += tv[j][0] * tv[j][0] + tv[j][1] * tv[j][1];
            s1 += tv[j][2] + tv[j][3]; q1 += tv[j][2] * tv[j][2] + tv[j][3] * tv[j][3];
        }
        s0 += __shfl_xor_sync(0xffffffffu, s0, 1); s0 += __shfl_xor_sync(0xffffffffu, s0, 2);
        q0 += __shfl_xor_sync(0xffffffffu, q0, 1); q0 += __shfl_xor_sync(0xffffffffu, q0, 2);
        s1 += __shfl_xor_sync(0xffffffffu, s1, 1); s1 += __shfl_xor_sync(0xffffffffu, s1, 2);
        q1 += __shfl_xor_sync(0xffffffffu, q1, 1); q1 += __shfl_xor_sync(0xffffffffu, q1, 2);
        const float m0 = s0 * (1.f / HDIM), m1 = s1 * (1.f / HDIM);
        const float r0std = rsqrtf(q0 * (1.f / HDIM) - m0 * m0 + LN_EPS);
        const float r1std = rsqrtf(q1 * (1.f / HDIM) - m1 * m1 + LN_EPS);
        #pragma unroll
        for (int j = 0; j < 16; j++) {
            const int col = 8 * j + 2 * c4;
            const float g0 = eg[col], g1 = eg[col + 1];
            const float bb0 = eb[col], bb1 = eb[col + 1];
            ewrite((size_t)(e0 + r0) * HDIM + col,
                   (tv[j][0] - m0) * r0std * g0 + bb0,
                   (tv[j][1] - m0) * r0std * g1 + bb1);
            ewrite((size_t)(e0 + r1) * HDIM + col,
                   (tv[j][2] - m1) * r1std * g0 + bb0,
                   (tv[j][3] - m1) * r1std * g1 + bb1);
        }
    }

    // ======== pass3: e_new @ Wn1_en ========
    zacc(acc);
    cpa_wait0(); __syncthreads();
    pass2_smem(sb + STH, sb + STL, sb + SB, acc, lane, R0);
    __syncthreads();
    stageB(sb, g_Wn2T, 128, 0, tid); cpa_commit();

    // E3: + P3[dst], relu -> tiles
    {
        const int r0 = R0 + (lane >> 2), r1 = r0 + 8;
        const int d0 = s_dst[r0], d1 = s_dst[r1];
        const int c4 = lane & 3;
        #pragma unroll
        for (int j = 0; j < 16; j++) {
            const int col = 8 * j + 2 * c4;
            const float2 pA = *(const float2*)&g_P3[(size_t)d0 * HDIM + col];
            const float2 pB = *(const float2*)&g_P3[(size_t)d1 * HDIM + col];
            twrite(smem, r0, j, c4, fmaxf(acc[j][0] + pA.x, 0.f),
                                    fmaxf(acc[j][1] + pA.y, 0.f));
            twrite(smem, r1, j, c4, fmaxf(acc[j][2] + pB.x, 0.f),
                                    fmaxf(acc[j][3] + pB.y, 0.f));
        }
    }

    // ======== pass4: hid2 @ Wn2 ========
    zacc(acc);
    cpa_wait0(); __syncthreads();
    pass2_smem(sb + STH, sb + STL, sb + SB, acc, lane, R0);

    // E4: scatter (xi residual folded via deg)
    {
        const int r0 = R0 + (lane >> 2), r1 = r0 + 8;
        const int d0 = s_dst[r0], d1 = s_dst[r1];
        #pragma unroll
        for (int j = 0; j < 16; j++) {
            const int col = 8 * j + 2 * (lane & 3);
            const float b0 = bn2[col], b1 = bn2[col + 1];
            float* p0 = &g_hagg[(size_t)d0 * HDIM + col];
            float* p1 = &g_hagg[(size_t)d1 * HDIM + col];
            asm volatile("red.global.add.v2.f32 [%0], {%1,%2};"
                         :: "l"(p0), "f"(acc[j][0] + b0), "f"(acc[j][1] + b1) : "memory");
            asm volatile("red.global.add.v2.f32 [%0], {%1,%2};"
                         :: "l"(p1), "f"(acc[j][2] + b0), "f"(acc[j][3] + b1) : "memory");
        }
    }
}

// ---------------- edge encoder (mma, 2-term) ----------------
__global__ void __launch_bounds__(THREADS, 2) edge_enc_mma(
    const float* __restrict__ ea, const float* __restrict__ noise,
    const float* __restrict__ w1, const float* __restrict__ b1,
    const float* __restrict__ b2)
{
    extern __shared__ char smem[];
    const uint32_t sb = smem_u32(smem);
    const int tid = threadIdx.x, lane = tid & 31, warp = tid >> 5;
    const int R0 = warp * 16;
    const int e0 = blockIdx.x * TE;
    float* sw1 = (float*)(smem + SW1);
    float* sb1 = (float*)(smem + SEB1);

    stageB(sb, g_Ee2T, 128, 0, tid); cpa_commit();

    for (int i = tid; i < 1024; i += THREADS) sw1[i] = w1[i];
    if (tid < 128) sb1[tid] = b1[tid];
    __syncthreads();

    // layer 1 (K=8, fp32 exact) -> hid hi/lo fp16 tiles
    {
        const int row = tid & 127, half = tid >> 7;
        const size_t grow = (size_t)(e0 + row) * 8;
        float in8[8];
        #pragma unroll
        for (int k = 0; k < 8; k++) in8[k] = ea[grow + k] + noise[grow + k];
        #pragma unroll 1
        for (int gg = 0; gg < 8; gg++) {
            const int g = half * 8 + gg;
            uint32_t H[4], L[4];
            #pragma unroll
            for (int p = 0; p < 4; p++) {
                const int col = g * 8 + p * 2;
                float v0 = sb1[col], v1 = sb1[col + 1];
                #pragma unroll
                for (int k = 0; k < 8; k++) {
                    v0 += in8[k] * sw1[k * 128 + col];
                    v1 += in8[k] * sw1[k * 128 + col + 1];
                }
                v0 = fmaxf(v0, 0.f); v1 = fmaxf(v1, 0.f);
                H[p] = pkhl(v0, v1); L[p] = lo2(H[p], v0, v1);
            }
            *(uint4*)(smem + STH + aoff(row, g)) = make_uint4(H[0], H[1], H[2], H[3]);
            *(uint4*)(smem + STL + aoff(row, g)) = make_uint4(L[0], L[1], L[2], L[3]);
        }
    }
    float acc[16][4];
    zacc(acc);
    cpa_wait0(); __syncthreads();
    pass2_smem(sb + STH, sb + STL, sb + SB, acc, lane, R0);

    {
        const int r0 = R0 + (lane >> 2), r1 = r0 + 8;
        #pragma unroll
        for (int j = 0; j < 16; j++) {
            const int col = 8 * j + 2 * (lane & 3);
            const float b0 = b2[col], b1v = b2[col + 1];
            ewrite((size_t)(e0 + r0) * HDIM + col, acc[j][0] + b0, acc[j][1] + b1v);
            ewrite((size_t)(e0 + r1) * HDIM + col, acc[j][2] + b0, acc[j][3] + b1v);
        }
    }
}

// ---------------- prep kernels ----------------
__global__ void prep_w_kernel(const float* __restrict__ W, __half* __restrict__ Wh, int K)
{
    const int i = blockIdx.x * 256 + threadIdx.x;
    if (i < K * 128) {
        const int n = i & 127, k = i >> 7;
        Wh[(size_t)n * K + k] = __float2half_rn(W[(size_t)k * 128 + n]);
    }
}
__global__ void zero_deg_kernel() {
    const int i = blockIdx.x * 256 + threadIdx.x;
    if (i < N_NODES) g_degf[i] = 0.f;
}
__global__ void calc_deg_kernel(const int* __restrict__ ei) {
    const int i = blockIdx.x * 256 + threadIdx.x;
    if (i < N_EDGES) atomicAdd(&g_degf[ei[(size_t)N_EDGES + i]], 1.0f);
}

// ---------------- node encoder (fp32 SIMT, tiny) ----------------
__global__ void __launch_bounds__(128) node_enc_kernel(
    const float* __restrict__ in, const float* __restrict__ noise,
    const float* __restrict__ w1, const float* __restrict__ b1,
    const float* __restrict__ w2, const float* __restrict__ b2,
    float* __restrict__ out)
{
    __shared__ float s_in [TR * 16];
    __shared__ float s_hid[TR * HDIM];
    const int tid = threadIdx.x;
    const size_t row0 = (size_t)blockIdx.x * TR;

    for (int i = tid; i < TR * 16; i += 128)
        s_in[i] = in[row0 * 16 + i] + noise[row0 * 16 + i];
    __syncthreads();

    float acc[TR];
    {
        const float bb = b1[tid];
        #pragma unroll
        for (int r = 0; r < TR; r++) acc[r] = bb;
    }
    #pragma unroll
    for (int k = 0; k < 16; k++) {
        const float w = w1[k * HDIM + tid];
        #pragma unroll
        for (int r = 0; r < TR; r++) acc[r] += s_in[r * 16 + k] * w;
    }
    #pragma unroll
    for (int r = 0; r < TR; r++) s_hid[r * HDIM + tid] = fmaxf(acc[r], 0.f);
    __syncthreads();

    {
        const float bb = b2[tid];
        #pragma unroll
        for (int r = 0; r < TR; r++) acc[r] = bb;
    }
    for (int k = 0; k < HDIM; k++) {
        const float w = w2[k * HDIM + tid];
        #pragma unroll
        for (int r = 0; r < TR; r++) acc[r] += s_hid[r * HDIM + k] * w;
    }
    #pragma unroll
    for (int r = 0; r < TR; r++) out[(row0 + r) * HDIM + tid] = acc[r];
}

// ---------------- node update: g_h <- LN(h*(1+deg) + agg); g_hagg <- 0 ----------------
__global__ void __launch_bounds__(256) node_update_kernel(
    const float* __restrict__ xg, const float* __restrict__ xb)
{
    const int warp = threadIdx.x >> 5, lane = threadIdx.x & 31;
    const int n = blockIdx.x * 8 + warp;
    if (n >= N_NODES) return;
    const size_t base = (size_t)n * HDIM + lane * 4;
    const float dg1 = 1.f + g_degf[n];

    const float4 hv = *(const float4*)&g_h[base];
    const float4 av = *(const float4*)&g_hagg[base];
    float v[4] = { hv.x * dg1 + av.x, hv.y * dg1 + av.y,
                   hv.z * dg1 + av.z, hv.w * dg1 + av.w };
    float s = 0.f, q = 0.f;
    #pragma unroll
    for (int j = 0; j < 4; j++) { s += v[j]; q += v[j] * v[j]; }
    #pragma unroll
    for (int o = 16; o > 0; o >>= 1) {
        s += __shfl_xor_sync(0xffffffffu, s, o);
        q += __shfl_xor_sync(0xffffffffu, q, o);
    }
    const float mean = s * (1.f / HDIM);
    const float var  = q * (1.f / HDIM) - mean * mean;
    const float rstd = rsqrtf(var + LN_EPS);

    float4 o4;
    o4.x = (v[0] - mean) * rstd * xg[lane * 4 + 0] + xb[lane * 4 + 0];
    o4.y = (v[1] - mean) * rstd * xg[lane * 4 + 1] + xb[lane * 4 + 1];
    o4.z = (v[2] - mean) * rstd * xg[lane * 4 + 2] + xb[lane * 4 + 2];
    o4.w = (v[3] - mean) * rstd * xg[lane * 4 + 3] + xb[lane * 4 + 3];
    *(float4*)&g_h[base]    = o4;
    *(float4*)&g_hagg[base] = make_float4(0.f, 0.f, 0.f, 0.f);
}

// ---------------- decoder ----------------
__global__ void __launch_bounds__(256) decoder_kernel(
    const float* __restrict__ w1, const float* __restrict__ b1,
    const float* __restrict__ w2, const float* __restrict__ b2,
    const float* __restrict__ noise, float* __restrict__ out)
{
    const int warp = threadIdx.x >> 5, lane = threadIdx.x & 31;
    const int n = blockIdx.x * 8 + warp;
    if (n >= N_NODES) return;
    const float* hrow = &g_h[(size_t)n * HDIM];

    float acc[4];
    #pragma unroll
    for (int j = 0; j < 4; j++) acc[j] = b1[lane * 4 + j];
    for (int k = 0; k < HDIM; k++) {
        const float hk = __ldg(&hrow[k]);
        const float4 w = *(const float4*)&w1[k * HDIM + lane * 4];
        acc[0] += hk * w.x; acc[1] += hk * w.y; acc[2] += hk * w.z; acc[3] += hk * w.w;
    }
    float o0 = 0.f, o1 = 0.f;
    #pragma unroll
    for (int j = 0; j < 4; j++) {
        const float hid = fmaxf(acc[j], 0.f);
        const int c = lane * 4 + j;
        o0 += hid * w2[c * 2 + 0];
        o1 += hid * w2[c * 2 + 1];
    }
    #pragma unroll
    for (int o = 16; o > 0; o >>= 1) {
        o0 += __shfl_xor_sync(0xffffffffu, o0, o);
        o1 += __shfl_xor_sync(0xffffffffu, o1, o);
    }
    if (lane == 0) {
        out[n * 2 + 0] = o0 + b2[0] - noise[n * 16 + 0];
        out[n * 2 + 1] = o1 + b2[1] - noise[n * 16 + 1];
    }
}

// ---------------- launch ----------------
extern "C" void kernel_launch(void* const* d_in, const int* in_sizes, int n_in,
                              void* d_out, int out_size)
{
    const float* x          = (const float*)d_in[0];
    const float* edge_attr  = (const float*)d_in[1];
    const int*   ei         = (const int*)d_in[2];
    const float* node_noise = (const float*)d_in[3];
    const float* edge_noise = (const float*)d_in[4];
    const float* nw1 = (const float*)d_in[5];  const float* nb1 = (const float*)d_in[6];
    const float* nw2 = (const float*)d_in[7];  const float* nb2 = (const float*)d_in[8];
    const float* ew1 = (const float*)d_in[9];  const float* eb1 = (const float*)d_in[10];
    const float* ew2 = (const float*)d_in[11]; const float* eb2 = (const float*)d_in[12];
    const float* gew1 = (const float*)d_in[13]; const float* geb1 = (const float*)d_in[14];
    const float* gew2 = (const float*)d_in[15]; const float* geb2 = (const float*)d_in[16];
    const float* gnw1 = (const float*)d_in[17]; const float* gnb1 = (const float*)d_in[18];
    const float* gnw2 = (const float*)d_in[19]; const float* gnb2 = (const float*)d_in[20];
    const float* xlg = (const float*)d_in[21]; const float* xlb = (const float*)d_in[22];
    const float* elg = (const float*)d_in[23]; const float* elb = (const float*)d_in[24];
    const float* dw1 = (const float*)d_in[25]; const float* db1 = (const float*)d_in[26];
    const float* dw2 = (const float*)d_in[27]; const float* db2 = (const float*)d_in[28];
    float* out = (float*)d_out;

    float* ph = nullptr;
    cudaGetSymbolAddress((void**)&ph, g_h);
    __half *w1h, *w2h, *w3h, *w4h, *e2h;
    cudaGetSymbolAddress((void**)&w1h, g_We1T);
    cudaGetSymbolAddress((void**)&w2h, g_We2T);
    cudaGetSymbolAddress((void**)&w3h, g_Wn1T);
    cudaGetSymbolAddress((void**)&w4h, g_Wn2T);
    cudaGetSymbolAddress((void**)&e2h, g_Ee2T);

    cudaFuncSetAttribute(gnn_layer_mma, cudaFuncAttributeMaxDynamicSharedMemorySize, GNN_SMEM);
    cudaFuncSetAttribute(node_pre_mma,  cudaFuncAttributeMaxDynamicSharedMemorySize, GNN_SMEM);
    cudaFuncSetAttribute(edge_enc_mma,  cudaFuncAttributeMaxDynamicSharedMemorySize, ENC_SMEM);

    zero_deg_kernel<<<(N_NODES + 255) / 256, 256>>>();
    calc_deg_kernel<<<(N_EDGES + 255) / 256, 256>>>(ei);
    prep_w_kernel<<<(384 * 128 + 255) / 256, 256>>>(gew1, w1h, 384);
    prep_w_kernel<<<(128 * 128 + 255) / 256, 256>>>(gew2, w2h, 128);
    prep_w_kernel<<<(256 * 128 + 255) / 256, 256>>>(gnw1, w3h, 256);
    prep_w_kernel<<<(128 * 128 + 255) / 256, 256>>>(gnw2, w4h, 128);
    prep_w_kernel<<<(128 * 128 + 255) / 256, 256>>>(ew2,  e2h, 128);

    node_enc_kernel<<<N_NODES / TR, 128>>>(x, node_noise, nw1, nb1, nw2, nb2, ph);
    edge_enc_mma<<<N_EDGES / TE, THREADS, ENC_SMEM>>>(edge_attr, edge_noise, ew1, eb1, eb2);

    for (int l = 0; l < NLAYERS; l++) {
        node_pre_mma<<<(N_NODES + TE - 1) / TE, THREADS, GNN_SMEM>>>(geb1, gnb1);
        gnn_layer_mma<<<N_EDGES / TE, THREADS, GNN_SMEM>>>(
            ei, geb2, gnb2, elg + (size_t)l * HDIM, elb + (size_t)l * HDIM);
        node_update_kernel<<<(N_NODES + 7) / 8, 256>>>(
            xlg + (size_t)l * HDIM, xlb + (size_t)l * HDIM);
    }

    decoder_kernel<<<(N_NODES + 7) / 8, 256>>>(dw1, db1, dw2, db2, node_noise, out);
}